// round 10
// baseline (speedup 1.0000x reference)
#include <cuda_runtime.h>
#include <math.h>
#include <stdint.h>

#define NTOK 65536
#define CIN 192
#define HID 384
#define OUTD 192
#define NE 8
#define KCAP 10240
#define TTILE 32
#define LSCALE 2.0f  /* alpha/r = 16/8 */

// FFN smem layout (floats)
#define XSTR 228
#define HSTR 420
#define OFF_XL   7296
#define OFF_A1   14592
#define OFF_HL   13440
#define OFF_WB   26880
#define WBUF_SZ  12544
#define WLO      6272
#define W1STR    392
#define W2STR    200
#define OFF_BW   51968
#define OFF_GW   52096
#define OFF_TOK  52128
#define FFN_FLOATS 52160

#define W1ELEM (NE*224*384)   /* 688128 */
#define W2ELEM (NE*416*192)   /* 638976 */

__device__ __forceinline__ void tf32split(float x, float& h, float& l) {
    unsigned hb; asm("cvt.rna.tf32.f32 %0, %1;" : "=r"(hb) : "f"(x));
    float hf = __uint_as_float(hb);
    float lf = x - hf;
    unsigned lb; asm("cvt.rna.tf32.f32 %0, %1;" : "=r"(lb) : "f"(lf));
    h = hf; l = __uint_as_float(lb);
}
__device__ __forceinline__ void mma8(float* d, const unsigned* a, unsigned b0, unsigned b1) {
    asm("mma.sync.aligned.m16n8k8.row.col.f32.tf32.tf32.f32 "
        "{%0,%1,%2,%3},{%4,%5,%6,%7},{%8,%9},{%0,%1,%2,%3};"
        : "+f"(d[0]), "+f"(d[1]), "+f"(d[2]), "+f"(d[3])
        : "r"(a[0]), "r"(a[1]), "r"(a[2]), "r"(a[3]), "r"(b0), "r"(b1));
}

// ---------------- device scratch ----------------
__device__ float    g_logits[NE * NTOK];
__device__ unsigned g_mask[NTOK];
__device__ int      g_cnt[NE];
__device__ int      g_list[NE * NTOK];
__device__ float    g_wl[NE * NTOK];
__device__ unsigned g_te[NTOK];
__device__ float    g_tw0[NTOK];
__device__ float    g_tw1[NTOK];
__device__ float    g_w1h[W1ELEM];
__device__ float    g_w1l[W1ELEM];
__device__ float    g_w2h[W2ELEM];
__device__ float    g_w2l[W2ELEM];

__global__ void init_kernel() {
    if (threadIdx.x < NE) g_cnt[threadIdx.x] = 0;
}

// ---------------- one-shot weight split (tf32 hi/lo planes) ----------------
__global__ void __launch_bounds__(1024) split_kernel(
    const float* __restrict__ W1, const float* __restrict__ B1,
    const float* __restrict__ W2, const float* __restrict__ B2)
{
    int i = blockIdx.x * 1024 + threadIdx.x;
    if (i < W1ELEM) {
        int e = i / (224*384), rem = i % (224*384);
        int k = rem / 384, n = rem % 384;
        float v = (k < 192) ? W1[((size_t)e*192 + k)*384 + n]
                            : B1[((size_t)e*32 + (k-192))*384 + n];
        float h, l; tf32split(v, h, l);
        g_w1h[i] = h; g_w1l[i] = l;
    }
    if (i < W2ELEM) {
        int e = i / (416*192), rem = i % (416*192);
        int k = rem / 192, n = rem % 192;
        float v = (k < 384) ? W2[((size_t)e*384 + k)*192 + n]
                            : B2[((size_t)e*32 + (k-384))*192 + n];
        float h, l; tf32split(v, h, l);
        g_w2h[i] = h; g_w2l[i] = l;
    }
}

// ---------------- gate: features + LN + logits ----------------
__global__ void __launch_bounds__(1024) gate_kernel(
    const float* __restrict__ x, const float* __restrict__ xprev,
    const float* __restrict__ Wz, const float* __restrict__ lng,
    const float* __restrict__ lnb, const float* __restrict__ Wg,
    const float* __restrict__ bg)
{
    extern __shared__ float sm[];
    float* sWz = sm;
    float* sWg = sWz + 12288;
    float* sg  = sWg + 2322;
    float* sb  = sg + 258;
    float* sbg = sb + 258;
    float* sX  = sbg + 8;

    int tid = threadIdx.x, lane = tid & 31, warp = tid >> 5;
    int n = blockIdx.x * 32 + warp;

    for (int i = tid; i < 12288; i += 1024) sWz[i] = Wz[i];
    for (int i = tid; i < 2064;  i += 1024) sWg[(i >> 3)*9 + (i & 7)] = Wg[i];
    for (int i = tid; i < 258;   i += 1024) { sg[i] = lng[i]; sb[i] = lnb[i]; }
    if (tid < 8) sbg[tid] = bg[tid];

    float xr[6];
    #pragma unroll
    for (int i = 0; i < 6; i++) {
        xr[i] = x[(size_t)n*CIN + lane + 32*i];
        sX[warp*CIN + lane + 32*i] = xr[i];
    }
    float s = 0.f, ss = 0.f;
    #pragma unroll
    for (int i = 0; i < 6; i++) {
        float a = fabsf(xr[i] - xprev[(size_t)n*CIN + lane + 32*i]);
        s += a; ss += a*a;
    }
    #pragma unroll
    for (int o = 16; o; o >>= 1) {
        s  += __shfl_xor_sync(0xffffffffu, s, o);
        ss += __shfl_xor_sync(0xffffffffu, ss, o);
    }
    float dmean = s * (1.0f/192.0f);
    float dvar  = fmaxf((ss - s*dmean) * (1.0f/191.0f), 0.f);
    float mu = log1pf(dmean), sd = log1pf(sqrtf(dvar));

    __syncthreads();

    float z0 = 0.f, z1 = 0.f;
    for (int c = 0; c < CIN; c++) {
        float xv = sX[warp*CIN + c];
        z0 = fmaf(xv, sWz[c*64 + lane],      z0);
        z1 = fmaf(xv, sWz[c*64 + lane + 32], z1);
    }
    float sa = z0 + z1, s2 = z0*z0 + z1*z1;
    #pragma unroll
    for (int i = 0; i < 6; i++) { sa += xr[i]; s2 += xr[i]*xr[i]; }
    if (lane == 0) { sa += mu + sd; s2 += mu*mu + sd*sd; }
    #pragma unroll
    for (int o = 16; o; o >>= 1) {
        sa += __shfl_xor_sync(0xffffffffu, sa, o);
        s2 += __shfl_xor_sync(0xffffffffu, s2, o);
    }
    float m_   = sa * (1.0f/258.0f);
    float rstd = rsqrtf(s2 * (1.0f/258.0f) - m_*m_ + 1e-5f);

    float acc[8] = {0,0,0,0,0,0,0,0};
    #pragma unroll
    for (int i = 0; i < 6; i++) {
        int idx = lane + 32*i;
        float nv = (xr[i] - m_)*rstd*sg[idx] + sb[idx];
        #pragma unroll
        for (int e = 0; e < 8; e++) acc[e] = fmaf(nv, sWg[idx*9 + e], acc[e]);
    }
    {
        int idx = 192 + lane;
        float nv = (z0 - m_)*rstd*sg[idx] + sb[idx];
        #pragma unroll
        for (int e = 0; e < 8; e++) acc[e] = fmaf(nv, sWg[idx*9 + e], acc[e]);
        idx = 224 + lane;
        nv = (z1 - m_)*rstd*sg[idx] + sb[idx];
        #pragma unroll
        for (int e = 0; e < 8; e++) acc[e] = fmaf(nv, sWg[idx*9 + e], acc[e]);
    }
    if (lane == 0) {
        float nv = (mu - m_)*rstd*sg[256] + sb[256];
        #pragma unroll
        for (int e = 0; e < 8; e++) acc[e] = fmaf(nv, sWg[256*9 + e], acc[e]);
        nv = (sd - m_)*rstd*sg[257] + sb[257];
        #pragma unroll
        for (int e = 0; e < 8; e++) acc[e] = fmaf(nv, sWg[257*9 + e], acc[e]);
    }
    #pragma unroll
    for (int e = 0; e < 8; e++) {
        #pragma unroll
        for (int o = 16; o; o >>= 1) acc[e] += __shfl_xor_sync(0xffffffffu, acc[e], o);
    }
    if (lane == 0) {
        #pragma unroll
        for (int e = 0; e < 8; e++) g_logits[e*NTOK + n] = acc[e] + sbg[e];
        g_mask[n] = 0u;
    }
}

// ---------------- expert-choice: radix select top-K per expert ----------------
__device__ __forceinline__ unsigned f2key(float f) {
    unsigned u = __float_as_uint(f);
    return (u & 0x80000000u) ? ~u : (u | 0x80000000u);
}

__global__ void __launch_bounds__(1024) select_kernel() {
    __shared__ unsigned hist[256];
    __shared__ unsigned sh_digit, sh_need;
    __shared__ int ccount[64];
    __shared__ int cbase[64];

    int e = blockIdx.x, tid = threadIdx.x;
    int lane = tid & 31, warp = tid >> 5;
    const float* base = g_logits + (size_t)e * NTOK;

    unsigned prefix = 0, pmask = 0, need = KCAP;
    for (int pass = 0; pass < 4; pass++) {
        int shift = 24 - pass*8;
        if (tid < 256) hist[tid] = 0;
        __syncthreads();
        for (int n = tid; n < NTOK; n += 1024) {
            unsigned k = f2key(base[n]);
            bool act = ((k & pmask) == prefix);
            unsigned dg = act ? ((k >> shift) & 255u) : 0xffffffffu;
            unsigned peers = __match_any_sync(0xffffffffu, dg);
            if (act && (__ffs(peers) - 1) == lane)
                atomicAdd(&hist[dg], (unsigned)__popc(peers));
        }
        __syncthreads();
        if (tid == 0) {
            unsigned cum = 0; int d = 255;
            for (; d > 0; d--) {
                unsigned h = hist[d];
                if (cum + h >= need) break;
                cum += h;
            }
            sh_digit = (unsigned)d;
            sh_need  = need - cum;
        }
        __syncthreads();
        prefix |= sh_digit << shift;
        pmask  |= 0xFFu << shift;
        need    = sh_need;
        __syncthreads();
    }
    unsigned thr = prefix;
    int r = (int)need;

    for (int n = tid; n < NTOK; n += 1024)
        if (f2key(base[n]) > thr) atomicOr(&g_mask[n], 1u << e);

    for (int c = warp; c < 64; c += 32) {
        int cnt = 0;
        for (int s = 0; s < 32; s++) {
            int n = c*1024 + s*32 + lane;
            cnt += (f2key(base[n]) == thr);
        }
        #pragma unroll
        for (int o = 16; o; o >>= 1) cnt += __shfl_xor_sync(0xffffffffu, cnt, o);
        if (lane == 0) ccount[c] = cnt;
    }
    __syncthreads();
    if (tid == 0) {
        int run = 0;
        for (int c = 0; c < 64; c++) { cbase[c] = run; run += ccount[c]; }
    }
    __syncthreads();
    for (int c = warp; c < 64; c += 32) {
        int rank = cbase[c];
        if (rank >= r) continue;
        for (int s = 0; s < 32; s++) {
            int n = c*1024 + s*32 + lane;
            bool p = (f2key(base[n]) == thr);
            unsigned bal = __ballot_sync(0xffffffffu, p);
            int myrank = rank + __popc(bal & ((1u << lane) - 1u));
            if (p && myrank < r) atomicOr(&g_mask[n], 1u << e);
            rank += __popc(bal);
        }
    }
}

// ---------------- routing (block-aggregated dispatch) ----------------
__global__ void __launch_bounds__(256) route_kernel(float* __restrict__ out) {
    __shared__ int sCnt[8], sBase[8];
    int tid = threadIdx.x;
    int n = blockIdx.x * 256 + tid;
    if (tid < 8) sCnt[tid] = 0;
    __syncthreads();

    float l[8];
    #pragma unroll
    for (int e = 0; e < 8; e++) l[e] = g_logits[e*NTOK + n];
    unsigned m = g_mask[n];
    if (m == 0u) {
        int best = 0; float bv = l[0];
        #pragma unroll
        for (int e = 1; e < 8; e++) if (l[e] > bv) { bv = l[e]; best = e; }
        m = 1u << best;
    }
    int e0 = -1, e1 = -1; float v0 = -INFINITY, v1 = -INFINITY;
    #pragma unroll
    for (int e = 0; e < 8; e++) {
        if ((m >> e) & 1u) {
            float f = l[e];
            if (f > v0)      { v1 = v0; e1 = e0; v0 = f; e0 = e; }
            else if (f > v1) { v1 = f; e1 = e; }
        }
    }
    float w0 = 1.f, w1 = 0.f;
    if (e1 >= 0) {
        float ex = expf(v1 - v0);
        w0 = 1.0f / (1.0f + ex);
        w1 = ex * w0;
    }
    bool has1 = (e1 >= 0 && w1 > 0.f);
    int p0 = atomicAdd(&sCnt[e0], 1);
    int p1 = has1 ? atomicAdd(&sCnt[e1], 1) : -1;
    __syncthreads();
    if (tid < 8) sBase[tid] = atomicAdd(&g_cnt[tid], sCnt[tid]);
    __syncthreads();
    {
        int pos = sBase[e0] + p0;
        g_list[e0*NTOK + pos] = n;
        g_wl[e0*NTOK + pos]   = w0;
    }
    unsigned te = (unsigned)e0 | (255u << 8);
    float tw1 = 0.f;
    if (has1) {
        int pos = sBase[e1] + p1;
        g_list[e1*NTOK + pos] = n;
        g_wl[e1*NTOK + pos]   = w1;
        te = (unsigned)e0 | ((unsigned)e1 << 8);
        tw1 = w1;
    }
    g_te[n] = te; g_tw0[n] = w0; g_tw1[n] = tw1;

    float4 z4 = make_float4(0.f, 0.f, 0.f, 0.f);
    float4* o4 = (float4*)out;
    for (int i = n; i < NTOK*OUTD/4; i += NTOK) o4[i] = z4;
}

// ---------------- fused expert FFN v10: tf32 MMA + pre-split weights ----------------
__global__ void __launch_bounds__(256) ffn_kernel(
    const float* __restrict__ x,  const float* __restrict__ bw,
    const float* __restrict__ b1, const float* __restrict__ b2,
    const float* __restrict__ A1, const float* __restrict__ A2,
    float* __restrict__ out)
{
    extern __shared__ float sm[];
    float* sBw = sm + OFF_BW;
    float* sGw = sm + OFF_GW;
    int*   sTok = (int*)(sm + OFF_TOK);

    int e = blockIdx.y;
    int cnt = g_cnt[e];
    int t0 = blockIdx.x * TTILE;
    if (t0 >= cnt) return;
    int nt = min(TTILE, cnt - t0);
    int tid = threadIdx.x;

    if (tid < TTILE) {
        int idx = t0 + min(tid, nt - 1);
        int tok = g_list[e*NTOK + idx];
        sTok[tid] = tok;
        sGw[tid]  = (tid < nt) ? g_wl[e*NTOK + idx] : 0.f;
        *(float4*)(sBw + tid*4) = *(const float4*)(bw + (size_t)tok*4);
    }
    __syncthreads();

    {   // gather x -> split [tok][k]; stage A1 raw
        int t = tid & 31, part = tid >> 5;
        int tok = sTok[t];
        const float4* src = (const float4*)(x + (size_t)tok*CIN) + part*6;
        #pragma unroll
        for (int i = 0; i < 6; i++) {
            float4 v = src[i];
            int c = part*24 + i*4;
            float h0,l0,h1,l1,h2,l2,h3,l3;
            tf32split(v.x,h0,l0); tf32split(v.y,h1,l1);
            tf32split(v.z,h2,l2); tf32split(v.w,h3,l3);
            *(float4*)(sm + t*XSTR + c)          = make_float4(h0,h1,h2,h3);
            *(float4*)(sm + OFF_XL + t*XSTR + c) = make_float4(l0,l1,l2,l3);
        }
        const float4* a4 = (const float4*)(A1 + (size_t)e*6144);
        float4* w4 = (float4*)(sm + OFF_A1);
        for (int i = tid; i < 1536; i += 256) w4[i] = a4[i];
    }
    __syncthreads();

    // LoRA1: thread = (token, band, r-half); x = xh + xl
    {
        int t = tid >> 3, b = (tid >> 1) & 3, rh = tid & 1, r0 = rh*4;
        const float* A = sm + OFF_A1 + b*1536 + r0;
        float acc[4] = {0,0,0,0};
        for (int c = 0; c < CIN; c++) {
            float xv = sm[t*XSTR + c] + sm[OFF_XL + t*XSTR + c];
            float4 av = *(const float4*)(A + c*8);
            acc[0] = fmaf(xv, av.x, acc[0]); acc[1] = fmaf(xv, av.y, acc[1]);
            acc[2] = fmaf(xv, av.z, acc[2]); acc[3] = fmaf(xv, av.w, acc[3]);
        }
        float scl = LSCALE * sBw[t*4 + b];
        #pragma unroll
        for (int j = 0; j < 4; j++) {
            float h, l; tf32split(scl*acc[j], h, l);
            sm[t*XSTR + 192 + b*8 + r0 + j]          = h;
            sm[OFF_XL + t*XSTR + 192 + b*8 + r0 + j] = l;
        }
    }

    int warp = tid >> 5, lane = tid & 31;
    int g = lane >> 2, kq = lane & 3;
    int row = tid >> 4, c4 = tid & 15;
    const unsigned* uX = (const unsigned*)sm;
    const float* w1h = g_w1h + (size_t)e*224*384;
    const float* w1l = g_w1l + (size_t)e*224*384;
    const float* w2h = g_w2h + (size_t)e*416*192;
    const float* w2l = g_w2l + (size_t)e*416*192;

    // ---- layer 1: [32,224]x[224,384]; warp = 2 M-tiles x 48 cols ----
    float d1[2][6][4];
    #pragma unroll
    for (int nj = 0; nj < 6; nj++) {
        int col = warp*48 + nj*8 + 2*kq;
        float b0v = b1[e*HID + col], b1v = b1[e*HID + col + 1];
        #pragma unroll
        for (int mt = 0; mt < 2; mt++) {
            d1[mt][nj][0] = b0v; d1[mt][nj][1] = b1v;
            d1[mt][nj][2] = b0v; d1[mt][nj][3] = b1v;
        }
    }
    {   // prologue: pure copy of pre-split tile 0
        const float4* sh4 = (const float4*)(w1h + (size_t)row*384);
        const float4* sl4 = (const float4*)(w1l + (size_t)row*384);
        float* Wd = sm + OFF_WB;
        #pragma unroll
        for (int i = 0; i < 6; i++) {
            int off = row*W1STR + 4*c4 + 64*i;
            *(float4*)(Wd + off)       = sh4[c4 + 16*i];
            *(float4*)(Wd + WLO + off) = sl4[c4 + 16*i];
        }
    }
    float4 prh[6], prl[6];
    for (int kt = 0; kt < 14; kt++) {
        if (kt < 13) {
            int k = (kt+1)*16 + row;
            const float4* sh4 = (const float4*)(w1h + (size_t)k*384);
            const float4* sl4 = (const float4*)(w1l + (size_t)k*384);
            #pragma unroll
            for (int i = 0; i < 6; i++) { prh[i] = sh4[c4 + 16*i]; prl[i] = sl4[c4 + 16*i]; }
        }
        __syncthreads();
        const unsigned* Wh = (const unsigned*)(sm + OFF_WB + (kt&1)*WBUF_SZ);
        const unsigned* Wl = Wh + WLO;
        #pragma unroll
        for (int k8 = 0; k8 < 2; k8++) {
            int kb = kt*16 + k8*8;
            unsigned ah[2][4], al[2][4];
            #pragma unroll
            for (int mt = 0; mt < 2; mt++) {
                int base = (mt*16 + g)*XSTR + kb + kq;
                ah[mt][0] = uX[base];               al[mt][0] = uX[OFF_XL + base];
                ah[mt][1] = uX[base + 8*XSTR];      al[mt][1] = uX[OFF_XL + base + 8*XSTR];
                ah[mt][2] = uX[base + 4];           al[mt][2] = uX[OFF_XL + base + 4];
                ah[mt][3] = uX[base + 8*XSTR + 4];  al[mt][3] = uX[OFF_XL + base + 8*XSTR + 4];
            }
            #pragma unroll
            for (int nj = 0; nj < 6; nj++) {
                int o0 = (k8*8 + kq)*W1STR + warp*48 + nj*8 + g;
                int o1 = o0 + 4*W1STR;
                unsigned bh0 = Wh[o0], bh1 = Wh[o1];
                unsigned bl0 = Wl[o0], bl1 = Wl[o1];
                #pragma unroll
                for (int mt = 0; mt < 2; mt++) {
                    mma8(d1[mt][nj], ah[mt], bh0, bh1);
                    mma8(d1[mt][nj], ah[mt], bl0, bl1);
                    mma8(d1[mt][nj], al[mt], bh0, bh1);
                }
            }
        }
        if (kt < 13) {
            float* Wd = sm + OFF_WB + ((kt+1)&1)*WBUF_SZ;
            #pragma unroll
            for (int i = 0; i < 6; i++) {
                int off = row*W1STR + 4*c4 + 64*i;
                *(float4*)(Wd + off)       = prh[i];
                *(float4*)(Wd + WLO + off) = prl[i];
            }
        }
    }
    __syncthreads();

    // exact GELU -> split H [tok][h]
    #pragma unroll
    for (int mt = 0; mt < 2; mt++)
        #pragma unroll
        for (int nj = 0; nj < 6; nj++) {
            int col = warp*48 + nj*8 + 2*kq;
            #pragma unroll
            for (int q = 0; q < 4; q++) {
                int t = mt*16 + g + (q >> 1)*8;
                int c = col + (q & 1);
                float v = d1[mt][nj][q];
                float gv = v * 0.5f * (1.0f + erff(v * 0.70710678118654752f));
                float h, l; tf32split(gv, h, l);
                sm[t*HSTR + c]          = h;
                sm[OFF_HL + t*HSTR + c] = l;
            }
        }
    __syncthreads();

    // LoRA2: thread = (token, band, r-half); h = hh + hl
    {
        int t = tid >> 3, b = (tid >> 1) & 3, rh = tid & 1, r0 = rh*4;
        const float* A = A2 + ((size_t)e*4 + b)*HID*8 + r0;
        float acc[4] = {0,0,0,0};
        for (int hh = 0; hh < HID; hh++) {
            float hv = sm[t*HSTR + hh] + sm[OFF_HL + t*HSTR + hh];
            float4 av = *(const float4*)(A + hh*8);
            acc[0] = fmaf(hv, av.x, acc[0]); acc[1] = fmaf(hv, av.y, acc[1]);
            acc[2] = fmaf(hv, av.z, acc[2]); acc[3] = fmaf(hv, av.w, acc[3]);
        }
        float scl = LSCALE * sBw[t*4 + b];
        #pragma unroll
        for (int j = 0; j < 4; j++) {
            float h, l; tf32split(scl*acc[j], h, l);
            sm[t*HSTR + 384 + b*8 + r0 + j]          = h;
            sm[OFF_HL + t*HSTR + 384 + b*8 + r0 + j] = l;
        }
    }

    // ---- layer 2: [32,416]x[416,192]; warp = 2 M-tiles x 24 cols ----
    float d2[2][3][4];
    #pragma unroll
    for (int nj = 0; nj < 3; nj++) {
        int col = warp*24 + nj*8 + 2*kq;
        float b0v = b2[e*OUTD + col], b1v = b2[e*OUTD + col + 1];
        #pragma unroll
        for (int mt = 0; mt < 2; mt++) {
            d2[mt][nj][0] = b0v; d2[mt][nj][1] = b1v;
            d2[mt][nj][2] = b0v; d2[mt][nj][3] = b1v;
        }
    }
    {   // prologue
        const float4* sh4 = (const float4*)(w2h + (size_t)row*192);
        const float4* sl4 = (const float4*)(w2l + (size_t)row*192);
        float* Wd = sm + OFF_WB;
        #pragma unroll
        for (int i = 0; i < 3; i++) {
            int off = row*W2STR + 4*c4 + 64*i;
            *(float4*)(Wd + off)       = sh4[c4 + 16*i];
            *(float4*)(Wd + WLO + off) = sl4[c4 + 16*i];
        }
    }
    for (int kt = 0; kt < 26; kt++) {
        if (kt < 25) {
            int k = (kt+1)*16 + row;
            const float4* sh4 = (const float4*)(w2h + (size_t)k*192);
            const float4* sl4 = (const float4*)(w2l + (size_t)k*192);
            #pragma unroll
            for (int i = 0; i < 3; i++) { prh[i] = sh4[c4 + 16*i]; prl[i] = sl4[c4 + 16*i]; }
        }
        __syncthreads();
        const unsigned* Wh = (const unsigned*)(sm + OFF_WB + (kt&1)*WBUF_SZ);
        const unsigned* Wl = Wh + WLO;
        #pragma unroll
        for (int k8 = 0; k8 < 2; k8++) {
            int kb = kt*16 + k8*8;
            unsigned ah[2][4], al[2][4];
            #pragma unroll
            for (int mt = 0; mt < 2; mt++) {
                int base = (mt*16 + g)*HSTR + kb + kq;
                ah[mt][0] = uX[base];               al[mt][0] = uX[OFF_HL + base];
                ah[mt][1] = uX[base + 8*HSTR];      al[mt][1] = uX[OFF_HL + base + 8*HSTR];
                ah[mt][2] = uX[base + 4];           al[mt][2] = uX[OFF_HL + base + 4];
                ah[mt][3] = uX[base + 8*HSTR + 4];  al[mt][3] = uX[OFF_HL + base + 8*HSTR + 4];
            }
            #pragma unroll
            for (int nj = 0; nj < 3; nj++) {
                int o0 = (k8*8 + kq)*W2STR + warp*24 + nj*8 + g;
                int o1 = o0 + 4*W2STR;
                unsigned bh0 = Wh[o0], bh1 = Wh[o1];
                unsigned bl0 = Wl[o0], bl1 = Wl[o1];
                #pragma unroll
                for (int mt = 0; mt < 2; mt++) {
                    mma8(d2[mt][nj], ah[mt], bh0, bh1);
                    mma8(d2[mt][nj], ah[mt], bl0, bl1);
                    mma8(d2[mt][nj], al[mt], bh0, bh1);
                }
            }
        }
        if (kt < 25) {
            float* Wd = sm + OFF_WB + ((kt+1)&1)*WBUF_SZ;
            #pragma unroll
            for (int i = 0; i < 3; i++) {
                int off = row*W2STR + 4*c4 + 64*i;
                *(float4*)(Wd + off)       = prh[i];
                *(float4*)(Wd + WLO + off) = prl[i];
            }
        }
    }
    // epilogue
    #pragma unroll
    for (int mt = 0; mt < 2; mt++)
        #pragma unroll
        for (int nj = 0; nj < 3; nj++) {
            int col = warp*24 + nj*8 + 2*kq;
            #pragma unroll
            for (int q = 0; q < 4; q++) {
                int t = mt*16 + g + (q >> 1)*8;
                if (t < nt) {
                    int tok = sTok[t];
                    atomicAdd(&out[(size_t)tok*OUTD + col + (q & 1)],
                              sGw[t]*d2[mt][nj][q]);
                }
            }
        }
}

// ---------------- deterministic loss ----------------
__global__ void __launch_bounds__(1024) loss_kernel(float* out, int out_size) {
    __shared__ float sI[8][32], sL[8][32];
    int tid = threadIdx.x, lane = tid & 31, warp = tid >> 5;
    float imp[8] = {0,0,0,0,0,0,0,0}, ld[8] = {0,0,0,0,0,0,0,0};
    for (int n = tid; n < NTOK; n += 1024) {
        unsigned te = g_te[n];
        int e0 = te & 255u, e1 = (te >> 8) & 255u;
        imp[e0] += g_tw0[n]; ld[e0] += 1.f;
        if (e1 != 255) { imp[e1] += g_tw1[n]; ld[e1] += 1.f; }
    }
    #pragma unroll
    for (int e = 0; e < 8; e++) {
        #pragma unroll
        for (int o = 16; o; o >>= 1) {
            imp[e] += __shfl_xor_sync(0xffffffffu, imp[e], o);
            ld[e]  += __shfl_xor_sync(0xffffffffu, ld[e],  o);
        }
        if (lane == 0) { sI[e][warp] = imp[e]; sL[e][warp] = ld[e]; }
    }
    __syncthreads();
    if (tid == 0) {
        float I[8], L[8], mi = 0.f, ml = 0.f;
        for (int e = 0; e < 8; e++) {
            float a = 0.f, b = 0.f;
            for (int w = 0; w < 32; w++) { a += sI[e][w]; b += sL[e][w]; }
            I[e] = a; L[e] = b; mi += a; ml += b;
        }
        mi *= 0.125f; ml *= 0.125f;
        float vi = 0.f, vl = 0.f;
        for (int e = 0; e < 8; e++) {
            float di = I[e] - mi; vi += di*di;
            float dl = L[e] - ml; vl += dl*dl;
        }
        vi *= 0.125f; vl *= 0.125f;
        float loss = (vi / (mi*mi + 1e-10f) + vl / (ml*ml + 1e-10f)) * 0.01f;
        if (out_size > NTOK*OUTD) out[NTOK*OUTD] = loss;
    }
    for (int i = NTOK*OUTD + 1 + tid; i < out_size; i += 1024) out[i] = 0.f;
}

// ---------------- launch ----------------
extern "C" void kernel_launch(void* const* d_in, const int* in_sizes, int n_in,
                              void* d_out, int out_size) {
    const float* x     = (const float*)d_in[0];
    const float* bw    = (const float*)d_in[1];
    const float* xprev = (const float*)d_in[2];
    const float* Wz    = (const float*)d_in[3];
    const float* lng   = (const float*)d_in[4];
    const float* lnb   = (const float*)d_in[5];
    const float* Wg    = (const float*)d_in[6];
    const float* bg    = (const float*)d_in[7];
    const float* W1    = (const float*)d_in[8];
    const float* b1    = (const float*)d_in[9];
    const float* W2    = (const float*)d_in[10];
    const float* b2    = (const float*)d_in[11];
    const float* A1    = (const float*)d_in[12];
    const float* B1    = (const float*)d_in[13];
    const float* A2    = (const float*)d_in[14];
    const float* B2    = (const float*)d_in[15];
    float* out = (float*)d_out;

    const size_t GATE_SMEM = (size_t)(12288 + 2322 + 258 + 258 + 8 + 32*192) * 4;
    const size_t FFN_SMEM  = (size_t)FFN_FLOATS * 4;
    cudaFuncSetAttribute(gate_kernel, cudaFuncAttributeMaxDynamicSharedMemorySize, (int)GATE_SMEM);
    cudaFuncSetAttribute(ffn_kernel,  cudaFuncAttributeMaxDynamicSharedMemorySize, (int)FFN_SMEM);

    init_kernel<<<1, 32>>>();
    split_kernel<<<(W1ELEM + 1023)/1024, 1024>>>(W1, B1, W2, B2);
    gate_kernel<<<NTOK/32, 1024, GATE_SMEM>>>(x, xprev, Wz, lng, lnb, Wg, bg);
    select_kernel<<<NE, 1024>>>();
    route_kernel<<<NTOK/256, 256>>>(out);
    ffn_kernel<<<dim3(NTOK/TTILE, NE), 256, FFN_SMEM>>>(x, bw, b1, b2, A1, A2, out);
    loss_kernel<<<1, 1024>>>(out, out_size);
}

// round 11
// speedup vs baseline: 1.1995x; 1.1995x over previous
#include <cuda_runtime.h>
#include <math.h>
#include <stdint.h>

#define NTOK 65536
#define CIN 192
#define HID 384
#define OUTD 192
#define NE 8
#define KCAP 10240
#define TTILE 32
#define LSCALE 2.0f

// FFN smem (u32 units)
#define XW32   116      /* x plane stride: 232 bf16 */
#define HW32   212      /* h plane stride: 424 bf16 */
#define OFF_XL 3712
#define OFF_HL 6784
#define OFF_A1 13568
#define OFF_WB 19712
#define WBUF   6272
#define PLO    3136
#define OFF_BW 32256
#define OFF_GW 32384
#define OFF_TOK 32416
#define FFN_U32 32448

#define W1PE 43904      /* per-expert u32: 112*392 */
#define W2PE 41600      /* 208*200 */

__device__ __forceinline__ unsigned short f2bf(float x) {
    unsigned u = __float_as_uint(x);
    return (unsigned short)((u + 0x7fffu + ((u >> 16) & 1u)) >> 16);
}
__device__ __forceinline__ float bf2f(unsigned short b) {
    return __uint_as_float((unsigned)b << 16);
}
__device__ __forceinline__ void bfsplit(float x, unsigned short& h, unsigned short& l) {
    h = f2bf(x);
    l = f2bf(x - bf2f(h));
}
__device__ __forceinline__ void mma16(float* d, const unsigned* a, unsigned b0, unsigned b1) {
    asm("mma.sync.aligned.m16n8k16.row.col.f32.bf16.bf16.f32 "
        "{%0,%1,%2,%3},{%4,%5,%6,%7},{%8,%9},{%0,%1,%2,%3};"
        : "+f"(d[0]), "+f"(d[1]), "+f"(d[2]), "+f"(d[3])
        : "r"(a[0]), "r"(a[1]), "r"(a[2]), "r"(a[3]), "r"(b0), "r"(b1));
}

// ---------------- device scratch ----------------
__device__ float    g_logits[NE * NTOK];
__device__ unsigned g_mask[NTOK];
__device__ int      g_cnt[NE];
__device__ int      g_list[NE * NTOK];
__device__ float    g_wl[NE * NTOK];
__device__ unsigned g_te[NTOK];
__device__ float    g_tw0[NTOK];
__device__ float    g_tw1[NTOK];
__device__ __align__(16) unsigned g_w1h[NE*W1PE];
__device__ __align__(16) unsigned g_w1l[NE*W1PE];
__device__ __align__(16) unsigned g_w2h[NE*W2PE];
__device__ __align__(16) unsigned g_w2l[NE*W2PE];

__global__ void init_kernel() {
    if (threadIdx.x < NE) g_cnt[threadIdx.x] = 0;
}

// ---------------- one-shot weight split: packed k-pair bf16 hi/lo planes ----
__global__ void __launch_bounds__(1024) split_kernel(
    const float* __restrict__ W1, const float* __restrict__ B1,
    const float* __restrict__ W2, const float* __restrict__ B2)
{
    int i = blockIdx.x * 1024 + threadIdx.x;
    if (i < NE*112*384) {
        int e = i / 43008, rem = i % 43008;
        int kp = rem / 384, n = rem % 384;
        int k0 = 2*kp, k1 = k0 + 1;
        float v0 = (k0 < 192) ? W1[((size_t)e*192 + k0)*384 + n]
                              : B1[((size_t)e*32 + (k0-192))*384 + n];
        float v1 = (k1 < 192) ? W1[((size_t)e*192 + k1)*384 + n]
                              : B1[((size_t)e*32 + (k1-192))*384 + n];
        unsigned short h0,l0,h1,l1;
        bfsplit(v0,h0,l0); bfsplit(v1,h1,l1);
        g_w1h[(size_t)e*W1PE + kp*392 + n] = (unsigned)h0 | ((unsigned)h1 << 16);
        g_w1l[(size_t)e*W1PE + kp*392 + n] = (unsigned)l0 | ((unsigned)l1 << 16);
    }
    if (i < NE*208*192) {
        int e = i / 39936, rem = i % 39936;
        int kp = rem / 192, n = rem % 192;
        int k0 = 2*kp, k1 = k0 + 1;
        float v0 = (k0 < 384) ? W2[((size_t)e*384 + k0)*192 + n]
                              : B2[((size_t)e*32 + (k0-384))*192 + n];
        float v1 = (k1 < 384) ? W2[((size_t)e*384 + k1)*192 + n]
                              : B2[((size_t)e*32 + (k1-384))*192 + n];
        unsigned short h0,l0,h1,l1;
        bfsplit(v0,h0,l0); bfsplit(v1,h1,l1);
        g_w2h[(size_t)e*W2PE + kp*200 + n] = (unsigned)h0 | ((unsigned)h1 << 16);
        g_w2l[(size_t)e*W2PE + kp*200 + n] = (unsigned)l0 | ((unsigned)l1 << 16);
    }
}

// ---------------- gate: features + LN + logits ----------------
__global__ void __launch_bounds__(1024) gate_kernel(
    const float* __restrict__ x, const float* __restrict__ xprev,
    const float* __restrict__ Wz, const float* __restrict__ lng,
    const float* __restrict__ lnb, const float* __restrict__ Wg,
    const float* __restrict__ bg)
{
    extern __shared__ float sm[];
    float* sWz = sm;
    float* sWg = sWz + 12288;
    float* sg  = sWg + 2322;
    float* sb  = sg + 258;
    float* sbg = sb + 258;
    float* sX  = sbg + 8;

    int tid = threadIdx.x, lane = tid & 31, warp = tid >> 5;
    int n = blockIdx.x * 32 + warp;

    for (int i = tid; i < 12288; i += 1024) sWz[i] = Wz[i];
    for (int i = tid; i < 2064;  i += 1024) sWg[(i >> 3)*9 + (i & 7)] = Wg[i];
    for (int i = tid; i < 258;   i += 1024) { sg[i] = lng[i]; sb[i] = lnb[i]; }
    if (tid < 8) sbg[tid] = bg[tid];

    float xr[6];
    #pragma unroll
    for (int i = 0; i < 6; i++) {
        xr[i] = x[(size_t)n*CIN + lane + 32*i];
        sX[warp*CIN + lane + 32*i] = xr[i];
    }
    float s = 0.f, ss = 0.f;
    #pragma unroll
    for (int i = 0; i < 6; i++) {
        float a = fabsf(xr[i] - xprev[(size_t)n*CIN + lane + 32*i]);
        s += a; ss += a*a;
    }
    #pragma unroll
    for (int o = 16; o; o >>= 1) {
        s  += __shfl_xor_sync(0xffffffffu, s, o);
        ss += __shfl_xor_sync(0xffffffffu, ss, o);
    }
    float dmean = s * (1.0f/192.0f);
    float dvar  = fmaxf((ss - s*dmean) * (1.0f/191.0f), 0.f);
    float mu = log1pf(dmean), sd = log1pf(sqrtf(dvar));

    __syncthreads();

    float z0 = 0.f, z1 = 0.f;
    for (int c = 0; c < CIN; c++) {
        float xv = sX[warp*CIN + c];
        z0 = fmaf(xv, sWz[c*64 + lane],      z0);
        z1 = fmaf(xv, sWz[c*64 + lane + 32], z1);
    }
    float sa = z0 + z1, s2 = z0*z0 + z1*z1;
    #pragma unroll
    for (int i = 0; i < 6; i++) { sa += xr[i]; s2 += xr[i]*xr[i]; }
    if (lane == 0) { sa += mu + sd; s2 += mu*mu + sd*sd; }
    #pragma unroll
    for (int o = 16; o; o >>= 1) {
        sa += __shfl_xor_sync(0xffffffffu, sa, o);
        s2 += __shfl_xor_sync(0xffffffffu, s2, o);
    }
    float m_   = sa * (1.0f/258.0f);
    float rstd = rsqrtf(s2 * (1.0f/258.0f) - m_*m_ + 1e-5f);

    float acc[8] = {0,0,0,0,0,0,0,0};
    #pragma unroll
    for (int i = 0; i < 6; i++) {
        int idx = lane + 32*i;
        float nv = (xr[i] - m_)*rstd*sg[idx] + sb[idx];
        #pragma unroll
        for (int e = 0; e < 8; e++) acc[e] = fmaf(nv, sWg[idx*9 + e], acc[e]);
    }
    {
        int idx = 192 + lane;
        float nv = (z0 - m_)*rstd*sg[idx] + sb[idx];
        #pragma unroll
        for (int e = 0; e < 8; e++) acc[e] = fmaf(nv, sWg[idx*9 + e], acc[e]);
        idx = 224 + lane;
        nv = (z1 - m_)*rstd*sg[idx] + sb[idx];
        #pragma unroll
        for (int e = 0; e < 8; e++) acc[e] = fmaf(nv, sWg[idx*9 + e], acc[e]);
    }
    if (lane == 0) {
        float nv = (mu - m_)*rstd*sg[256] + sb[256];
        #pragma unroll
        for (int e = 0; e < 8; e++) acc[e] = fmaf(nv, sWg[256*9 + e], acc[e]);
        nv = (sd - m_)*rstd*sg[257] + sb[257];
        #pragma unroll
        for (int e = 0; e < 8; e++) acc[e] = fmaf(nv, sWg[257*9 + e], acc[e]);
    }
    #pragma unroll
    for (int e = 0; e < 8; e++) {
        #pragma unroll
        for (int o = 16; o; o >>= 1) acc[e] += __shfl_xor_sync(0xffffffffu, acc[e], o);
    }
    if (lane == 0) {
        #pragma unroll
        for (int e = 0; e < 8; e++) g_logits[e*NTOK + n] = acc[e] + sbg[e];
        g_mask[n] = 0u;
    }
}

// ---------------- expert-choice: radix select top-K per expert ----------------
__device__ __forceinline__ unsigned f2key(float f) {
    unsigned u = __float_as_uint(f);
    return (u & 0x80000000u) ? ~u : (u | 0x80000000u);
}

__global__ void __launch_bounds__(1024) select_kernel() {
    __shared__ unsigned hist[256];
    __shared__ unsigned sh_digit, sh_need;
    __shared__ int ccount[64];
    __shared__ int cbase[64];

    int e = blockIdx.x, tid = threadIdx.x;
    int lane = tid & 31, warp = tid >> 5;
    const float* base = g_logits + (size_t)e * NTOK;

    unsigned prefix = 0, pmask = 0, need = KCAP;
    for (int pass = 0; pass < 4; pass++) {
        int shift = 24 - pass*8;
        if (tid < 256) hist[tid] = 0;
        __syncthreads();
        for (int n = tid; n < NTOK; n += 1024) {
            unsigned k = f2key(base[n]);
            bool act = ((k & pmask) == prefix);
            unsigned dg = act ? ((k >> shift) & 255u) : 0xffffffffu;
            unsigned peers = __match_any_sync(0xffffffffu, dg);
            if (act && (__ffs(peers) - 1) == lane)
                atomicAdd(&hist[dg], (unsigned)__popc(peers));
        }
        __syncthreads();
        if (tid == 0) {
            unsigned cum = 0; int d = 255;
            for (; d > 0; d--) {
                unsigned h = hist[d];
                if (cum + h >= need) break;
                cum += h;
            }
            sh_digit = (unsigned)d;
            sh_need  = need - cum;
        }
        __syncthreads();
        prefix |= sh_digit << shift;
        pmask  |= 0xFFu << shift;
        need    = sh_need;
        __syncthreads();
    }
    unsigned thr = prefix;
    int r = (int)need;

    for (int n = tid; n < NTOK; n += 1024)
        if (f2key(base[n]) > thr) atomicOr(&g_mask[n], 1u << e);

    for (int c = warp; c < 64; c += 32) {
        int cnt = 0;
        for (int s = 0; s < 32; s++) {
            int n = c*1024 + s*32 + lane;
            cnt += (f2key(base[n]) == thr);
        }
        #pragma unroll
        for (int o = 16; o; o >>= 1) cnt += __shfl_xor_sync(0xffffffffu, cnt, o);
        if (lane == 0) ccount[c] = cnt;
    }
    __syncthreads();
    if (tid == 0) {
        int run = 0;
        for (int c = 0; c < 64; c++) { cbase[c] = run; run += ccount[c]; }
    }
    __syncthreads();
    for (int c = warp; c < 64; c += 32) {
        int rank = cbase[c];
        if (rank >= r) continue;
        for (int s = 0; s < 32; s++) {
            int n = c*1024 + s*32 + lane;
            bool p = (f2key(base[n]) == thr);
            unsigned bal = __ballot_sync(0xffffffffu, p);
            int myrank = rank + __popc(bal & ((1u << lane) - 1u));
            if (p && myrank < r) atomicOr(&g_mask[n], 1u << e);
            rank += __popc(bal);
        }
    }
}

// ---------------- routing (block-aggregated dispatch) ----------------
__global__ void __launch_bounds__(256) route_kernel(float* __restrict__ out) {
    __shared__ int sCnt[8], sBase[8];
    int tid = threadIdx.x;
    int n = blockIdx.x * 256 + tid;
    if (tid < 8) sCnt[tid] = 0;
    __syncthreads();

    float l[8];
    #pragma unroll
    for (int e = 0; e < 8; e++) l[e] = g_logits[e*NTOK + n];
    unsigned m = g_mask[n];
    if (m == 0u) {
        int best = 0; float bv = l[0];
        #pragma unroll
        for (int e = 1; e < 8; e++) if (l[e] > bv) { bv = l[e]; best = e; }
        m = 1u << best;
    }
    int e0 = -1, e1 = -1; float v0 = -INFINITY, v1 = -INFINITY;
    #pragma unroll
    for (int e = 0; e < 8; e++) {
        if ((m >> e) & 1u) {
            float f = l[e];
            if (f > v0)      { v1 = v0; e1 = e0; v0 = f; e0 = e; }
            else if (f > v1) { v1 = f; e1 = e; }
        }
    }
    float w0 = 1.f, w1 = 0.f;
    if (e1 >= 0) {
        float ex = expf(v1 - v0);
        w0 = 1.0f / (1.0f + ex);
        w1 = ex * w0;
    }
    bool has1 = (e1 >= 0 && w1 > 0.f);
    int p0 = atomicAdd(&sCnt[e0], 1);
    int p1 = has1 ? atomicAdd(&sCnt[e1], 1) : -1;
    __syncthreads();
    if (tid < 8) sBase[tid] = atomicAdd(&g_cnt[tid], sCnt[tid]);
    __syncthreads();
    {
        int pos = sBase[e0] + p0;
        g_list[e0*NTOK + pos] = n;
        g_wl[e0*NTOK + pos]   = w0;
    }
    unsigned te = (unsigned)e0 | (255u << 8);
    float tw1 = 0.f;
    if (has1) {
        int pos = sBase[e1] + p1;
        g_list[e1*NTOK + pos] = n;
        g_wl[e1*NTOK + pos]   = w1;
        te = (unsigned)e0 | ((unsigned)e1 << 8);
        tw1 = w1;
    }
    g_te[n] = te; g_tw0[n] = w0; g_tw1[n] = tw1;

    float4 z4 = make_float4(0.f, 0.f, 0.f, 0.f);
    float4* o4 = (float4*)out;
    for (int i = n; i < NTOK*OUTD/4; i += NTOK) o4[i] = z4;
}

// ---------------- fused expert FFN v11: bf16-split m16n8k16 MMA ----------------
__global__ void __launch_bounds__(256) ffn_kernel(
    const float* __restrict__ x,  const float* __restrict__ bw,
    const float* __restrict__ b1, const float* __restrict__ b2,
    const float* __restrict__ A1, const float* __restrict__ A2,
    float* __restrict__ out)
{
    extern __shared__ float sm[];
    unsigned* um = (unsigned*)sm;
    unsigned short* us = (unsigned short*)sm;
    float* sBw = sm + OFF_BW;
    float* sGw = sm + OFF_GW;
    int*   sTok = (int*)(sm + OFF_TOK);

    int e = blockIdx.y;
    int cnt = g_cnt[e];
    int t0 = blockIdx.x * TTILE;
    if (t0 >= cnt) return;
    int nt = min(TTILE, cnt - t0);
    int tid = threadIdx.x;

    if (tid < TTILE) {
        int idx = t0 + min(tid, nt - 1);
        int tok = g_list[e*NTOK + idx];
        sTok[tid] = tok;
        sGw[tid]  = (tid < nt) ? g_wl[e*NTOK + idx] : 0.f;
        *(float4*)(sBw + tid*4) = *(const float4*)(bw + (size_t)tok*4);
    }
    __syncthreads();

    {   // gather x -> packed bf16 hi/lo planes [tok][k]; stage A1 raw
        int t = tid & 31, part = tid >> 5;
        int tok = sTok[t];
        const float4* src = (const float4*)(x + (size_t)tok*CIN) + part*6;
        unsigned* dh = um + t*XW32 + part*12;
        unsigned* dl = um + OFF_XL + t*XW32 + part*12;
        #pragma unroll
        for (int i = 0; i < 6; i++) {
            float4 v = src[i];
            unsigned short h0,l0,h1,l1,h2,l2,h3,l3;
            bfsplit(v.x,h0,l0); bfsplit(v.y,h1,l1);
            bfsplit(v.z,h2,l2); bfsplit(v.w,h3,l3);
            dh[2*i]   = (unsigned)h0 | ((unsigned)h1 << 16);
            dh[2*i+1] = (unsigned)h2 | ((unsigned)h3 << 16);
            dl[2*i]   = (unsigned)l0 | ((unsigned)l1 << 16);
            dl[2*i+1] = (unsigned)l2 | ((unsigned)l3 << 16);
        }
        const float4* a4 = (const float4*)(A1 + (size_t)e*6144);
        float4* w4 = (float4*)(sm + OFF_A1);
        for (int i = tid; i < 1536; i += 256) w4[i] = a4[i];
    }
    __syncthreads();

    // LoRA1: thread = (token, band, r-half); x reconstructed from planes
    {
        int t = tid >> 3, b = (tid >> 1) & 3, rh = tid & 1, r0 = rh*4;
        const float* A = sm + OFF_A1 + b*1536 + r0;
        float acc[4] = {0,0,0,0};
        for (int c = 0; c < CIN; c++) {
            float xv = bf2f(us[t*232 + c]) + bf2f(us[2*OFF_XL + t*232 + c]);
            float4 av = *(const float4*)(A + c*8);
            acc[0] = fmaf(xv, av.x, acc[0]); acc[1] = fmaf(xv, av.y, acc[1]);
            acc[2] = fmaf(xv, av.z, acc[2]); acc[3] = fmaf(xv, av.w, acc[3]);
        }
        float scl = LSCALE * sBw[t*4 + b];
        int ub = t*XW32 + 96 + b*4 + rh*2;   // k=192+b*8+rh*4, u32 pairs
        #pragma unroll
        for (int j = 0; j < 2; j++) {
            unsigned short ha,la,hb,lb;
            bfsplit(scl*acc[2*j],   ha, la);
            bfsplit(scl*acc[2*j+1], hb, lb);
            um[ub + j]          = (unsigned)ha | ((unsigned)hb << 16);
            um[OFF_XL + ub + j] = (unsigned)la | ((unsigned)lb << 16);
        }
    }

    int warp = tid >> 5, lane = tid & 31;
    int g = lane >> 2, kq = lane & 3;

    // ---- layer 1: [32,224]x[224,384]; warp = 2 M-tiles x 48 cols ----
    float d1[2][6][4];
    #pragma unroll
    for (int nj = 0; nj < 6; nj++) {
        int col = warp*48 + nj*8 + 2*kq;
        float b0v = b1[e*HID + col], b1v = b1[e*HID + col + 1];
        #pragma unroll
        for (int mt = 0; mt < 2; mt++) {
            d1[mt][nj][0] = b0v; d1[mt][nj][1] = b1v;
            d1[mt][nj][2] = b0v; d1[mt][nj][3] = b1v;
        }
    }
    const unsigned* w1h = g_w1h + (size_t)e*W1PE;
    const unsigned* w1l = g_w1l + (size_t)e*W1PE;
    {   // prologue: copy tile 0 (3136 u32/plane)
        const float4* gh = (const float4*)w1h;
        const float4* gl = (const float4*)w1l;
        float4* dh = (float4*)(um + OFF_WB);
        float4* dl = (float4*)(um + OFF_WB + PLO);
        #pragma unroll
        for (int j = 0; j < 4; j++) {
            int idx = tid + j*256;
            if (idx < 784) { dh[idx] = gh[idx]; dl[idx] = gl[idx]; }
        }
    }
    float4 ph[4], pl[4];
    for (int kt = 0; kt < 14; kt++) {
        if (kt < 13) {
            const float4* gh = (const float4*)(w1h + (kt+1)*3136);
            const float4* gl = (const float4*)(w1l + (kt+1)*3136);
            #pragma unroll
            for (int j = 0; j < 4; j++) {
                int idx = tid + j*256;
                if (idx < 784) { ph[j] = gh[idx]; pl[j] = gl[idx]; }
            }
        }
        __syncthreads();
        const unsigned* Wh = um + OFF_WB + (kt&1)*WBUF;
        const unsigned* Wl = Wh + PLO;
        unsigned ah[2][4], al[2][4];
        #pragma unroll
        for (int mt = 0; mt < 2; mt++) {
            int base = (mt*16 + g)*XW32 + kt*8 + kq;
            ah[mt][0] = um[base];              al[mt][0] = um[OFF_XL + base];
            ah[mt][1] = um[base + 8*XW32];     al[mt][1] = um[OFF_XL + base + 8*XW32];
            ah[mt][2] = um[base + 4];          al[mt][2] = um[OFF_XL + base + 4];
            ah[mt][3] = um[base + 8*XW32 + 4]; al[mt][3] = um[OFF_XL + base + 8*XW32 + 4];
        }
        #pragma unroll
        for (int nj = 0; nj < 6; nj++) {
            int n = warp*48 + nj*8 + g;
            unsigned bh0 = Wh[kq*392 + n], bh1 = Wh[(kq+4)*392 + n];
            unsigned bl0 = Wl[kq*392 + n], bl1 = Wl[(kq+4)*392 + n];
            #pragma unroll
            for (int mt = 0; mt < 2; mt++) {
                mma16(d1[mt][nj], ah[mt], bh0, bh1);
                mma16(d1[mt][nj], ah[mt], bl0, bl1);
                mma16(d1[mt][nj], al[mt], bh0, bh1);
            }
        }
        if (kt < 13) {
            float4* dh = (float4*)(um + OFF_WB + ((kt+1)&1)*WBUF);
            float4* dl = (float4*)(um + OFF_WB + ((kt+1)&1)*WBUF + PLO);
            #pragma unroll
            for (int j = 0; j < 4; j++) {
                int idx = tid + j*256;
                if (idx < 784) { dh[idx] = ph[j]; dl[idx] = pl[j]; }
            }
        }
    }
    __syncthreads();   // X reads done; H overwrites region

    // exact GELU -> packed bf16 split H [tok][h]
    #pragma unroll
    for (int mt = 0; mt < 2; mt++)
        #pragma unroll
        for (int nj = 0; nj < 6; nj++) {
            int uc = warp*24 + nj*4 + kq;
            #pragma unroll
            for (int half = 0; half < 2; half++) {
                int t = mt*16 + g + half*8;
                float v0 = d1[mt][nj][2*half], v1 = d1[mt][nj][2*half + 1];
                float g0 = v0 * 0.5f * (1.0f + erff(v0 * 0.70710678118654752f));
                float g1 = v1 * 0.5f * (1.0f + erff(v1 * 0.70710678118654752f));
                unsigned short h0,l0,h1,l1;
                bfsplit(g0,h0,l0); bfsplit(g1,h1,l1);
                um[t*HW32 + uc]          = (unsigned)h0 | ((unsigned)h1 << 16);
                um[OFF_HL + t*HW32 + uc] = (unsigned)l0 | ((unsigned)l1 << 16);
            }
        }
    __syncthreads();

    // LoRA2: thread = (token, band, r-half)
    {
        int t = tid >> 3, b = (tid >> 1) & 3, rh = tid & 1, r0 = rh*4;
        const float* A = A2 + ((size_t)e*4 + b)*HID*8 + r0;
        float acc[4] = {0,0,0,0};
        for (int hh = 0; hh < HID; hh++) {
            float hv = bf2f(us[t*424 + hh]) + bf2f(us[2*OFF_HL + t*424 + hh]);
            float4 av = *(const float4*)(A + hh*8);
            acc[0] = fmaf(hv, av.x, acc[0]); acc[1] = fmaf(hv, av.y, acc[1]);
            acc[2] = fmaf(hv, av.z, acc[2]); acc[3] = fmaf(hv, av.w, acc[3]);
        }
        float scl = LSCALE * sBw[t*4 + b];
        int ub = t*HW32 + 192 + b*4 + rh*2;
        #pragma unroll
        for (int j = 0; j < 2; j++) {
            unsigned short ha,la,hb,lb;
            bfsplit(scl*acc[2*j],   ha, la);
            bfsplit(scl*acc[2*j+1], hb, lb);
            um[ub + j]          = (unsigned)ha | ((unsigned)hb << 16);
            um[OFF_HL + ub + j] = (unsigned)la | ((unsigned)lb << 16);
        }
    }

    // ---- layer 2: [32,416]x[416,192]; warp = 2 M-tiles x 24 cols ----
    float d2[2][3][4];
    #pragma unroll
    for (int nj = 0; nj < 3; nj++) {
        int col = warp*24 + nj*8 + 2*kq;
        float b0v = b2[e*OUTD + col], b1v = b2[e*OUTD + col + 1];
        #pragma unroll
        for (int mt = 0; mt < 2; mt++) {
            d2[mt][nj][0] = b0v; d2[mt][nj][1] = b1v;
            d2[mt][nj][2] = b0v; d2[mt][nj][3] = b1v;
        }
    }
    const unsigned* w2h = g_w2h + (size_t)e*W2PE;
    const unsigned* w2l = g_w2l + (size_t)e*W2PE;
    {   // prologue: copy tile 0 (1600 u32/plane)
        const float4* gh = (const float4*)w2h;
        const float4* gl = (const float4*)w2l;
        float4* dh = (float4*)(um + OFF_WB);
        float4* dl = (float4*)(um + OFF_WB + PLO);
        #pragma unroll
        for (int j = 0; j < 2; j++) {
            int idx = tid + j*256;
            if (idx < 400) { dh[idx] = gh[idx]; dl[idx] = gl[idx]; }
        }
    }
    for (int kt = 0; kt < 26; kt++) {
        if (kt < 25) {
            const float4* gh = (const float4*)(w2h + (kt+1)*1600);
            const float4* gl = (const float4*)(w2l + (kt+1)*1600);
            #pragma unroll
            for (int j = 0; j < 2; j++) {
                int idx = tid + j*256;
                if (idx < 400) { ph[j] = gh[idx]; pl[j] = gl[idx]; }
            }
        }
        __syncthreads();
        const unsigned* Wh = um + OFF_WB + (kt&1)*WBUF;
        const unsigned* Wl = Wh + PLO;
        unsigned ah[2][4], al[2][4];
        #pragma unroll
        for (int mt = 0; mt < 2; mt++) {
            int base = (mt*16 + g)*HW32 + kt*8 + kq;
            ah[mt][0] = um[base];              al[mt][0] = um[OFF_HL + base];
            ah[mt][1] = um[base + 8*HW32];     al[mt][1] = um[OFF_HL + base + 8*HW32];
            ah[mt][2] = um[base + 4];          al[mt][2] = um[OFF_HL + base + 4];
            ah[mt][3] = um[base + 8*HW32 + 4]; al[mt][3] = um[OFF_HL + base + 8*HW32 + 4];
        }
        #pragma unroll
        for (int nj = 0; nj < 3; nj++) {
            int n = warp*24 + nj*8 + g;
            unsigned bh0 = Wh[kq*200 + n], bh1 = Wh[(kq+4)*200 + n];
            unsigned bl0 = Wl[kq*200 + n], bl1 = Wl[(kq+4)*200 + n];
            #pragma unroll
            for (int mt = 0; mt < 2; mt++) {
                mma16(d2[mt][nj], ah[mt], bh0, bh1);
                mma16(d2[mt][nj], ah[mt], bl0, bl1);
                mma16(d2[mt][nj], al[mt], bh0, bh1);
            }
        }
        if (kt < 25) {
            float4* dh = (float4*)(um + OFF_WB + ((kt+1)&1)*WBUF);
            float4* dl = (float4*)(um + OFF_WB + ((kt+1)&1)*WBUF + PLO);
            #pragma unroll
            for (int j = 0; j < 2; j++) {
                int idx = tid + j*256;
                if (idx < 400) { dh[idx] = ph[j]; dl[idx] = pl[j]; }
            }
        }
    }
    // epilogue
    #pragma unroll
    for (int mt = 0; mt < 2; mt++)
        #pragma unroll
        for (int nj = 0; nj < 3; nj++) {
            int col = warp*24 + nj*8 + 2*kq;
            #pragma unroll
            for (int q = 0; q < 4; q++) {
                int t = mt*16 + g + (q >> 1)*8;
                if (t < nt) {
                    int tok = sTok[t];
                    atomicAdd(&out[(size_t)tok*OUTD + col + (q & 1)],
                              sGw[t]*d2[mt][nj][q]);
                }
            }
        }
}

// ---------------- deterministic loss ----------------
__global__ void __launch_bounds__(1024) loss_kernel(float* out, int out_size) {
    __shared__ float sI[8][32], sL[8][32];
    int tid = threadIdx.x, lane = tid & 31, warp = tid >> 5;
    float imp[8] = {0,0,0,0,0,0,0,0}, ld[8] = {0,0,0,0,0,0,0,0};
    for (int n = tid; n < NTOK; n += 1024) {
        unsigned te = g_te[n];
        int e0 = te & 255u, e1 = (te >> 8) & 255u;
        imp[e0] += g_tw0[n]; ld[e0] += 1.f;
        if (e1 != 255) { imp[e1] += g_tw1[n]; ld[e1] += 1.f; }
    }
    #pragma unroll
    for (int e = 0; e < 8; e++) {
        #pragma unroll
        for (int o = 16; o; o >>= 1) {
            imp[e] += __shfl_xor_sync(0xffffffffu, imp[e], o);
            ld[e]  += __shfl_xor_sync(0xffffffffu, ld[e],  o);
        }
        if (lane == 0) { sI[e][warp] = imp[e]; sL[e][warp] = ld[e]; }
    }
    __syncthreads();
    if (tid == 0) {
        float I[8], L[8], mi = 0.f, ml = 0.f;
        for (int e = 0; e < 8; e++) {
            float a = 0.f, b = 0.f;
            for (int w = 0; w < 32; w++) { a += sI[e][w]; b += sL[e][w]; }
            I[e] = a; L[e] = b; mi += a; ml += b;
        }
        mi *= 0.125f; ml *= 0.125f;
        float vi = 0.f, vl = 0.f;
        for (int e = 0; e < 8; e++) {
            float di = I[e] - mi; vi += di*di;
            float dl = L[e] - ml; vl += dl*dl;
        }
        vi *= 0.125f; vl *= 0.125f;
        float loss = (vi / (mi*mi + 1e-10f) + vl / (ml*ml + 1e-10f)) * 0.01f;
        if (out_size > NTOK*OUTD) out[NTOK*OUTD] = loss;
    }
    for (int i = NTOK*OUTD + 1 + tid; i < out_size; i += 1024) out[i] = 0.f;
}

// ---------------- launch ----------------
extern "C" void kernel_launch(void* const* d_in, const int* in_sizes, int n_in,
                              void* d_out, int out_size) {
    const float* x     = (const float*)d_in[0];
    const float* bw    = (const float*)d_in[1];
    const float* xprev = (const float*)d_in[2];
    const float* Wz    = (const float*)d_in[3];
    const float* lng   = (const float*)d_in[4];
    const float* lnb   = (const float*)d_in[5];
    const float* Wg    = (const float*)d_in[6];
    const float* bg    = (const float*)d_in[7];
    const float* W1    = (const float*)d_in[8];
    const float* b1    = (const float*)d_in[9];
    const float* W2    = (const float*)d_in[10];
    const float* b2    = (const float*)d_in[11];
    const float* A1    = (const float*)d_in[12];
    const float* B1    = (const float*)d_in[13];
    const float* A2    = (const float*)d_in[14];
    const float* B2    = (const float*)d_in[15];
    float* out = (float*)d_out;

    const size_t GATE_SMEM = (size_t)(12288 + 2322 + 258 + 258 + 8 + 32*192) * 4;
    const size_t FFN_SMEM  = (size_t)FFN_U32 * 4;
    cudaFuncSetAttribute(gate_kernel, cudaFuncAttributeMaxDynamicSharedMemorySize, (int)GATE_SMEM);
    cudaFuncSetAttribute(ffn_kernel,  cudaFuncAttributeMaxDynamicSharedMemorySize, (int)FFN_SMEM);

    init_kernel<<<1, 32>>>();
    split_kernel<<<336, 1024>>>(W1, B1, W2, B2);
    gate_kernel<<<NTOK/32, 1024, GATE_SMEM>>>(x, xprev, Wz, lng, lnb, Wg, bg);
    select_kernel<<<NE, 1024>>>();
    route_kernel<<<NTOK/256, 256>>>(out);
    ffn_kernel<<<dim3(NTOK/TTILE, NE), 256, FFN_SMEM>>>(x, bw, b1, b2, A1, A2, out);
    loss_kernel<<<1, 1024>>>(out, out_size);
}

// round 12
// speedup vs baseline: 1.2991x; 1.0831x over previous
#include <cuda_runtime.h>
#include <math.h>
#include <stdint.h>

#define NTOK 65536
#define CIN 192
#define HID 384
#define OUTD 192
#define NE 8
#define KCAP 10240
#define TTILE 64
#define LSCALE 2.0f

// FFN smem (u32 units); X and H planes share one union (x dead before h written)
#define XW32   116      /* x plane stride: 232 bf16 */
#define HW32   212      /* h plane stride: 424 bf16 */
#define OFF_XL 7424     /* 64*116 */
#define OFF_HL 13568    /* 64*212 */
#define OFF_A1 27136
#define OFF_WB 33280
#define WBUF   6272
#define PLO    3136
#define OFF_BW 45824
#define OFF_GW 46080
#define OFF_TOK 46144
#define FFN_U32 46208

#define W1PE 43904      /* per-expert u32: 112*392 */
#define W2PE 41600      /* 208*200 */

__device__ __forceinline__ unsigned short f2bf(float x) {
    unsigned u = __float_as_uint(x);
    return (unsigned short)((u + 0x7fffu + ((u >> 16) & 1u)) >> 16);
}
__device__ __forceinline__ float bf2f(unsigned short b) {
    return __uint_as_float((unsigned)b << 16);
}
__device__ __forceinline__ void bfsplit(float x, unsigned short& h, unsigned short& l) {
    h = f2bf(x);
    l = f2bf(x - bf2f(h));
}
__device__ __forceinline__ void mma16(float* d, const unsigned* a, unsigned b0, unsigned b1) {
    asm("mma.sync.aligned.m16n8k16.row.col.f32.bf16.bf16.f32 "
        "{%0,%1,%2,%3},{%4,%5,%6,%7},{%8,%9},{%0,%1,%2,%3};"
        : "+f"(d[0]), "+f"(d[1]), "+f"(d[2]), "+f"(d[3])
        : "r"(a[0]), "r"(a[1]), "r"(a[2]), "r"(a[3]), "r"(b0), "r"(b1));
}

// ---------------- device scratch ----------------
__device__ float    g_logits[NE * NTOK];
__device__ unsigned g_mask[NTOK];
__device__ int      g_cnt[NE];
__device__ int      g_list[NE * NTOK];
__device__ float    g_wl[NE * NTOK];
__device__ unsigned g_te[NTOK];
__device__ float    g_tw0[NTOK];
__device__ float    g_tw1[NTOK];
__device__ __align__(16) unsigned g_w1h[NE*W1PE];
__device__ __align__(16) unsigned g_w1l[NE*W1PE];
__device__ __align__(16) unsigned g_w2h[NE*W2PE];
__device__ __align__(16) unsigned g_w2l[NE*W2PE];

__global__ void init_kernel() {
    if (threadIdx.x < NE) g_cnt[threadIdx.x] = 0;
}

// ---------------- one-shot weight split: packed k-pair bf16 hi/lo planes ----
__global__ void __launch_bounds__(1024) split_kernel(
    const float* __restrict__ W1, const float* __restrict__ B1,
    const float* __restrict__ W2, const float* __restrict__ B2)
{
    int i = blockIdx.x * 1024 + threadIdx.x;
    if (i < NE*112*384) {
        int e = i / 43008, rem = i % 43008;
        int kp = rem / 384, n = rem % 384;
        int k0 = 2*kp, k1 = k0 + 1;
        float v0 = (k0 < 192) ? W1[((size_t)e*192 + k0)*384 + n]
                              : B1[((size_t)e*32 + (k0-192))*384 + n];
        float v1 = (k1 < 192) ? W1[((size_t)e*192 + k1)*384 + n]
                              : B1[((size_t)e*32 + (k1-192))*384 + n];
        unsigned short h0,l0,h1,l1;
        bfsplit(v0,h0,l0); bfsplit(v1,h1,l1);
        g_w1h[(size_t)e*W1PE + kp*392 + n] = (unsigned)h0 | ((unsigned)h1 << 16);
        g_w1l[(size_t)e*W1PE + kp*392 + n] = (unsigned)l0 | ((unsigned)l1 << 16);
    }
    if (i < NE*208*192) {
        int e = i / 39936, rem = i % 39936;
        int kp = rem / 192, n = rem % 192;
        int k0 = 2*kp, k1 = k0 + 1;
        float v0 = (k0 < 384) ? W2[((size_t)e*384 + k0)*192 + n]
                              : B2[((size_t)e*32 + (k0-384))*192 + n];
        float v1 = (k1 < 384) ? W2[((size_t)e*384 + k1)*192 + n]
                              : B2[((size_t)e*32 + (k1-384))*192 + n];
        unsigned short h0,l0,h1,l1;
        bfsplit(v0,h0,l0); bfsplit(v1,h1,l1);
        g_w2h[(size_t)e*W2PE + kp*200 + n] = (unsigned)h0 | ((unsigned)h1 << 16);
        g_w2l[(size_t)e*W2PE + kp*200 + n] = (unsigned)l0 | ((unsigned)l1 << 16);
    }
}

// ---------------- gate: features + LN + logits ----------------
__global__ void __launch_bounds__(1024) gate_kernel(
    const float* __restrict__ x, const float* __restrict__ xprev,
    const float* __restrict__ Wz, const float* __restrict__ lng,
    const float* __restrict__ lnb, const float* __restrict__ Wg,
    const float* __restrict__ bg)
{
    extern __shared__ float sm[];
    float* sWz = sm;
    float* sWg = sWz + 12288;
    float* sg  = sWg + 2322;
    float* sb  = sg + 258;
    float* sbg = sb + 258;
    float* sX  = sbg + 8;

    int tid = threadIdx.x, lane = tid & 31, warp = tid >> 5;
    int n = blockIdx.x * 32 + warp;

    for (int i = tid; i < 12288; i += 1024) sWz[i] = Wz[i];
    for (int i = tid; i < 2064;  i += 1024) sWg[(i >> 3)*9 + (i & 7)] = Wg[i];
    for (int i = tid; i < 258;   i += 1024) { sg[i] = lng[i]; sb[i] = lnb[i]; }
    if (tid < 8) sbg[tid] = bg[tid];

    float xr[6];
    #pragma unroll
    for (int i = 0; i < 6; i++) {
        xr[i] = x[(size_t)n*CIN + lane + 32*i];
        sX[warp*CIN + lane + 32*i] = xr[i];
    }
    float s = 0.f, ss = 0.f;
    #pragma unroll
    for (int i = 0; i < 6; i++) {
        float a = fabsf(xr[i] - xprev[(size_t)n*CIN + lane + 32*i]);
        s += a; ss += a*a;
    }
    #pragma unroll
    for (int o = 16; o; o >>= 1) {
        s  += __shfl_xor_sync(0xffffffffu, s, o);
        ss += __shfl_xor_sync(0xffffffffu, ss, o);
    }
    float dmean = s * (1.0f/192.0f);
    float dvar  = fmaxf((ss - s*dmean) * (1.0f/191.0f), 0.f);
    float mu = log1pf(dmean), sd = log1pf(sqrtf(dvar));

    __syncthreads();

    float z0 = 0.f, z1 = 0.f;
    for (int c = 0; c < CIN; c++) {
        float xv = sX[warp*CIN + c];
        z0 = fmaf(xv, sWz[c*64 + lane],      z0);
        z1 = fmaf(xv, sWz[c*64 + lane + 32], z1);
    }
    float sa = z0 + z1, s2 = z0*z0 + z1*z1;
    #pragma unroll
    for (int i = 0; i < 6; i++) { sa += xr[i]; s2 += xr[i]*xr[i]; }
    if (lane == 0) { sa += mu + sd; s2 += mu*mu + sd*sd; }
    #pragma unroll
    for (int o = 16; o; o >>= 1) {
        sa += __shfl_xor_sync(0xffffffffu, sa, o);
        s2 += __shfl_xor_sync(0xffffffffu, s2, o);
    }
    float m_   = sa * (1.0f/258.0f);
    float rstd = rsqrtf(s2 * (1.0f/258.0f) - m_*m_ + 1e-5f);

    float acc[8] = {0,0,0,0,0,0,0,0};
    #pragma unroll
    for (int i = 0; i < 6; i++) {
        int idx = lane + 32*i;
        float nv = (xr[i] - m_)*rstd*sg[idx] + sb[idx];
        #pragma unroll
        for (int e = 0; e < 8; e++) acc[e] = fmaf(nv, sWg[idx*9 + e], acc[e]);
    }
    {
        int idx = 192 + lane;
        float nv = (z0 - m_)*rstd*sg[idx] + sb[idx];
        #pragma unroll
        for (int e = 0; e < 8; e++) acc[e] = fmaf(nv, sWg[idx*9 + e], acc[e]);
        idx = 224 + lane;
        nv = (z1 - m_)*rstd*sg[idx] + sb[idx];
        #pragma unroll
        for (int e = 0; e < 8; e++) acc[e] = fmaf(nv, sWg[idx*9 + e], acc[e]);
    }
    if (lane == 0) {
        float nv = (mu - m_)*rstd*sg[256] + sb[256];
        #pragma unroll
        for (int e = 0; e < 8; e++) acc[e] = fmaf(nv, sWg[256*9 + e], acc[e]);
        nv = (sd - m_)*rstd*sg[257] + sb[257];
        #pragma unroll
        for (int e = 0; e < 8; e++) acc[e] = fmaf(nv, sWg[257*9 + e], acc[e]);
    }
    #pragma unroll
    for (int e = 0; e < 8; e++) {
        #pragma unroll
        for (int o = 16; o; o >>= 1) acc[e] += __shfl_xor_sync(0xffffffffu, acc[e], o);
    }
    if (lane == 0) {
        #pragma unroll
        for (int e = 0; e < 8; e++) g_logits[e*NTOK + n] = acc[e] + sbg[e];
        g_mask[n] = 0u;
    }
}

// ---------------- expert-choice: radix select top-K per expert ----------------
__device__ __forceinline__ unsigned f2key(float f) {
    unsigned u = __float_as_uint(f);
    return (u & 0x80000000u) ? ~u : (u | 0x80000000u);
}

__global__ void __launch_bounds__(1024) select_kernel() {
    __shared__ unsigned hist[256];
    __shared__ unsigned sh_digit, sh_need;
    __shared__ int ccount[64];
    __shared__ int cbase[64];

    int e = blockIdx.x, tid = threadIdx.x;
    int lane = tid & 31, warp = tid >> 5;
    const float* base = g_logits + (size_t)e * NTOK;

    unsigned prefix = 0, pmask = 0, need = KCAP;
    for (int pass = 0; pass < 4; pass++) {
        int shift = 24 - pass*8;
        if (tid < 256) hist[tid] = 0;
        __syncthreads();
        for (int n = tid; n < NTOK; n += 1024) {
            unsigned k = f2key(base[n]);
            bool act = ((k & pmask) == prefix);
            unsigned dg = act ? ((k >> shift) & 255u) : 0xffffffffu;
            unsigned peers = __match_any_sync(0xffffffffu, dg);
            if (act && (__ffs(peers) - 1) == lane)
                atomicAdd(&hist[dg], (unsigned)__popc(peers));
        }
        __syncthreads();
        if (tid == 0) {
            unsigned cum = 0; int d = 255;
            for (; d > 0; d--) {
                unsigned h = hist[d];
                if (cum + h >= need) break;
                cum += h;
            }
            sh_digit = (unsigned)d;
            sh_need  = need - cum;
        }
        __syncthreads();
        prefix |= sh_digit << shift;
        pmask  |= 0xFFu << shift;
        need    = sh_need;
        __syncthreads();
    }
    unsigned thr = prefix;
    int r = (int)need;

    for (int n = tid; n < NTOK; n += 1024)
        if (f2key(base[n]) > thr) atomicOr(&g_mask[n], 1u << e);

    for (int c = warp; c < 64; c += 32) {
        int cnt = 0;
        for (int s = 0; s < 32; s++) {
            int n = c*1024 + s*32 + lane;
            cnt += (f2key(base[n]) == thr);
        }
        #pragma unroll
        for (int o = 16; o; o >>= 1) cnt += __shfl_xor_sync(0xffffffffu, cnt, o);
        if (lane == 0) ccount[c] = cnt;
    }
    __syncthreads();
    if (tid == 0) {
        int run = 0;
        for (int c = 0; c < 64; c++) { cbase[c] = run; run += ccount[c]; }
    }
    __syncthreads();
    for (int c = warp; c < 64; c += 32) {
        int rank = cbase[c];
        if (rank >= r) continue;
        for (int s = 0; s < 32; s++) {
            int n = c*1024 + s*32 + lane;
            bool p = (f2key(base[n]) == thr);
            unsigned bal = __ballot_sync(0xffffffffu, p);
            int myrank = rank + __popc(bal & ((1u << lane) - 1u));
            if (p && myrank < r) atomicOr(&g_mask[n], 1u << e);
            rank += __popc(bal);
        }
    }
}

// ---------------- routing (block-aggregated dispatch) ----------------
__global__ void __launch_bounds__(256) route_kernel(float* __restrict__ out) {
    __shared__ int sCnt[8], sBase[8];
    int tid = threadIdx.x;
    int n = blockIdx.x * 256 + tid;
    if (tid < 8) sCnt[tid] = 0;
    __syncthreads();

    float l[8];
    #pragma unroll
    for (int e = 0; e < 8; e++) l[e] = g_logits[e*NTOK + n];
    unsigned m = g_mask[n];
    if (m == 0u) {
        int best = 0; float bv = l[0];
        #pragma unroll
        for (int e = 1; e < 8; e++) if (l[e] > bv) { bv = l[e]; best = e; }
        m = 1u << best;
    }
    int e0 = -1, e1 = -1; float v0 = -INFINITY, v1 = -INFINITY;
    #pragma unroll
    for (int e = 0; e < 8; e++) {
        if ((m >> e) & 1u) {
            float f = l[e];
            if (f > v0)      { v1 = v0; e1 = e0; v0 = f; e0 = e; }
            else if (f > v1) { v1 = f; e1 = e; }
        }
    }
    float w0 = 1.f, w1 = 0.f;
    if (e1 >= 0) {
        float ex = expf(v1 - v0);
        w0 = 1.0f / (1.0f + ex);
        w1 = ex * w0;
    }
    bool has1 = (e1 >= 0 && w1 > 0.f);
    int p0 = atomicAdd(&sCnt[e0], 1);
    int p1 = has1 ? atomicAdd(&sCnt[e1], 1) : -1;
    __syncthreads();
    if (tid < 8) sBase[tid] = atomicAdd(&g_cnt[tid], sCnt[tid]);
    __syncthreads();
    {
        int pos = sBase[e0] + p0;
        g_list[e0*NTOK + pos] = n;
        g_wl[e0*NTOK + pos]   = w0;
    }
    unsigned te = (unsigned)e0 | (255u << 8);
    float tw1 = 0.f;
    if (has1) {
        int pos = sBase[e1] + p1;
        g_list[e1*NTOK + pos] = n;
        g_wl[e1*NTOK + pos]   = w1;
        te = (unsigned)e0 | ((unsigned)e1 << 8);
        tw1 = w1;
    }
    g_te[n] = te; g_tw0[n] = w0; g_tw1[n] = tw1;

    float4 z4 = make_float4(0.f, 0.f, 0.f, 0.f);
    float4* o4 = (float4*)out;
    for (int i = n; i < NTOK*OUTD/4; i += NTOK) o4[i] = z4;
}

// ---------------- fused expert FFN v12: 64-token tiles, bf16-split MMA ----------
__global__ void __launch_bounds__(256) ffn_kernel(
    const float* __restrict__ x,  const float* __restrict__ bw,
    const float* __restrict__ b1, const float* __restrict__ b2,
    const float* __restrict__ A1, const float* __restrict__ A2,
    float* __restrict__ out)
{
    extern __shared__ float sm[];
    unsigned* um = (unsigned*)sm;
    unsigned short* us = (unsigned short*)sm;
    float* sBw = sm + OFF_BW;
    float* sGw = sm + OFF_GW;
    int*   sTok = (int*)(sm + OFF_TOK);

    int e = blockIdx.y;
    int cnt = g_cnt[e];
    int t0 = blockIdx.x * TTILE;
    if (t0 >= cnt) return;
    int nt = min(TTILE, cnt - t0);
    int tid = threadIdx.x;

    if (tid < TTILE) {
        int idx = t0 + min(tid, nt - 1);
        int tok = g_list[e*NTOK + idx];
        sTok[tid] = tok;
        sGw[tid]  = (tid < nt) ? g_wl[e*NTOK + idx] : 0.f;
        *(float4*)(sBw + tid*4) = *(const float4*)(bw + (size_t)tok*4);
    }
    __syncthreads();

    {   // gather x -> packed bf16 hi/lo planes [tok][k]; stage A1 raw
        int t = tid & 63;
        int tok = sTok[t];
        #pragma unroll
        for (int pp = 0; pp < 2; pp++) {
            int part = (tid >> 6)*2 + pp;    // 0..7, 24 cols each
            const float4* src = (const float4*)(x + (size_t)tok*CIN) + part*6;
            unsigned* dh = um + t*XW32 + part*12;
            unsigned* dl = um + OFF_XL + t*XW32 + part*12;
            #pragma unroll
            for (int i = 0; i < 6; i++) {
                float4 v = src[i];
                unsigned short h0,l0,h1,l1,h2,l2,h3,l3;
                bfsplit(v.x,h0,l0); bfsplit(v.y,h1,l1);
                bfsplit(v.z,h2,l2); bfsplit(v.w,h3,l3);
                dh[2*i]   = (unsigned)h0 | ((unsigned)h1 << 16);
                dh[2*i+1] = (unsigned)h2 | ((unsigned)h3 << 16);
                dl[2*i]   = (unsigned)l0 | ((unsigned)l1 << 16);
                dl[2*i+1] = (unsigned)l2 | ((unsigned)l3 << 16);
            }
        }
        const float4* a4 = (const float4*)(A1 + (size_t)e*6144);
        float4* w4 = (float4*)(sm + OFF_A1);
        for (int i = tid; i < 1536; i += 256) w4[i] = a4[i];
    }
    __syncthreads();

    // LoRA1: thread = (token, band), full r=8; x reconstructed from planes
    {
        int t = tid >> 2, b = tid & 3;
        const float* A = sm + OFF_A1 + b*1536;
        float acc[8] = {0,0,0,0,0,0,0,0};
        for (int c = 0; c < CIN; c++) {
            float xv = bf2f(us[t*232 + c]) + bf2f(us[2*OFF_XL + t*232 + c]);
            float4 a0 = *(const float4*)(A + c*8);
            float4 a1 = *(const float4*)(A + c*8 + 4);
            acc[0]=fmaf(xv,a0.x,acc[0]); acc[1]=fmaf(xv,a0.y,acc[1]);
            acc[2]=fmaf(xv,a0.z,acc[2]); acc[3]=fmaf(xv,a0.w,acc[3]);
            acc[4]=fmaf(xv,a1.x,acc[4]); acc[5]=fmaf(xv,a1.y,acc[5]);
            acc[6]=fmaf(xv,a1.z,acc[6]); acc[7]=fmaf(xv,a1.w,acc[7]);
        }
        float scl = LSCALE * sBw[t*4 + b];
        int ub = t*XW32 + 96 + b*4;          // k = 192 + b*8, u32 pairs
        #pragma unroll
        for (int j = 0; j < 4; j++) {
            unsigned short ha,la,hb,lb;
            bfsplit(scl*acc[2*j],   ha, la);
            bfsplit(scl*acc[2*j+1], hb, lb);
            um[ub + j]          = (unsigned)ha | ((unsigned)hb << 16);
            um[OFF_XL + ub + j] = (unsigned)la | ((unsigned)lb << 16);
        }
    }

    int warp = tid >> 5, lane = tid & 31;
    int g = lane >> 2, kq = lane & 3;

    // ---- layer 1: [64,224]x[224,384]; warp = 4 M-tiles x 48 cols ----
    float d1[4][6][4];
    #pragma unroll
    for (int nj = 0; nj < 6; nj++) {
        int col = warp*48 + nj*8 + 2*kq;
        float b0v = b1[e*HID + col], b1v = b1[e*HID + col + 1];
        #pragma unroll
        for (int mt = 0; mt < 4; mt++) {
            d1[mt][nj][0] = b0v; d1[mt][nj][1] = b1v;
            d1[mt][nj][2] = b0v; d1[mt][nj][3] = b1v;
        }
    }
    const unsigned* w1h = g_w1h + (size_t)e*W1PE;
    const unsigned* w1l = g_w1l + (size_t)e*W1PE;
    {   // prologue: copy tile 0 (3136 u32/plane = 784 f4)
        const float4* gh = (const float4*)w1h;
        const float4* gl = (const float4*)w1l;
        float4* dh = (float4*)(um + OFF_WB);
        float4* dl = (float4*)(um + OFF_WB + PLO);
        #pragma unroll
        for (int j = 0; j < 4; j++) {
            int idx = tid + j*256;
            if (idx < 784) { dh[idx] = gh[idx]; dl[idx] = gl[idx]; }
        }
    }
    float4 ph[4], pl[4];
    for (int kt = 0; kt < 14; kt++) {
        if (kt < 13) {
            const float4* gh = (const float4*)(w1h + (kt+1)*3136);
            const float4* gl = (const float4*)(w1l + (kt+1)*3136);
            #pragma unroll
            for (int j = 0; j < 4; j++) {
                int idx = tid + j*256;
                if (idx < 784) { ph[j] = gh[idx]; pl[j] = gl[idx]; }
            }
        }
        __syncthreads();
        const unsigned* Wh = um + OFF_WB + (kt&1)*WBUF;
        const unsigned* Wl = Wh + PLO;
        #pragma unroll
        for (int mt = 0; mt < 4; mt++) {
            int base = (mt*16 + g)*XW32 + kt*8 + kq;
            unsigned ah[4], al[4];
            ah[0] = um[base];              al[0] = um[OFF_XL + base];
            ah[1] = um[base + 8*XW32];     al[1] = um[OFF_XL + base + 8*XW32];
            ah[2] = um[base + 4];          al[2] = um[OFF_XL + base + 4];
            ah[3] = um[base + 8*XW32 + 4]; al[3] = um[OFF_XL + base + 8*XW32 + 4];
            #pragma unroll
            for (int nj = 0; nj < 6; nj++) {
                int n = warp*48 + nj*8 + g;
                unsigned bh0 = Wh[kq*392 + n], bh1 = Wh[(kq+4)*392 + n];
                unsigned bl0 = Wl[kq*392 + n], bl1 = Wl[(kq+4)*392 + n];
                mma16(d1[mt][nj], ah, bh0, bh1);
                mma16(d1[mt][nj], ah, bl0, bl1);
                mma16(d1[mt][nj], al, bh0, bh1);
            }
        }
        if (kt < 13) {
            float4* dh = (float4*)(um + OFF_WB + ((kt+1)&1)*WBUF);
            float4* dl = (float4*)(um + OFF_WB + ((kt+1)&1)*WBUF + PLO);
            #pragma unroll
            for (int j = 0; j < 4; j++) {
                int idx = tid + j*256;
                if (idx < 784) { dh[idx] = ph[j]; dl[idx] = pl[j]; }
            }
        }
    }
    __syncthreads();   // X reads done; H overwrites the union region

    // exact GELU -> packed bf16 split H [tok][h]
    #pragma unroll
    for (int mt = 0; mt < 4; mt++)
        #pragma unroll
        for (int nj = 0; nj < 6; nj++) {
            int uc = warp*24 + nj*4 + kq;
            #pragma unroll
            for (int half = 0; half < 2; half++) {
                int t = mt*16 + g + half*8;
                float v0 = d1[mt][nj][2*half], v1 = d1[mt][nj][2*half + 1];
                float g0 = v0 * 0.5f * (1.0f + erff(v0 * 0.70710678118654752f));
                float g1 = v1 * 0.5f * (1.0f + erff(v1 * 0.70710678118654752f));
                unsigned short h0,l0,h1,l1;
                bfsplit(g0,h0,l0); bfsplit(g1,h1,l1);
                um[t*HW32 + uc]          = (unsigned)h0 | ((unsigned)h1 << 16);
                um[OFF_HL + t*HW32 + uc] = (unsigned)l0 | ((unsigned)l1 << 16);
            }
        }
    __syncthreads();

    // LoRA2: thread = (token, band), full r=8
    {
        int t = tid >> 2, b = tid & 3;
        const float* A = A2 + ((size_t)e*4 + b)*HID*8;
        float acc[8] = {0,0,0,0,0,0,0,0};
        for (int hh = 0; hh < HID; hh++) {
            float hv = bf2f(us[t*424 + hh]) + bf2f(us[2*OFF_HL + t*424 + hh]);
            float4 a0 = *(const float4*)(A + hh*8);
            float4 a1 = *(const float4*)(A + hh*8 + 4);
            acc[0]=fmaf(hv,a0.x,acc[0]); acc[1]=fmaf(hv,a0.y,acc[1]);
            acc[2]=fmaf(hv,a0.z,acc[2]); acc[3]=fmaf(hv,a0.w,acc[3]);
            acc[4]=fmaf(hv,a1.x,acc[4]); acc[5]=fmaf(hv,a1.y,acc[5]);
            acc[6]=fmaf(hv,a1.z,acc[6]); acc[7]=fmaf(hv,a1.w,acc[7]);
        }
        float scl = LSCALE * sBw[t*4 + b];
        int ub = t*HW32 + 192 + b*4;
        #pragma unroll
        for (int j = 0; j < 4; j++) {
            unsigned short ha,la,hb,lb;
            bfsplit(scl*acc[2*j],   ha, la);
            bfsplit(scl*acc[2*j+1], hb, lb);
            um[ub + j]          = (unsigned)ha | ((unsigned)hb << 16);
            um[OFF_HL + ub + j] = (unsigned)la | ((unsigned)lb << 16);
        }
    }

    // ---- layer 2: [64,416]x[416,192]; warp = 4 M-tiles x 24 cols ----
    float d2[4][3][4];
    #pragma unroll
    for (int nj = 0; nj < 3; nj++) {
        int col = warp*24 + nj*8 + 2*kq;
        float b0v = b2[e*OUTD + col], b1v = b2[e*OUTD + col + 1];
        #pragma unroll
        for (int mt = 0; mt < 4; mt++) {
            d2[mt][nj][0] = b0v; d2[mt][nj][1] = b1v;
            d2[mt][nj][2] = b0v; d2[mt][nj][3] = b1v;
        }
    }
    const unsigned* w2h = g_w2h + (size_t)e*W2PE;
    const unsigned* w2l = g_w2l + (size_t)e*W2PE;
    {   // prologue: copy tile 0 (1600 u32/plane = 400 f4)
        const float4* gh = (const float4*)w2h;
        const float4* gl = (const float4*)w2l;
        float4* dh = (float4*)(um + OFF_WB);
        float4* dl = (float4*)(um + OFF_WB + PLO);
        #pragma unroll
        for (int j = 0; j < 2; j++) {
            int idx = tid + j*256;
            if (idx < 400) { dh[idx] = gh[idx]; dl[idx] = gl[idx]; }
        }
    }
    for (int kt = 0; kt < 26; kt++) {
        if (kt < 25) {
            const float4* gh = (const float4*)(w2h + (kt+1)*1600);
            const float4* gl = (const float4*)(w2l + (kt+1)*1600);
            #pragma unroll
            for (int j = 0; j < 2; j++) {
                int idx = tid + j*256;
                if (idx < 400) { ph[j] = gh[idx]; pl[j] = gl[idx]; }
            }
        }
        __syncthreads();
        const unsigned* Wh = um + OFF_WB + (kt&1)*WBUF;
        const unsigned* Wl = Wh + PLO;
        #pragma unroll
        for (int mt = 0; mt < 4; mt++) {
            int base = (mt*16 + g)*HW32 + kt*8 + kq;
            unsigned ah[4], al[4];
            ah[0] = um[base];              al[0] = um[OFF_HL + base];
            ah[1] = um[base + 8*HW32];     al[1] = um[OFF_HL + base + 8*HW32];
            ah[2] = um[base + 4];          al[2] = um[OFF_HL + base + 4];
            ah[3] = um[base + 8*HW32 + 4]; al[3] = um[OFF_HL + base + 8*HW32 + 4];
            #pragma unroll
            for (int nj = 0; nj < 3; nj++) {
                int n = warp*24 + nj*8 + g;
                unsigned bh0 = Wh[kq*200 + n], bh1 = Wh[(kq+4)*200 + n];
                unsigned bl0 = Wl[kq*200 + n], bl1 = Wl[(kq+4)*200 + n];
                mma16(d2[mt][nj], ah, bh0, bh1);
                mma16(d2[mt][nj], ah, bl0, bl1);
                mma16(d2[mt][nj], al, bh0, bh1);
            }
        }
        if (kt < 25) {
            float4* dh = (float4*)(um + OFF_WB + ((kt+1)&1)*WBUF);
            float4* dl = (float4*)(um + OFF_WB + ((kt+1)&1)*WBUF + PLO);
            #pragma unroll
            for (int j = 0; j < 2; j++) {
                int idx = tid + j*256;
                if (idx < 400) { dh[idx] = ph[j]; dl[idx] = pl[j]; }
            }
        }
    }
    // epilogue
    #pragma unroll
    for (int mt = 0; mt < 4; mt++)
        #pragma unroll
        for (int nj = 0; nj < 3; nj++) {
            int col = warp*24 + nj*8 + 2*kq;
            #pragma unroll
            for (int q = 0; q < 4; q++) {
                int t = mt*16 + g + (q >> 1)*8;
                if (t < nt) {
                    int tok = sTok[t];
                    atomicAdd(&out[(size_t)tok*OUTD + col + (q & 1)],
                              sGw[t]*d2[mt][nj][q]);
                }
            }
        }
}

// ---------------- deterministic loss ----------------
__global__ void __launch_bounds__(1024) loss_kernel(float* out, int out_size) {
    __shared__ float sI[8][32], sL[8][32];
    int tid = threadIdx.x, lane = tid & 31, warp = tid >> 5;
    float imp[8] = {0,0,0,0,0,0,0,0}, ld[8] = {0,0,0,0,0,0,0,0};
    for (int n = tid; n < NTOK; n += 1024) {
        unsigned te = g_te[n];
        int e0 = te & 255u, e1 = (te >> 8) & 255u;
        imp[e0] += g_tw0[n]; ld[e0] += 1.f;
        if (e1 != 255) { imp[e1] += g_tw1[n]; ld[e1] += 1.f; }
    }
    #pragma unroll
    for (int e = 0; e < 8; e++) {
        #pragma unroll
        for (int o = 16; o; o >>= 1) {
            imp[e] += __shfl_xor_sync(0xffffffffu, imp[e], o);
            ld[e]  += __shfl_xor_sync(0xffffffffu, ld[e],  o);
        }
        if (lane == 0) { sI[e][warp] = imp[e]; sL[e][warp] = ld[e]; }
    }
    __syncthreads();
    if (tid == 0) {
        float I[8], L[8], mi = 0.f, ml = 0.f;
        for (int e = 0; e < 8; e++) {
            float a = 0.f, b = 0.f;
            for (int w = 0; w < 32; w++) { a += sI[e][w]; b += sL[e][w]; }
            I[e] = a; L[e] = b; mi += a; ml += b;
        }
        mi *= 0.125f; ml *= 0.125f;
        float vi = 0.f, vl = 0.f;
        for (int e = 0; e < 8; e++) {
            float di = I[e] - mi; vi += di*di;
            float dl = L[e] - ml; vl += dl*dl;
        }
        vi *= 0.125f; vl *= 0.125f;
        float loss = (vi / (mi*mi + 1e-10f) + vl / (ml*ml + 1e-10f)) * 0.01f;
        if (out_size > NTOK*OUTD) out[NTOK*OUTD] = loss;
    }
    for (int i = NTOK*OUTD + 1 + tid; i < out_size; i += 1024) out[i] = 0.f;
}

// ---------------- launch ----------------
extern "C" void kernel_launch(void* const* d_in, const int* in_sizes, int n_in,
                              void* d_out, int out_size) {
    const float* x     = (const float*)d_in[0];
    const float* bw    = (const float*)d_in[1];
    const float* xprev = (const float*)d_in[2];
    const float* Wz    = (const float*)d_in[3];
    const float* lng   = (const float*)d_in[4];
    const float* lnb   = (const float*)d_in[5];
    const float* Wg    = (const float*)d_in[6];
    const float* bg    = (const float*)d_in[7];
    const float* W1    = (const float*)d_in[8];
    const float* b1    = (const float*)d_in[9];
    const float* W2    = (const float*)d_in[10];
    const float* b2    = (const float*)d_in[11];
    const float* A1    = (const float*)d_in[12];
    const float* B1    = (const float*)d_in[13];
    const float* A2    = (const float*)d_in[14];
    const float* B2    = (const float*)d_in[15];
    float* out = (float*)d_out;

    const size_t GATE_SMEM = (size_t)(12288 + 2322 + 258 + 258 + 8 + 32*192) * 4;
    const size_t FFN_SMEM  = (size_t)FFN_U32 * 4;
    cudaFuncSetAttribute(gate_kernel, cudaFuncAttributeMaxDynamicSharedMemorySize, (int)GATE_SMEM);
    cudaFuncSetAttribute(ffn_kernel,  cudaFuncAttributeMaxDynamicSharedMemorySize, (int)FFN_SMEM);

    init_kernel<<<1, 32>>>();
    split_kernel<<<336, 1024>>>(W1, B1, W2, B2);
    gate_kernel<<<NTOK/32, 1024, GATE_SMEM>>>(x, xprev, Wz, lng, lnb, Wg, bg);
    select_kernel<<<NE, 1024>>>();
    route_kernel<<<NTOK/256, 256>>>(out);
    ffn_kernel<<<dim3(NTOK/TTILE, NE), 256, FFN_SMEM>>>(x, bw, b1, b2, A1, A2, out);
    loss_kernel<<<1, 1024>>>(out, out_size);
}

// round 13
// speedup vs baseline: 2.3808x; 1.8326x over previous
#include <cuda_runtime.h>
#include <math.h>
#include <stdint.h>

#define NTOK 65536
#define CIN 192
#define HID 384
#define OUTD 192
#define NE 8
#define KCAP 10240
#define TTILE 64
#define LSCALE 2.0f

// FFN smem (u32 units); X and H planes share one union (x dead before h written)
#define XW32   116      /* x plane stride: 232 bf16 */
#define HW32   212      /* h plane stride: 424 bf16 */
#define OFF_XL 7424     /* 64*116 */
#define OFF_HL 13568    /* 64*212 */
#define OFF_WB 27136
#define WBUF   6272
#define PLO    3136
#define OFF_BW 39680
#define OFF_GW 39936
#define OFF_TOK 40000
#define FFN_U32 40064

#define W1PE 43904      /* per-expert u32: 112*392 */
#define W2PE 41600      /* 208*200 */
#define A1PE 3840       /* 96*40 */
#define A2PE 7680       /* 192*40 */

__device__ __forceinline__ unsigned short f2bf(float x) {
    unsigned u = __float_as_uint(x);
    return (unsigned short)((u + 0x7fffu + ((u >> 16) & 1u)) >> 16);
}
__device__ __forceinline__ float bf2f(unsigned short b) {
    return __uint_as_float((unsigned)b << 16);
}
__device__ __forceinline__ void bfsplit(float x, unsigned short& h, unsigned short& l) {
    h = f2bf(x);
    l = f2bf(x - bf2f(h));
}
__device__ __forceinline__ void mma16(float* d, const unsigned* a, unsigned b0, unsigned b1) {
    asm("mma.sync.aligned.m16n8k16.row.col.f32.bf16.bf16.f32 "
        "{%0,%1,%2,%3},{%4,%5,%6,%7},{%8,%9},{%0,%1,%2,%3};"
        : "+f"(d[0]), "+f"(d[1]), "+f"(d[2]), "+f"(d[3])
        : "r"(a[0]), "r"(a[1]), "r"(a[2]), "r"(a[3]), "r"(b0), "r"(b1));
}

// ---------------- device scratch ----------------
__device__ float    g_logits[NE * NTOK];
__device__ unsigned g_mask[NTOK];
__device__ int      g_cnt[NE];
__device__ int      g_list[NE * NTOK];
__device__ float    g_wl[NE * NTOK];
__device__ unsigned g_te[NTOK];
__device__ float    g_tw0[NTOK];
__device__ float    g_tw1[NTOK];
__device__ __align__(16) unsigned g_w1h[NE*W1PE];
__device__ __align__(16) unsigned g_w1l[NE*W1PE];
__device__ __align__(16) unsigned g_w2h[NE*W2PE];
__device__ __align__(16) unsigned g_w2l[NE*W2PE];
__device__ __align__(16) unsigned g_a1h[NE*A1PE];
__device__ __align__(16) unsigned g_a1l[NE*A1PE];
__device__ __align__(16) unsigned g_a2h[NE*A2PE];
__device__ __align__(16) unsigned g_a2l[NE*A2PE];

__global__ void init_kernel() {
    if (threadIdx.x < NE) g_cnt[threadIdx.x] = 0;
}

// ---------------- one-shot weight split: packed k-pair bf16 hi/lo planes ----
__global__ void __launch_bounds__(1024) split_kernel(
    const float* __restrict__ W1, const float* __restrict__ B1,
    const float* __restrict__ W2, const float* __restrict__ B2,
    const float* __restrict__ A1, const float* __restrict__ A2)
{
    int i = blockIdx.x * 1024 + threadIdx.x;
    if (i < NE*112*384) {
        int e = i / 43008, rem = i % 43008;
        int kp = rem / 384, n = rem % 384;
        int k0 = 2*kp, k1 = k0 + 1;
        float v0 = (k0 < 192) ? W1[((size_t)e*192 + k0)*384 + n]
                              : B1[((size_t)e*32 + (k0-192))*384 + n];
        float v1 = (k1 < 192) ? W1[((size_t)e*192 + k1)*384 + n]
                              : B1[((size_t)e*32 + (k1-192))*384 + n];
        unsigned short h0,l0,h1,l1;
        bfsplit(v0,h0,l0); bfsplit(v1,h1,l1);
        g_w1h[(size_t)e*W1PE + kp*392 + n] = (unsigned)h0 | ((unsigned)h1 << 16);
        g_w1l[(size_t)e*W1PE + kp*392 + n] = (unsigned)l0 | ((unsigned)l1 << 16);
    }
    if (i < NE*208*192) {
        int e = i / 39936, rem = i % 39936;
        int kp = rem / 192, n = rem % 192;
        int k0 = 2*kp, k1 = k0 + 1;
        float v0 = (k0 < 384) ? W2[((size_t)e*384 + k0)*192 + n]
                              : B2[((size_t)e*32 + (k0-384))*192 + n];
        float v1 = (k1 < 384) ? W2[((size_t)e*384 + k1)*192 + n]
                              : B2[((size_t)e*32 + (k1-384))*192 + n];
        unsigned short h0,l0,h1,l1;
        bfsplit(v0,h0,l0); bfsplit(v1,h1,l1);
        g_w2h[(size_t)e*W2PE + kp*200 + n] = (unsigned)h0 | ((unsigned)h1 << 16);
        g_w2l[(size_t)e*W2PE + kp*200 + n] = (unsigned)l0 | ((unsigned)l1 << 16);
    }
    if (i < NE*96*32) {   // A1 planes: [96 kp][32 col], col = b*8+r
        int e = i / 3072, rem = i % 3072;
        int kp = rem / 32, col = rem & 31;
        int b = col >> 3, r = col & 7;
        const float* A = A1 + ((size_t)(e*4 + b)*192)*8 + r;
        float v0 = A[(size_t)(2*kp)*8], v1 = A[(size_t)(2*kp+1)*8];
        unsigned short h0,l0,h1,l1;
        bfsplit(v0,h0,l0); bfsplit(v1,h1,l1);
        g_a1h[(size_t)e*A1PE + kp*40 + col] = (unsigned)h0 | ((unsigned)h1 << 16);
        g_a1l[(size_t)e*A1PE + kp*40 + col] = (unsigned)l0 | ((unsigned)l1 << 16);
    }
    if (i < NE*192*32) {  // A2 planes: [192 kp][32 col]
        int e = i / 6144, rem = i % 6144;
        int kp = rem / 32, col = rem & 31;
        int b = col >> 3, r = col & 7;
        const float* A = A2 + ((size_t)(e*4 + b)*384)*8 + r;
        float v0 = A[(size_t)(2*kp)*8], v1 = A[(size_t)(2*kp+1)*8];
        unsigned short h0,l0,h1,l1;
        bfsplit(v0,h0,l0); bfsplit(v1,h1,l1);
        g_a2h[(size_t)e*A2PE + kp*40 + col] = (unsigned)h0 | ((unsigned)h1 << 16);
        g_a2l[(size_t)e*A2PE + kp*40 + col] = (unsigned)l0 | ((unsigned)l1 << 16);
    }
}

// ---------------- gate: features + LN + logits ----------------
__global__ void __launch_bounds__(1024) gate_kernel(
    const float* __restrict__ x, const float* __restrict__ xprev,
    const float* __restrict__ Wz, const float* __restrict__ lng,
    const float* __restrict__ lnb, const float* __restrict__ Wg,
    const float* __restrict__ bg)
{
    extern __shared__ float sm[];
    float* sWz = sm;
    float* sWg = sWz + 12288;
    float* sg  = sWg + 2322;
    float* sb  = sg + 258;
    float* sbg = sb + 258;
    float* sX  = sbg + 8;

    int tid = threadIdx.x, lane = tid & 31, warp = tid >> 5;
    int n = blockIdx.x * 32 + warp;

    for (int i = tid; i < 12288; i += 1024) sWz[i] = Wz[i];
    for (int i = tid; i < 2064;  i += 1024) sWg[(i >> 3)*9 + (i & 7)] = Wg[i];
    for (int i = tid; i < 258;   i += 1024) { sg[i] = lng[i]; sb[i] = lnb[i]; }
    if (tid < 8) sbg[tid] = bg[tid];

    float xr[6];
    #pragma unroll
    for (int i = 0; i < 6; i++) {
        xr[i] = x[(size_t)n*CIN + lane + 32*i];
        sX[warp*CIN + lane + 32*i] = xr[i];
    }
    float s = 0.f, ss = 0.f;
    #pragma unroll
    for (int i = 0; i < 6; i++) {
        float a = fabsf(xr[i] - xprev[(size_t)n*CIN + lane + 32*i]);
        s += a; ss += a*a;
    }
    #pragma unroll
    for (int o = 16; o; o >>= 1) {
        s  += __shfl_xor_sync(0xffffffffu, s, o);
        ss += __shfl_xor_sync(0xffffffffu, ss, o);
    }
    float dmean = s * (1.0f/192.0f);
    float dvar  = fmaxf((ss - s*dmean) * (1.0f/191.0f), 0.f);
    float mu = log1pf(dmean), sd = log1pf(sqrtf(dvar));

    __syncthreads();

    float z0 = 0.f, z1 = 0.f;
    for (int c = 0; c < CIN; c++) {
        float xv = sX[warp*CIN + c];
        z0 = fmaf(xv, sWz[c*64 + lane],      z0);
        z1 = fmaf(xv, sWz[c*64 + lane + 32], z1);
    }
    float sa = z0 + z1, s2 = z0*z0 + z1*z1;
    #pragma unroll
    for (int i = 0; i < 6; i++) { sa += xr[i]; s2 += xr[i]*xr[i]; }
    if (lane == 0) { sa += mu + sd; s2 += mu*mu + sd*sd; }
    #pragma unroll
    for (int o = 16; o; o >>= 1) {
        sa += __shfl_xor_sync(0xffffffffu, sa, o);
        s2 += __shfl_xor_sync(0xffffffffu, s2, o);
    }
    float m_   = sa * (1.0f/258.0f);
    float rstd = rsqrtf(s2 * (1.0f/258.0f) - m_*m_ + 1e-5f);

    float acc[8] = {0,0,0,0,0,0,0,0};
    #pragma unroll
    for (int i = 0; i < 6; i++) {
        int idx = lane + 32*i;
        float nv = (xr[i] - m_)*rstd*sg[idx] + sb[idx];
        #pragma unroll
        for (int e = 0; e < 8; e++) acc[e] = fmaf(nv, sWg[idx*9 + e], acc[e]);
    }
    {
        int idx = 192 + lane;
        float nv = (z0 - m_)*rstd*sg[idx] + sb[idx];
        #pragma unroll
        for (int e = 0; e < 8; e++) acc[e] = fmaf(nv, sWg[idx*9 + e], acc[e]);
        idx = 224 + lane;
        nv = (z1 - m_)*rstd*sg[idx] + sb[idx];
        #pragma unroll
        for (int e = 0; e < 8; e++) acc[e] = fmaf(nv, sWg[idx*9 + e], acc[e]);
    }
    if (lane == 0) {
        float nv = (mu - m_)*rstd*sg[256] + sb[256];
        #pragma unroll
        for (int e = 0; e < 8; e++) acc[e] = fmaf(nv, sWg[256*9 + e], acc[e]);
        nv = (sd - m_)*rstd*sg[257] + sb[257];
        #pragma unroll
        for (int e = 0; e < 8; e++) acc[e] = fmaf(nv, sWg[257*9 + e], acc[e]);
    }
    #pragma unroll
    for (int e = 0; e < 8; e++) {
        #pragma unroll
        for (int o = 16; o; o >>= 1) acc[e] += __shfl_xor_sync(0xffffffffu, acc[e], o);
    }
    if (lane == 0) {
        #pragma unroll
        for (int e = 0; e < 8; e++) g_logits[e*NTOK + n] = acc[e] + sbg[e];
        g_mask[n] = 0u;
    }
}

// ---------------- expert-choice: radix select top-K per expert ----------------
__device__ __forceinline__ unsigned f2key(float f) {
    unsigned u = __float_as_uint(f);
    return (u & 0x80000000u) ? ~u : (u | 0x80000000u);
}

__global__ void __launch_bounds__(1024) select_kernel() {
    __shared__ unsigned hist[256];
    __shared__ unsigned sh_digit, sh_need;
    __shared__ int ccount[64];
    __shared__ int cbase[64];

    int e = blockIdx.x, tid = threadIdx.x;
    int lane = tid & 31, warp = tid >> 5;
    const float* base = g_logits + (size_t)e * NTOK;

    unsigned prefix = 0, pmask = 0, need = KCAP;
    for (int pass = 0; pass < 4; pass++) {
        int shift = 24 - pass*8;
        if (tid < 256) hist[tid] = 0;
        __syncthreads();
        for (int n = tid; n < NTOK; n += 1024) {
            unsigned k = f2key(base[n]);
            bool act = ((k & pmask) == prefix);
            unsigned dg = act ? ((k >> shift) & 255u) : 0xffffffffu;
            unsigned peers = __match_any_sync(0xffffffffu, dg);
            if (act && (__ffs(peers) - 1) == lane)
                atomicAdd(&hist[dg], (unsigned)__popc(peers));
        }
        __syncthreads();
        if (tid == 0) {
            unsigned cum = 0; int d = 255;
            for (; d > 0; d--) {
                unsigned h = hist[d];
                if (cum + h >= need) break;
                cum += h;
            }
            sh_digit = (unsigned)d;
            sh_need  = need - cum;
        }
        __syncthreads();
        prefix |= sh_digit << shift;
        pmask  |= 0xFFu << shift;
        need    = sh_need;
        __syncthreads();
    }
    unsigned thr = prefix;
    int r = (int)need;

    for (int n = tid; n < NTOK; n += 1024)
        if (f2key(base[n]) > thr) atomicOr(&g_mask[n], 1u << e);

    for (int c = warp; c < 64; c += 32) {
        int cnt = 0;
        for (int s = 0; s < 32; s++) {
            int n = c*1024 + s*32 + lane;
            cnt += (f2key(base[n]) == thr);
        }
        #pragma unroll
        for (int o = 16; o; o >>= 1) cnt += __shfl_xor_sync(0xffffffffu, cnt, o);
        if (lane == 0) ccount[c] = cnt;
    }
    __syncthreads();
    if (tid == 0) {
        int run = 0;
        for (int c = 0; c < 64; c++) { cbase[c] = run; run += ccount[c]; }
    }
    __syncthreads();
    for (int c = warp; c < 64; c += 32) {
        int rank = cbase[c];
        if (rank >= r) continue;
        for (int s = 0; s < 32; s++) {
            int n = c*1024 + s*32 + lane;
            bool p = (f2key(base[n]) == thr);
            unsigned bal = __ballot_sync(0xffffffffu, p);
            int myrank = rank + __popc(bal & ((1u << lane) - 1u));
            if (p && myrank < r) atomicOr(&g_mask[n], 1u << e);
            rank += __popc(bal);
        }
    }
}

// ---------------- routing (block-aggregated dispatch) ----------------
__global__ void __launch_bounds__(256) route_kernel(float* __restrict__ out) {
    __shared__ int sCnt[8], sBase[8];
    int tid = threadIdx.x;
    int n = blockIdx.x * 256 + tid;
    if (tid < 8) sCnt[tid] = 0;
    __syncthreads();

    float l[8];
    #pragma unroll
    for (int e = 0; e < 8; e++) l[e] = g_logits[e*NTOK + n];
    unsigned m = g_mask[n];
    if (m == 0u) {
        int best = 0; float bv = l[0];
        #pragma unroll
        for (int e = 1; e < 8; e++) if (l[e] > bv) { bv = l[e]; best = e; }
        m = 1u << best;
    }
    int e0 = -1, e1 = -1; float v0 = -INFINITY, v1 = -INFINITY;
    #pragma unroll
    for (int e = 0; e < 8; e++) {
        if ((m >> e) & 1u) {
            float f = l[e];
            if (f > v0)      { v1 = v0; e1 = e0; v0 = f; e0 = e; }
            else if (f > v1) { v1 = f; e1 = e; }
        }
    }
    float w0 = 1.f, w1 = 0.f;
    if (e1 >= 0) {
        float ex = expf(v1 - v0);
        w0 = 1.0f / (1.0f + ex);
        w1 = ex * w0;
    }
    bool has1 = (e1 >= 0 && w1 > 0.f);
    int p0 = atomicAdd(&sCnt[e0], 1);
    int p1 = has1 ? atomicAdd(&sCnt[e1], 1) : -1;
    __syncthreads();
    if (tid < 8) sBase[tid] = atomicAdd(&g_cnt[tid], sCnt[tid]);
    __syncthreads();
    {
        int pos = sBase[e0] + p0;
        g_list[e0*NTOK + pos] = n;
        g_wl[e0*NTOK + pos]   = w0;
    }
    unsigned te = (unsigned)e0 | (255u << 8);
    float tw1 = 0.f;
    if (has1) {
        int pos = sBase[e1] + p1;
        g_list[e1*NTOK + pos] = n;
        g_wl[e1*NTOK + pos]   = w1;
        te = (unsigned)e0 | ((unsigned)e1 << 8);
        tw1 = w1;
    }
    g_te[n] = te; g_tw0[n] = w0; g_tw1[n] = tw1;

    float4 z4 = make_float4(0.f, 0.f, 0.f, 0.f);
    float4* o4 = (float4*)out;
    for (int i = n; i < NTOK*OUTD/4; i += NTOK) o4[i] = z4;
}

// ---------------- fused expert FFN v13: all-MMA (main + LoRA) ----------------
__global__ void __launch_bounds__(256) ffn_kernel(
    const float* __restrict__ x,  const float* __restrict__ bw,
    const float* __restrict__ b1, const float* __restrict__ b2,
    float* __restrict__ out)
{
    extern __shared__ float sm[];
    unsigned* um = (unsigned*)sm;
    float* sBw = sm + OFF_BW;
    float* sGw = sm + OFF_GW;
    int*   sTok = (int*)(sm + OFF_TOK);

    int e = blockIdx.y;
    int cnt = g_cnt[e];
    int t0 = blockIdx.x * TTILE;
    if (t0 >= cnt) return;
    int nt = min(TTILE, cnt - t0);
    int tid = threadIdx.x;

    if (tid < TTILE) {
        int idx = t0 + min(tid, nt - 1);
        int tok = g_list[e*NTOK + idx];
        sTok[tid] = tok;
        sGw[tid]  = (tid < nt) ? g_wl[e*NTOK + idx] : 0.f;
        *(float4*)(sBw + tid*4) = *(const float4*)(bw + (size_t)tok*4);
    }
    __syncthreads();

    {   // gather x -> packed bf16 hi/lo planes [tok][k]
        int t = tid & 63;
        int tok = sTok[t];
        #pragma unroll
        for (int pp = 0; pp < 2; pp++) {
            int part = (tid >> 6)*2 + pp;
            const float4* src = (const float4*)(x + (size_t)tok*CIN) + part*6;
            unsigned* dh = um + t*XW32 + part*12;
            unsigned* dl = um + OFF_XL + t*XW32 + part*12;
            #pragma unroll
            for (int i = 0; i < 6; i++) {
                float4 v = src[i];
                unsigned short h0,l0,h1,l1,h2,l2,h3,l3;
                bfsplit(v.x,h0,l0); bfsplit(v.y,h1,l1);
                bfsplit(v.z,h2,l2); bfsplit(v.w,h3,l3);
                dh[2*i]   = (unsigned)h0 | ((unsigned)h1 << 16);
                dh[2*i+1] = (unsigned)h2 | ((unsigned)h3 << 16);
                dl[2*i]   = (unsigned)l0 | ((unsigned)l1 << 16);
                dl[2*i+1] = (unsigned)l2 | ((unsigned)l3 << 16);
            }
        }
    }
    __syncthreads();

    int warp = tid >> 5, lane = tid & 31;
    int g = lane >> 2, kq = lane & 3;

    // LoRA1 as MMA: t1 = x @ A1  [64,192]x[192,32]; warp = (mt, nh)
    {
        int mt = warp >> 1, nh = warp & 1;
        float d[2][4] = {{0,0,0,0},{0,0,0,0}};
        const unsigned* a1h = g_a1h + (size_t)e*A1PE;
        const unsigned* a1l = g_a1l + (size_t)e*A1PE;
        #pragma unroll
        for (int kt = 0; kt < 12; kt++) {
            int base = (mt*16 + g)*XW32 + kt*8 + kq;
            unsigned ah[4], al[4];
            ah[0]=um[base];              al[0]=um[OFF_XL+base];
            ah[1]=um[base+8*XW32];       al[1]=um[OFF_XL+base+8*XW32];
            ah[2]=um[base+4];            al[2]=um[OFF_XL+base+4];
            ah[3]=um[base+8*XW32+4];     al[3]=um[OFF_XL+base+8*XW32+4];
            #pragma unroll
            for (int nj = 0; nj < 2; nj++) {
                int col = nh*16 + nj*8 + g;
                unsigned bh0 = a1h[(kt*8+kq)*40 + col], bh1 = a1h[(kt*8+kq+4)*40 + col];
                unsigned bl0 = a1l[(kt*8+kq)*40 + col], bl1 = a1l[(kt*8+kq+4)*40 + col];
                mma16(d[nj], ah, bh0, bh1);
                mma16(d[nj], ah, bl0, bl1);
                mma16(d[nj], al, bh0, bh1);
            }
        }
        #pragma unroll
        for (int nj = 0; nj < 2; nj++) {
            int b = nh*2 + nj;
            int kp = 96 + nh*8 + nj*4 + kq;
            #pragma unroll
            for (int half = 0; half < 2; half++) {
                int t = mt*16 + g + half*8;
                float scl = LSCALE * sBw[t*4 + b];
                unsigned short h0,l0,h1,l1;
                bfsplit(scl*d[nj][2*half],   h0, l0);
                bfsplit(scl*d[nj][2*half+1], h1, l1);
                um[t*XW32 + kp]          = (unsigned)h0 | ((unsigned)h1 << 16);
                um[OFF_XL + t*XW32 + kp] = (unsigned)l0 | ((unsigned)l1 << 16);
            }
        }
    }

    // ---- layer 1: [64,224]x[224,384]; warp = 4 M-tiles x 48 cols ----
    float d1[4][6][4];
    #pragma unroll
    for (int nj = 0; nj < 6; nj++) {
        int col = warp*48 + nj*8 + 2*kq;
        float b0v = b1[e*HID + col], b1v = b1[e*HID + col + 1];
        #pragma unroll
        for (int mt = 0; mt < 4; mt++) {
            d1[mt][nj][0] = b0v; d1[mt][nj][1] = b1v;
            d1[mt][nj][2] = b0v; d1[mt][nj][3] = b1v;
        }
    }
    const unsigned* w1h = g_w1h + (size_t)e*W1PE;
    const unsigned* w1l = g_w1l + (size_t)e*W1PE;
    {   // prologue: copy tile 0 (784 f4/plane)
        const float4* gh = (const float4*)w1h;
        const float4* gl = (const float4*)w1l;
        float4* dh = (float4*)(um + OFF_WB);
        float4* dl = (float4*)(um + OFF_WB + PLO);
        #pragma unroll
        for (int j = 0; j < 4; j++) {
            int idx = tid + j*256;
            if (idx < 784) { dh[idx] = gh[idx]; dl[idx] = gl[idx]; }
        }
    }
    float4 ph[4], pl[4];
    for (int kt = 0; kt < 14; kt++) {
        if (kt < 13) {
            const float4* gh = (const float4*)(w1h + (kt+1)*3136);
            const float4* gl = (const float4*)(w1l + (kt+1)*3136);
            #pragma unroll
            for (int j = 0; j < 4; j++) {
                int idx = tid + j*256;
                if (idx < 784) { ph[j] = gh[idx]; pl[j] = gl[idx]; }
            }
        }
        __syncthreads();
        const unsigned* Wh = um + OFF_WB + (kt&1)*WBUF;
        const unsigned* Wl = Wh + PLO;
        #pragma unroll
        for (int mt = 0; mt < 4; mt++) {
            int base = (mt*16 + g)*XW32 + kt*8 + kq;
            unsigned ah[4], al[4];
            ah[0] = um[base];              al[0] = um[OFF_XL + base];
            ah[1] = um[base + 8*XW32];     al[1] = um[OFF_XL + base + 8*XW32];
            ah[2] = um[base + 4];          al[2] = um[OFF_XL + base + 4];
            ah[3] = um[base + 8*XW32 + 4]; al[3] = um[OFF_XL + base + 8*XW32 + 4];
            #pragma unroll
            for (int nj = 0; nj < 6; nj++) {
                int n = warp*48 + nj*8 + g;
                unsigned bh0 = Wh[kq*392 + n], bh1 = Wh[(kq+4)*392 + n];
                unsigned bl0 = Wl[kq*392 + n], bl1 = Wl[(kq+4)*392 + n];
                mma16(d1[mt][nj], ah, bh0, bh1);
                mma16(d1[mt][nj], ah, bl0, bl1);
                mma16(d1[mt][nj], al, bh0, bh1);
            }
        }
        if (kt < 13) {
            float4* dh = (float4*)(um + OFF_WB + ((kt+1)&1)*WBUF);
            float4* dl = (float4*)(um + OFF_WB + ((kt+1)&1)*WBUF + PLO);
            #pragma unroll
            for (int j = 0; j < 4; j++) {
                int idx = tid + j*256;
                if (idx < 784) { dh[idx] = ph[j]; dl[idx] = pl[j]; }
            }
        }
    }
    __syncthreads();   // X reads done; H overwrites the union region

    // exact GELU -> packed bf16 split H [tok][h]
    #pragma unroll
    for (int mt = 0; mt < 4; mt++)
        #pragma unroll
        for (int nj = 0; nj < 6; nj++) {
            int uc = warp*24 + nj*4 + kq;
            #pragma unroll
            for (int half = 0; half < 2; half++) {
                int t = mt*16 + g + half*8;
                float v0 = d1[mt][nj][2*half], v1 = d1[mt][nj][2*half + 1];
                float g0 = v0 * 0.5f * (1.0f + erff(v0 * 0.70710678118654752f));
                float g1 = v1 * 0.5f * (1.0f + erff(v1 * 0.70710678118654752f));
                unsigned short h0,l0,h1,l1;
                bfsplit(g0,h0,l0); bfsplit(g1,h1,l1);
                um[t*HW32 + uc]          = (unsigned)h0 | ((unsigned)h1 << 16);
                um[OFF_HL + t*HW32 + uc] = (unsigned)l0 | ((unsigned)l1 << 16);
            }
        }
    __syncthreads();

    // LoRA2 as MMA: t2 = h @ A2  [64,384]x[384,32]
    {
        int mt = warp >> 1, nh = warp & 1;
        float d[2][4] = {{0,0,0,0},{0,0,0,0}};
        const unsigned* a2h = g_a2h + (size_t)e*A2PE;
        const unsigned* a2l = g_a2l + (size_t)e*A2PE;
        #pragma unroll 4
        for (int kt = 0; kt < 24; kt++) {
            int base = (mt*16 + g)*HW32 + kt*8 + kq;
            unsigned ah[4], al[4];
            ah[0]=um[base];              al[0]=um[OFF_HL+base];
            ah[1]=um[base+8*HW32];       al[1]=um[OFF_HL+base+8*HW32];
            ah[2]=um[base+4];            al[2]=um[OFF_HL+base+4];
            ah[3]=um[base+8*HW32+4];     al[3]=um[OFF_HL+base+8*HW32+4];
            #pragma unroll
            for (int nj = 0; nj < 2; nj++) {
                int col = nh*16 + nj*8 + g;
                unsigned bh0 = a2h[(kt*8+kq)*40 + col], bh1 = a2h[(kt*8+kq+4)*40 + col];
                unsigned bl0 = a2l[(kt*8+kq)*40 + col], bl1 = a2l[(kt*8+kq+4)*40 + col];
                mma16(d[nj], ah, bh0, bh1);
                mma16(d[nj], ah, bl0, bl1);
                mma16(d[nj], al, bh0, bh1);
            }
        }
        #pragma unroll
        for (int nj = 0; nj < 2; nj++) {
            int b = nh*2 + nj;
            int kp = 192 + nh*8 + nj*4 + kq;
            #pragma unroll
            for (int half = 0; half < 2; half++) {
                int t = mt*16 + g + half*8;
                float scl = LSCALE * sBw[t*4 + b];
                unsigned short h0,l0,h1,l1;
                bfsplit(scl*d[nj][2*half],   h0, l0);
                bfsplit(scl*d[nj][2*half+1], h1, l1);
                um[t*HW32 + kp]          = (unsigned)h0 | ((unsigned)h1 << 16);
                um[OFF_HL + t*HW32 + kp] = (unsigned)l0 | ((unsigned)l1 << 16);
            }
        }
    }

    // ---- layer 2: [64,416]x[416,192]; warp = 4 M-tiles x 24 cols ----
    float d2[4][3][4];
    #pragma unroll
    for (int nj = 0; nj < 3; nj++) {
        int col = warp*24 + nj*8 + 2*kq;
        float b0v = b2[e*OUTD + col], b1v = b2[e*OUTD + col + 1];
        #pragma unroll
        for (int mt = 0; mt < 4; mt++) {
            d2[mt][nj][0] = b0v; d2[mt][nj][1] = b1v;
            d2[mt][nj][2] = b0v; d2[mt][nj][3] = b1v;
        }
    }
    const unsigned* w2h = g_w2h + (size_t)e*W2PE;
    const unsigned* w2l = g_w2l + (size_t)e*W2PE;
    {   // prologue: copy tile 0 (400 f4/plane)
        const float4* gh = (const float4*)w2h;
        const float4* gl = (const float4*)w2l;
        float4* dh = (float4*)(um + OFF_WB);
        float4* dl = (float4*)(um + OFF_WB + PLO);
        #pragma unroll
        for (int j = 0; j < 2; j++) {
            int idx = tid + j*256;
            if (idx < 400) { dh[idx] = gh[idx]; dl[idx] = gl[idx]; }
        }
    }
    for (int kt = 0; kt < 26; kt++) {
        if (kt < 25) {
            const float4* gh = (const float4*)(w2h + (kt+1)*1600);
            const float4* gl = (const float4*)(w2l + (kt+1)*1600);
            #pragma unroll
            for (int j = 0; j < 2; j++) {
                int idx = tid + j*256;
                if (idx < 400) { ph[j] = gh[idx]; pl[j] = gl[idx]; }
            }
        }
        __syncthreads();
        const unsigned* Wh = um + OFF_WB + (kt&1)*WBUF;
        const unsigned* Wl = Wh + PLO;
        #pragma unroll
        for (int mt = 0; mt < 4; mt++) {
            int base = (mt*16 + g)*HW32 + kt*8 + kq;
            unsigned ah[4], al[4];
            ah[0] = um[base];              al[0] = um[OFF_HL + base];
            ah[1] = um[base + 8*HW32];     al[1] = um[OFF_HL + base + 8*HW32];
            ah[2] = um[base + 4];          al[2] = um[OFF_HL + base + 4];
            ah[3] = um[base + 8*HW32 + 4]; al[3] = um[OFF_HL + base + 8*HW32 + 4];
            #pragma unroll
            for (int nj = 0; nj < 3; nj++) {
                int n = warp*24 + nj*8 + g;
                unsigned bh0 = Wh[kq*200 + n], bh1 = Wh[(kq+4)*200 + n];
                unsigned bl0 = Wl[kq*200 + n], bl1 = Wl[(kq+4)*200 + n];
                mma16(d2[mt][nj], ah, bh0, bh1);
                mma16(d2[mt][nj], ah, bl0, bl1);
                mma16(d2[mt][nj], al, bh0, bh1);
            }
        }
        if (kt < 25) {
            float4* dh = (float4*)(um + OFF_WB + ((kt+1)&1)*WBUF);
            float4* dl = (float4*)(um + OFF_WB + ((kt+1)&1)*WBUF + PLO);
            #pragma unroll
            for (int j = 0; j < 2; j++) {
                int idx = tid + j*256;
                if (idx < 400) { dh[idx] = ph[j]; dl[idx] = pl[j]; }
            }
        }
    }
    // epilogue
    #pragma unroll
    for (int mt = 0; mt < 4; mt++)
        #pragma unroll
        for (int nj = 0; nj < 3; nj++) {
            int col = warp*24 + nj*8 + 2*kq;
            #pragma unroll
            for (int q = 0; q < 4; q++) {
                int t = mt*16 + g + (q >> 1)*8;
                if (t < nt) {
                    int tok = sTok[t];
                    atomicAdd(&out[(size_t)tok*OUTD + col + (q & 1)],
                              sGw[t]*d2[mt][nj][q]);
                }
            }
        }
}

// ---------------- deterministic loss ----------------
__global__ void __launch_bounds__(1024) loss_kernel(float* out, int out_size) {
    __shared__ float sI[8][32], sL[8][32];
    int tid = threadIdx.x, lane = tid & 31, warp = tid >> 5;
    float imp[8] = {0,0,0,0,0,0,0,0}, ld[8] = {0,0,0,0,0,0,0,0};
    for (int n = tid; n < NTOK; n += 1024) {
        unsigned te = g_te[n];
        int e0 = te & 255u, e1 = (te >> 8) & 255u;
        imp[e0] += g_tw0[n]; ld[e0] += 1.f;
        if (e1 != 255) { imp[e1] += g_tw1[n]; ld[e1] += 1.f; }
    }
    #pragma unroll
    for (int e = 0; e < 8; e++) {
        #pragma unroll
        for (int o = 16; o; o >>= 1) {
            imp[e] += __shfl_xor_sync(0xffffffffu, imp[e], o);
            ld[e]  += __shfl_xor_sync(0xffffffffu, ld[e],  o);
        }
        if (lane == 0) { sI[e][warp] = imp[e]; sL[e][warp] = ld[e]; }
    }
    __syncthreads();
    if (tid == 0) {
        float I[8], L[8], mi = 0.f, ml = 0.f;
        for (int e = 0; e < 8; e++) {
            float a = 0.f, b = 0.f;
            for (int w = 0; w < 32; w++) { a += sI[e][w]; b += sL[e][w]; }
            I[e] = a; L[e] = b; mi += a; ml += b;
        }
        mi *= 0.125f; ml *= 0.125f;
        float vi = 0.f, vl = 0.f;
        for (int e = 0; e < 8; e++) {
            float di = I[e] - mi; vi += di*di;
            float dl = L[e] - ml; vl += dl*dl;
        }
        vi *= 0.125f; vl *= 0.125f;
        float loss = (vi / (mi*mi + 1e-10f) + vl / (ml*ml + 1e-10f)) * 0.01f;
        if (out_size > NTOK*OUTD) out[NTOK*OUTD] = loss;
    }
    for (int i = NTOK*OUTD + 1 + tid; i < out_size; i += 1024) out[i] = 0.f;
}

// ---------------- launch ----------------
extern "C" void kernel_launch(void* const* d_in, const int* in_sizes, int n_in,
                              void* d_out, int out_size) {
    const float* x     = (const float*)d_in[0];
    const float* bw    = (const float*)d_in[1];
    const float* xprev = (const float*)d_in[2];
    const float* Wz    = (const float*)d_in[3];
    const float* lng   = (const float*)d_in[4];
    const float* lnb   = (const float*)d_in[5];
    const float* Wg    = (const float*)d_in[6];
    const float* bg    = (const float*)d_in[7];
    const float* W1    = (const float*)d_in[8];
    const float* b1    = (const float*)d_in[9];
    const float* W2    = (const float*)d_in[10];
    const float* b2    = (const float*)d_in[11];
    const float* A1    = (const float*)d_in[12];
    const float* B1    = (const float*)d_in[13];
    const float* A2    = (const float*)d_in[14];
    const float* B2    = (const float*)d_in[15];
    float* out = (float*)d_out;

    const size_t GATE_SMEM = (size_t)(12288 + 2322 + 258 + 258 + 8 + 32*192) * 4;
    const size_t FFN_SMEM  = (size_t)FFN_U32 * 4;
    cudaFuncSetAttribute(gate_kernel, cudaFuncAttributeMaxDynamicSharedMemorySize, (int)GATE_SMEM);
    cudaFuncSetAttribute(ffn_kernel,  cudaFuncAttributeMaxDynamicSharedMemorySize, (int)FFN_SMEM);

    init_kernel<<<1, 32>>>();
    split_kernel<<<336, 1024>>>(W1, B1, W2, B2, A1, A2);
    gate_kernel<<<NTOK/32, 1024, GATE_SMEM>>>(x, xprev, Wz, lng, lnb, Wg, bg);
    select_kernel<<<NE, 1024>>>();
    route_kernel<<<NTOK/256, 256>>>(out);
    ffn_kernel<<<dim3(NTOK/TTILE, NE), 256, FFN_SMEM>>>(x, bw, b1, b2, out);
    loss_kernel<<<1, 1024>>>(out, out_size);
}

// round 14
// speedup vs baseline: 2.4575x; 1.0322x over previous
#include <cuda_runtime.h>
#include <math.h>
#include <stdint.h>

#define NTOK 65536
#define CIN 192
#define HID 384
#define OUTD 192
#define NE 8
#define KCAP 10240
#define TTILE 64
#define LSCALE 2.0f

// FFN smem (u32 units); X and H planes share one union (x dead before h written)
#define XW32   116
#define HW32   212
#define OFF_XL 7424
#define OFF_HL 13568
#define OFF_WB 27136
#define WBUF   6272
#define PLO    3136
#define OFF_BW 39680
#define OFF_GW 39936
#define OFF_TOK 40000
#define FFN_U32 40064

#define W1PE 43904
#define W2PE 41600
#define A1PE 3840
#define A2PE 7680

__device__ __forceinline__ unsigned short f2bf(float x) {
    unsigned u = __float_as_uint(x);
    return (unsigned short)((u + 0x7fffu + ((u >> 16) & 1u)) >> 16);
}
__device__ __forceinline__ float bf2f(unsigned short b) {
    return __uint_as_float((unsigned)b << 16);
}
__device__ __forceinline__ void bfsplit(float x, unsigned short& h, unsigned short& l) {
    h = f2bf(x);
    l = f2bf(x - bf2f(h));
}
__device__ __forceinline__ void mma16(float* d, const unsigned* a, unsigned b0, unsigned b1) {
    asm("mma.sync.aligned.m16n8k16.row.col.f32.bf16.bf16.f32 "
        "{%0,%1,%2,%3},{%4,%5,%6,%7},{%8,%9},{%0,%1,%2,%3};"
        : "+f"(d[0]), "+f"(d[1]), "+f"(d[2]), "+f"(d[3])
        : "r"(a[0]), "r"(a[1]), "r"(a[2]), "r"(a[3]), "r"(b0), "r"(b1));
}

// ---------------- device scratch ----------------
__device__ float    g_logits[NE * NTOK];
__device__ unsigned g_mask[NTOK];
__device__ int      g_cnt[NE];
__device__ int      g_list[NE * NTOK];
__device__ float    g_wl[NE * NTOK];
__device__ unsigned g_te[NTOK];
__device__ float    g_tw0[NTOK];
__device__ float    g_tw1[NTOK];
__device__ __align__(16) unsigned g_w1h[NE*W1PE];
__device__ __align__(16) unsigned g_w1l[NE*W1PE];
__device__ __align__(16) unsigned g_w2h[NE*W2PE];
__device__ __align__(16) unsigned g_w2l[NE*W2PE];
__device__ __align__(16) unsigned g_a1h[NE*A1PE];
__device__ __align__(16) unsigned g_a1l[NE*A1PE];
__device__ __align__(16) unsigned g_a2h[NE*A2PE];
__device__ __align__(16) unsigned g_a2l[NE*A2PE];
// parallel radix select state
__device__ unsigned g_hist[NE][256];
__device__ unsigned g_thr[NE];
__device__ unsigned g_need[NE];
__device__ int      g_ccount[NE][64];
__device__ int      g_cbase[NE][64];

__global__ void init_kernel() {
    int t = blockIdx.x * 1024 + threadIdx.x;
    if (t < NE) { g_cnt[t] = 0; g_thr[t] = 0u; g_need[t] = KCAP; }
    if (t < NE*256) ((unsigned*)g_hist)[t] = 0u;
}

// ---------------- one-shot weight split ----------------
__global__ void __launch_bounds__(1024) split_kernel(
    const float* __restrict__ W1, const float* __restrict__ B1,
    const float* __restrict__ W2, const float* __restrict__ B2,
    const float* __restrict__ A1, const float* __restrict__ A2)
{
    int i = blockIdx.x * 1024 + threadIdx.x;
    if (i < NE*112*384) {
        int e = i / 43008, rem = i % 43008;
        int kp = rem / 384, n = rem % 384;
        int k0 = 2*kp, k1 = k0 + 1;
        float v0 = (k0 < 192) ? W1[((size_t)e*192 + k0)*384 + n]
                              : B1[((size_t)e*32 + (k0-192))*384 + n];
        float v1 = (k1 < 192) ? W1[((size_t)e*192 + k1)*384 + n]
                              : B1[((size_t)e*32 + (k1-192))*384 + n];
        unsigned short h0,l0,h1,l1;
        bfsplit(v0,h0,l0); bfsplit(v1,h1,l1);
        g_w1h[(size_t)e*W1PE + kp*392 + n] = (unsigned)h0 | ((unsigned)h1 << 16);
        g_w1l[(size_t)e*W1PE + kp*392 + n] = (unsigned)l0 | ((unsigned)l1 << 16);
    }
    if (i < NE*208*192) {
        int e = i / 39936, rem = i % 39936;
        int kp = rem / 192, n = rem % 192;
        int k0 = 2*kp, k1 = k0 + 1;
        float v0 = (k0 < 384) ? W2[((size_t)e*384 + k0)*192 + n]
                              : B2[((size_t)e*32 + (k0-384))*192 + n];
        float v1 = (k1 < 384) ? W2[((size_t)e*384 + k1)*192 + n]
                              : B2[((size_t)e*32 + (k1-384))*192 + n];
        unsigned short h0,l0,h1,l1;
        bfsplit(v0,h0,l0); bfsplit(v1,h1,l1);
        g_w2h[(size_t)e*W2PE + kp*200 + n] = (unsigned)h0 | ((unsigned)h1 << 16);
        g_w2l[(size_t)e*W2PE + kp*200 + n] = (unsigned)l0 | ((unsigned)l1 << 16);
    }
    if (i < NE*96*32) {
        int e = i / 3072, rem = i % 3072;
        int kp = rem / 32, col = rem & 31;
        int b = col >> 3, r = col & 7;
        const float* A = A1 + ((size_t)(e*4 + b)*192)*8 + r;
        float v0 = A[(size_t)(2*kp)*8], v1 = A[(size_t)(2*kp+1)*8];
        unsigned short h0,l0,h1,l1;
        bfsplit(v0,h0,l0); bfsplit(v1,h1,l1);
        g_a1h[(size_t)e*A1PE + kp*40 + col] = (unsigned)h0 | ((unsigned)h1 << 16);
        g_a1l[(size_t)e*A1PE + kp*40 + col] = (unsigned)l0 | ((unsigned)l1 << 16);
    }
    if (i < NE*192*32) {
        int e = i / 6144, rem = i % 6144;
        int kp = rem / 32, col = rem & 31;
        int b = col >> 3, r = col & 7;
        const float* A = A2 + ((size_t)(e*4 + b)*384)*8 + r;
        float v0 = A[(size_t)(2*kp)*8], v1 = A[(size_t)(2*kp+1)*8];
        unsigned short h0,l0,h1,l1;
        bfsplit(v0,h0,l0); bfsplit(v1,h1,l1);
        g_a2h[(size_t)e*A2PE + kp*40 + col] = (unsigned)h0 | ((unsigned)h1 << 16);
        g_a2l[(size_t)e*A2PE + kp*40 + col] = (unsigned)l0 | ((unsigned)l1 << 16);
    }
}

// ---------------- gate: features + LN + logits ----------------
__global__ void __launch_bounds__(1024) gate_kernel(
    const float* __restrict__ x, const float* __restrict__ xprev,
    const float* __restrict__ Wz, const float* __restrict__ lng,
    const float* __restrict__ lnb, const float* __restrict__ Wg,
    const float* __restrict__ bg)
{
    extern __shared__ float sm[];
    float* sWz = sm;
    float* sWg = sWz + 12288;
    float* sg  = sWg + 2322;
    float* sb  = sg + 258;
    float* sbg = sb + 258;
    float* sX  = sbg + 8;

    int tid = threadIdx.x, lane = tid & 31, warp = tid >> 5;
    int n = blockIdx.x * 32 + warp;

    for (int i = tid; i < 12288; i += 1024) sWz[i] = Wz[i];
    for (int i = tid; i < 2064;  i += 1024) sWg[(i >> 3)*9 + (i & 7)] = Wg[i];
    for (int i = tid; i < 258;   i += 1024) { sg[i] = lng[i]; sb[i] = lnb[i]; }
    if (tid < 8) sbg[tid] = bg[tid];

    float xr[6];
    #pragma unroll
    for (int i = 0; i < 6; i++) {
        xr[i] = x[(size_t)n*CIN + lane + 32*i];
        sX[warp*CIN + lane + 32*i] = xr[i];
    }
    float s = 0.f, ss = 0.f;
    #pragma unroll
    for (int i = 0; i < 6; i++) {
        float a = fabsf(xr[i] - xprev[(size_t)n*CIN + lane + 32*i]);
        s += a; ss += a*a;
    }
    #pragma unroll
    for (int o = 16; o; o >>= 1) {
        s  += __shfl_xor_sync(0xffffffffu, s, o);
        ss += __shfl_xor_sync(0xffffffffu, ss, o);
    }
    float dmean = s * (1.0f/192.0f);
    float dvar  = fmaxf((ss - s*dmean) * (1.0f/191.0f), 0.f);
    float mu = log1pf(dmean), sd = log1pf(sqrtf(dvar));

    __syncthreads();

    float z0 = 0.f, z1 = 0.f;
    for (int c = 0; c < CIN; c++) {
        float xv = sX[warp*CIN + c];
        z0 = fmaf(xv, sWz[c*64 + lane],      z0);
        z1 = fmaf(xv, sWz[c*64 + lane + 32], z1);
    }
    float sa = z0 + z1, s2 = z0*z0 + z1*z1;
    #pragma unroll
    for (int i = 0; i < 6; i++) { sa += xr[i]; s2 += xr[i]*xr[i]; }
    if (lane == 0) { sa += mu + sd; s2 += mu*mu + sd*sd; }
    #pragma unroll
    for (int o = 16; o; o >>= 1) {
        sa += __shfl_xor_sync(0xffffffffu, sa, o);
        s2 += __shfl_xor_sync(0xffffffffu, s2, o);
    }
    float m_   = sa * (1.0f/258.0f);
    float rstd = rsqrtf(s2 * (1.0f/258.0f) - m_*m_ + 1e-5f);

    float acc[8] = {0,0,0,0,0,0,0,0};
    #pragma unroll
    for (int i = 0; i < 6; i++) {
        int idx = lane + 32*i;
        float nv = (xr[i] - m_)*rstd*sg[idx] + sb[idx];
        #pragma unroll
        for (int e = 0; e < 8; e++) acc[e] = fmaf(nv, sWg[idx*9 + e], acc[e]);
    }
    {
        int idx = 192 + lane;
        float nv = (z0 - m_)*rstd*sg[idx] + sb[idx];
        #pragma unroll
        for (int e = 0; e < 8; e++) acc[e] = fmaf(nv, sWg[idx*9 + e], acc[e]);
        idx = 224 + lane;
        nv = (z1 - m_)*rstd*sg[idx] + sb[idx];
        #pragma unroll
        for (int e = 0; e < 8; e++) acc[e] = fmaf(nv, sWg[idx*9 + e], acc[e]);
    }
    if (lane == 0) {
        float nv = (mu - m_)*rstd*sg[256] + sb[256];
        #pragma unroll
        for (int e = 0; e < 8; e++) acc[e] = fmaf(nv, sWg[256*9 + e], acc[e]);
        nv = (sd - m_)*rstd*sg[257] + sb[257];
        #pragma unroll
        for (int e = 0; e < 8; e++) acc[e] = fmaf(nv, sWg[257*9 + e], acc[e]);
    }
    #pragma unroll
    for (int e = 0; e < 8; e++) {
        #pragma unroll
        for (int o = 16; o; o >>= 1) acc[e] += __shfl_xor_sync(0xffffffffu, acc[e], o);
    }
    if (lane == 0) {
        #pragma unroll
        for (int e = 0; e < 8; e++) g_logits[e*NTOK + n] = acc[e] + sbg[e];
        g_mask[n] = 0u;
    }
}

// ---------------- parallel radix select ----------------
__device__ __forceinline__ unsigned f2key(float f) {
    unsigned u = __float_as_uint(f);
    return (u & 0x80000000u) ? ~u : (u | 0x80000000u);
}

// grid (32, NE) x 256: histogram one pass into g_hist[e]
__global__ void __launch_bounds__(256) hist_kernel(int shift) {
    __shared__ unsigned hist[256];
    int e = blockIdx.y, tid = threadIdx.x, lane = tid & 31;
    hist[tid] = 0;
    __syncthreads();
    unsigned pmask = (shift == 24) ? 0u : (0xFFFFFFFFu << (shift + 8));
    unsigned prefix = g_thr[e] & pmask;
    const float* base = g_logits + (size_t)e * NTOK;
    int n0 = blockIdx.x * 2048;
    for (int i = tid; i < 2048; i += 256) {
        unsigned k = f2key(base[n0 + i]);
        bool act = ((k & pmask) == prefix);
        unsigned dg = act ? ((k >> shift) & 255u) : 0xffffffffu;
        unsigned peers = __match_any_sync(0xffffffffu, dg);
        if (act && (__ffs(peers) - 1) == lane)
            atomicAdd(&hist[dg], (unsigned)__popc(peers));
    }
    __syncthreads();
    if (hist[tid]) atomicAdd(&g_hist[e][tid], hist[tid]);
}

// grid NE x 32: pick digit, update thr/need, zero hist
__global__ void __launch_bounds__(32) digit_kernel(int shift) {
    int e = blockIdx.x, tid = threadIdx.x;
    if (tid == 0) {
        unsigned need = g_need[e];
        unsigned cum = 0; int d = 255;
        for (; d > 0; d--) {
            unsigned h = g_hist[e][d];
            if (cum + h >= need) break;
            cum += h;
        }
        g_thr[e] |= ((unsigned)d) << shift;
        g_need[e] = need - cum;
    }
    __syncthreads();
    for (int i = tid; i < 256; i += 32) g_hist[e][i] = 0u;
}

// grid (64, NE) x 256: mark > thr; count ==thr per chunk
__global__ void __launch_bounds__(256) mark_kernel() {
    int e = blockIdx.y, c = blockIdx.x, tid = threadIdx.x, lane = tid & 31;
    unsigned thr = g_thr[e];
    const float* base = g_logits + (size_t)e * NTOK;
    int cnt = 0;
    for (int i = tid; i < 1024; i += 256) {
        unsigned k = f2key(base[c*1024 + i]);
        if (k > thr) atomicOr(&g_mask[c*1024 + i], 1u << e);
        cnt += (k == thr);
    }
    #pragma unroll
    for (int o = 16; o; o >>= 1) cnt += __shfl_xor_sync(0xffffffffu, cnt, o);
    __shared__ int ws[8];
    if (lane == 0) ws[tid >> 5] = cnt;
    __syncthreads();
    if (tid == 0) {
        int t = 0;
        for (int w = 0; w < 8; w++) t += ws[w];
        g_ccount[e][c] = t;
    }
}

// grid NE x 32: exclusive scan of chunk counts
__global__ void __launch_bounds__(32) scan_kernel() {
    int e = blockIdx.x;
    if (threadIdx.x == 0) {
        int run = 0;
        for (int c = 0; c < 64; c++) { g_cbase[e][c] = run; run += g_ccount[e][c]; }
    }
}

// grid (64, NE) x 32: index-ordered ranked marking of ==thr keys
__global__ void __launch_bounds__(32) tie_kernel() {
    int e = blockIdx.y, c = blockIdx.x, lane = threadIdx.x;
    int r = (int)g_need[e];
    int rank = g_cbase[e][c];
    if (rank >= r) return;
    unsigned thr = g_thr[e];
    const float* base = g_logits + (size_t)e * NTOK;
    for (int s = 0; s < 32; s++) {
        int n = c*1024 + s*32 + lane;
        bool p = (f2key(base[n]) == thr);
        unsigned bal = __ballot_sync(0xffffffffu, p);
        int myrank = rank + __popc(bal & ((1u << lane) - 1u));
        if (p && myrank < r) atomicOr(&g_mask[n], 1u << e);
        rank += __popc(bal);
        if (rank >= r) break;
    }
}

// ---------------- routing (block-aggregated dispatch) ----------------
__global__ void __launch_bounds__(256) route_kernel(float* __restrict__ out) {
    __shared__ int sCnt[8], sBase[8];
    int tid = threadIdx.x;
    int n = blockIdx.x * 256 + tid;
    if (tid < 8) sCnt[tid] = 0;
    __syncthreads();

    float l[8];
    #pragma unroll
    for (int e = 0; e < 8; e++) l[e] = g_logits[e*NTOK + n];
    unsigned m = g_mask[n];
    if (m == 0u) {
        int best = 0; float bv = l[0];
        #pragma unroll
        for (int e = 1; e < 8; e++) if (l[e] > bv) { bv = l[e]; best = e; }
        m = 1u << best;
    }
    int e0 = -1, e1 = -1; float v0 = -INFINITY, v1 = -INFINITY;
    #pragma unroll
    for (int e = 0; e < 8; e++) {
        if ((m >> e) & 1u) {
            float f = l[e];
            if (f > v0)      { v1 = v0; e1 = e0; v0 = f; e0 = e; }
            else if (f > v1) { v1 = f; e1 = e; }
        }
    }
    float w0 = 1.f, w1 = 0.f;
    if (e1 >= 0) {
        float ex = expf(v1 - v0);
        w0 = 1.0f / (1.0f + ex);
        w1 = ex * w0;
    }
    bool has1 = (e1 >= 0 && w1 > 0.f);
    int p0 = atomicAdd(&sCnt[e0], 1);
    int p1 = has1 ? atomicAdd(&sCnt[e1], 1) : -1;
    __syncthreads();
    if (tid < 8) sBase[tid] = atomicAdd(&g_cnt[tid], sCnt[tid]);
    __syncthreads();
    {
        int pos = sBase[e0] + p0;
        g_list[e0*NTOK + pos] = n;
        g_wl[e0*NTOK + pos]   = w0;
    }
    unsigned te = (unsigned)e0 | (255u << 8);
    float tw1 = 0.f;
    if (has1) {
        int pos = sBase[e1] + p1;
        g_list[e1*NTOK + pos] = n;
        g_wl[e1*NTOK + pos]   = w1;
        te = (unsigned)e0 | ((unsigned)e1 << 8);
        tw1 = w1;
    }
    g_te[n] = te; g_tw0[n] = w0; g_tw1[n] = tw1;

    float4 z4 = make_float4(0.f, 0.f, 0.f, 0.f);
    float4* o4 = (float4*)out;
    for (int i = n; i < NTOK*OUTD/4; i += NTOK) o4[i] = z4;
}

// ---------------- fused expert FFN: all-MMA (main + LoRA) ----------------
__global__ void __launch_bounds__(256) ffn_kernel(
    const float* __restrict__ x,  const float* __restrict__ bw,
    const float* __restrict__ b1, const float* __restrict__ b2,
    float* __restrict__ out)
{
    extern __shared__ float sm[];
    unsigned* um = (unsigned*)sm;
    float* sBw = sm + OFF_BW;
    float* sGw = sm + OFF_GW;
    int*   sTok = (int*)(sm + OFF_TOK);

    int e = blockIdx.y;
    int cnt = g_cnt[e];
    int t0 = blockIdx.x * TTILE;
    if (t0 >= cnt) return;
    int nt = min(TTILE, cnt - t0);
    int tid = threadIdx.x;

    if (tid < TTILE) {
        int idx = t0 + min(tid, nt - 1);
        int tok = g_list[e*NTOK + idx];
        sTok[tid] = tok;
        sGw[tid]  = (tid < nt) ? g_wl[e*NTOK + idx] : 0.f;
        *(float4*)(sBw + tid*4) = *(const float4*)(bw + (size_t)tok*4);
    }
    __syncthreads();

    {   // gather x -> packed bf16 hi/lo planes [tok][k]
        int t = tid & 63;
        int tok = sTok[t];
        #pragma unroll
        for (int pp = 0; pp < 2; pp++) {
            int part = (tid >> 6)*2 + pp;
            const float4* src = (const float4*)(x + (size_t)tok*CIN) + part*6;
            unsigned* dh = um + t*XW32 + part*12;
            unsigned* dl = um + OFF_XL + t*XW32 + part*12;
            #pragma unroll
            for (int i = 0; i < 6; i++) {
                float4 v = src[i];
                unsigned short h0,l0,h1,l1,h2,l2,h3,l3;
                bfsplit(v.x,h0,l0); bfsplit(v.y,h1,l1);
                bfsplit(v.z,h2,l2); bfsplit(v.w,h3,l3);
                dh[2*i]   = (unsigned)h0 | ((unsigned)h1 << 16);
                dh[2*i+1] = (unsigned)h2 | ((unsigned)h3 << 16);
                dl[2*i]   = (unsigned)l0 | ((unsigned)l1 << 16);
                dl[2*i+1] = (unsigned)l2 | ((unsigned)l3 << 16);
            }
        }
    }
    __syncthreads();

    int warp = tid >> 5, lane = tid & 31;
    int g = lane >> 2, kq = lane & 3;

    // LoRA1 as MMA: t1 = x @ A1  [64,192]x[192,32]; warp = (mt, nh)
    {
        int mt = warp >> 1, nh = warp & 1;
        float d[2][4] = {{0,0,0,0},{0,0,0,0}};
        const unsigned* a1h = g_a1h + (size_t)e*A1PE;
        const unsigned* a1l = g_a1l + (size_t)e*A1PE;
        #pragma unroll
        for (int kt = 0; kt < 12; kt++) {
            int base = (mt*16 + g)*XW32 + kt*8 + kq;
            unsigned ah[4], al[4];
            ah[0]=um[base];              al[0]=um[OFF_XL+base];
            ah[1]=um[base+8*XW32];       al[1]=um[OFF_XL+base+8*XW32];
            ah[2]=um[base+4];            al[2]=um[OFF_XL+base+4];
            ah[3]=um[base+8*XW32+4];     al[3]=um[OFF_XL+base+8*XW32+4];
            #pragma unroll
            for (int nj = 0; nj < 2; nj++) {
                int col = nh*16 + nj*8 + g;
                unsigned bh0 = a1h[(kt*8+kq)*40 + col], bh1 = a1h[(kt*8+kq+4)*40 + col];
                unsigned bl0 = a1l[(kt*8+kq)*40 + col], bl1 = a1l[(kt*8+kq+4)*40 + col];
                mma16(d[nj], ah, bh0, bh1);
                mma16(d[nj], ah, bl0, bl1);
                mma16(d[nj], al, bh0, bh1);
            }
        }
        #pragma unroll
        for (int nj = 0; nj < 2; nj++) {
            int b = nh*2 + nj;
            int kp = 96 + nh*8 + nj*4 + kq;
            #pragma unroll
            for (int half = 0; half < 2; half++) {
                int t = mt*16 + g + half*8;
                float scl = LSCALE * sBw[t*4 + b];
                unsigned short h0,l0,h1,l1;
                bfsplit(scl*d[nj][2*half],   h0, l0);
                bfsplit(scl*d[nj][2*half+1], h1, l1);
                um[t*XW32 + kp]          = (unsigned)h0 | ((unsigned)h1 << 16);
                um[OFF_XL + t*XW32 + kp] = (unsigned)l0 | ((unsigned)l1 << 16);
            }
        }
    }

    // ---- layer 1: [64,224]x[224,384]; warp = 4 M-tiles x 48 cols ----
    float d1[4][6][4];
    #pragma unroll
    for (int nj = 0; nj < 6; nj++) {
        int col = warp*48 + nj*8 + 2*kq;
        float b0v = b1[e*HID + col], b1v = b1[e*HID + col + 1];
        #pragma unroll
        for (int mt = 0; mt < 4; mt++) {
            d1[mt][nj][0] = b0v; d1[mt][nj][1] = b1v;
            d1[mt][nj][2] = b0v; d1[mt][nj][3] = b1v;
        }
    }
    const unsigned* w1h = g_w1h + (size_t)e*W1PE;
    const unsigned* w1l = g_w1l + (size_t)e*W1PE;
    {
        const float4* gh = (const float4*)w1h;
        const float4* gl = (const float4*)w1l;
        float4* dh = (float4*)(um + OFF_WB);
        float4* dl = (float4*)(um + OFF_WB + PLO);
        #pragma unroll
        for (int j = 0; j < 4; j++) {
            int idx = tid + j*256;
            if (idx < 784) { dh[idx] = gh[idx]; dl[idx] = gl[idx]; }
        }
    }
    float4 ph[4], pl[4];
    for (int kt = 0; kt < 14; kt++) {
        if (kt < 13) {
            const float4* gh = (const float4*)(w1h + (kt+1)*3136);
            const float4* gl = (const float4*)(w1l + (kt+1)*3136);
            #pragma unroll
            for (int j = 0; j < 4; j++) {
                int idx = tid + j*256;
                if (idx < 784) { ph[j] = gh[idx]; pl[j] = gl[idx]; }
            }
        }
        __syncthreads();
        const unsigned* Wh = um + OFF_WB + (kt&1)*WBUF;
        const unsigned* Wl = Wh + PLO;
        #pragma unroll
        for (int mt = 0; mt < 4; mt++) {
            int base = (mt*16 + g)*XW32 + kt*8 + kq;
            unsigned ah[4], al[4];
            ah[0] = um[base];              al[0] = um[OFF_XL + base];
            ah[1] = um[base + 8*XW32];     al[1] = um[OFF_XL + base + 8*XW32];
            ah[2] = um[base + 4];          al[2] = um[OFF_XL + base + 4];
            ah[3] = um[base + 8*XW32 + 4]; al[3] = um[OFF_XL + base + 8*XW32 + 4];
            #pragma unroll
            for (int nj = 0; nj < 6; nj++) {
                int n = warp*48 + nj*8 + g;
                unsigned bh0 = Wh[kq*392 + n], bh1 = Wh[(kq+4)*392 + n];
                unsigned bl0 = Wl[kq*392 + n], bl1 = Wl[(kq+4)*392 + n];
                mma16(d1[mt][nj], ah, bh0, bh1);
                mma16(d1[mt][nj], ah, bl0, bl1);
                mma16(d1[mt][nj], al, bh0, bh1);
            }
        }
        if (kt < 13) {
            float4* dh = (float4*)(um + OFF_WB + ((kt+1)&1)*WBUF);
            float4* dl = (float4*)(um + OFF_WB + ((kt+1)&1)*WBUF + PLO);
            #pragma unroll
            for (int j = 0; j < 4; j++) {
                int idx = tid + j*256;
                if (idx < 784) { dh[idx] = ph[j]; dl[idx] = pl[j]; }
            }
        }
    }
    __syncthreads();

    // exact GELU -> packed bf16 split H [tok][h]
    #pragma unroll
    for (int mt = 0; mt < 4; mt++)
        #pragma unroll
        for (int nj = 0; nj < 6; nj++) {
            int uc = warp*24 + nj*4 + kq;
            #pragma unroll
            for (int half = 0; half < 2; half++) {
                int t = mt*16 + g + half*8;
                float v0 = d1[mt][nj][2*half], v1 = d1[mt][nj][2*half + 1];
                float g0 = v0 * 0.5f * (1.0f + erff(v0 * 0.70710678118654752f));
                float g1 = v1 * 0.5f * (1.0f + erff(v1 * 0.70710678118654752f));
                unsigned short h0,l0,h1,l1;
                bfsplit(g0,h0,l0); bfsplit(g1,h1,l1);
                um[t*HW32 + uc]          = (unsigned)h0 | ((unsigned)h1 << 16);
                um[OFF_HL + t*HW32 + uc] = (unsigned)l0 | ((unsigned)l1 << 16);
            }
        }
    __syncthreads();

    // LoRA2 as MMA: t2 = h @ A2  [64,384]x[384,32]
    {
        int mt = warp >> 1, nh = warp & 1;
        float d[2][4] = {{0,0,0,0},{0,0,0,0}};
        const unsigned* a2h = g_a2h + (size_t)e*A2PE;
        const unsigned* a2l = g_a2l + (size_t)e*A2PE;
        #pragma unroll 4
        for (int kt = 0; kt < 24; kt++) {
            int base = (mt*16 + g)*HW32 + kt*8 + kq;
            unsigned ah[4], al[4];
            ah[0]=um[base];              al[0]=um[OFF_HL+base];
            ah[1]=um[base+8*HW32];       al[1]=um[OFF_HL+base+8*HW32];
            ah[2]=um[base+4];            al[2]=um[OFF_HL+base+4];
            ah[3]=um[base+8*HW32+4];     al[3]=um[OFF_HL+base+8*HW32+4];
            #pragma unroll
            for (int nj = 0; nj < 2; nj++) {
                int col = nh*16 + nj*8 + g;
                unsigned bh0 = a2h[(kt*8+kq)*40 + col], bh1 = a2h[(kt*8+kq+4)*40 + col];
                unsigned bl0 = a2l[(kt*8+kq)*40 + col], bl1 = a2l[(kt*8+kq+4)*40 + col];
                mma16(d[nj], ah, bh0, bh1);
                mma16(d[nj], ah, bl0, bl1);
                mma16(d[nj], al, bh0, bh1);
            }
        }
        #pragma unroll
        for (int nj = 0; nj < 2; nj++) {
            int b = nh*2 + nj;
            int kp = 192 + nh*8 + nj*4 + kq;
            #pragma unroll
            for (int half = 0; half < 2; half++) {
                int t = mt*16 + g + half*8;
                float scl = LSCALE * sBw[t*4 + b];
                unsigned short h0,l0,h1,l1;
                bfsplit(scl*d[nj][2*half],   h0, l0);
                bfsplit(scl*d[nj][2*half+1], h1, l1);
                um[t*HW32 + kp]          = (unsigned)h0 | ((unsigned)h1 << 16);
                um[OFF_HL + t*HW32 + kp] = (unsigned)l0 | ((unsigned)l1 << 16);
            }
        }
    }

    // ---- layer 2: [64,416]x[416,192]; warp = 4 M-tiles x 24 cols ----
    float d2[4][3][4];
    #pragma unroll
    for (int nj = 0; nj < 3; nj++) {
        int col = warp*24 + nj*8 + 2*kq;
        float b0v = b2[e*OUTD + col], b1v = b2[e*OUTD + col + 1];
        #pragma unroll
        for (int mt = 0; mt < 4; mt++) {
            d2[mt][nj][0] = b0v; d2[mt][nj][1] = b1v;
            d2[mt][nj][2] = b0v; d2[mt][nj][3] = b1v;
        }
    }
    const unsigned* w2h = g_w2h + (size_t)e*W2PE;
    const unsigned* w2l = g_w2l + (size_t)e*W2PE;
    {
        const float4* gh = (const float4*)w2h;
        const float4* gl = (const float4*)w2l;
        float4* dh = (float4*)(um + OFF_WB);
        float4* dl = (float4*)(um + OFF_WB + PLO);
        #pragma unroll
        for (int j = 0; j < 2; j++) {
            int idx = tid + j*256;
            if (idx < 400) { dh[idx] = gh[idx]; dl[idx] = gl[idx]; }
        }
    }
    for (int kt = 0; kt < 26; kt++) {
        if (kt < 25) {
            const float4* gh = (const float4*)(w2h + (kt+1)*1600);
            const float4* gl = (const float4*)(w2l + (kt+1)*1600);
            #pragma unroll
            for (int j = 0; j < 2; j++) {
                int idx = tid + j*256;
                if (idx < 400) { ph[j] = gh[idx]; pl[j] = gl[idx]; }
            }
        }
        __syncthreads();
        const unsigned* Wh = um + OFF_WB + (kt&1)*WBUF;
        const unsigned* Wl = Wh + PLO;
        #pragma unroll
        for (int mt = 0; mt < 4; mt++) {
            int base = (mt*16 + g)*HW32 + kt*8 + kq;
            unsigned ah[4], al[4];
            ah[0] = um[base];              al[0] = um[OFF_HL + base];
            ah[1] = um[base + 8*HW32];     al[1] = um[OFF_HL + base + 8*HW32];
            ah[2] = um[base + 4];          al[2] = um[OFF_HL + base + 4];
            ah[3] = um[base + 8*HW32 + 4]; al[3] = um[OFF_HL + base + 8*HW32 + 4];
            #pragma unroll
            for (int nj = 0; nj < 3; nj++) {
                int n = warp*24 + nj*8 + g;
                unsigned bh0 = Wh[kq*200 + n], bh1 = Wh[(kq+4)*200 + n];
                unsigned bl0 = Wl[kq*200 + n], bl1 = Wl[(kq+4)*200 + n];
                mma16(d2[mt][nj], ah, bh0, bh1);
                mma16(d2[mt][nj], ah, bl0, bl1);
                mma16(d2[mt][nj], al, bh0, bh1);
            }
        }
        if (kt < 25) {
            float4* dh = (float4*)(um + OFF_WB + ((kt+1)&1)*WBUF);
            float4* dl = (float4*)(um + OFF_WB + ((kt+1)&1)*WBUF + PLO);
            #pragma unroll
            for (int j = 0; j < 2; j++) {
                int idx = tid + j*256;
                if (idx < 400) { dh[idx] = ph[j]; dl[idx] = pl[j]; }
            }
        }
    }
    // epilogue
    #pragma unroll
    for (int mt = 0; mt < 4; mt++)
        #pragma unroll
        for (int nj = 0; nj < 3; nj++) {
            int col = warp*24 + nj*8 + 2*kq;
            #pragma unroll
            for (int q = 0; q < 4; q++) {
                int t = mt*16 + g + (q >> 1)*8;
                if (t < nt) {
                    int tok = sTok[t];
                    atomicAdd(&out[(size_t)tok*OUTD + col + (q & 1)],
                              sGw[t]*d2[mt][nj][q]);
                }
            }
        }
}

// ---------------- deterministic loss ----------------
__global__ void __launch_bounds__(1024) loss_kernel(float* out, int out_size) {
    __shared__ float sI[8][32], sL[8][32];
    int tid = threadIdx.x, lane = tid & 31, warp = tid >> 5;
    float imp[8] = {0,0,0,0,0,0,0,0}, ld[8] = {0,0,0,0,0,0,0,0};
    for (int n = tid; n < NTOK; n += 1024) {
        unsigned te = g_te[n];
        int e0 = te & 255u, e1 = (te >> 8) & 255u;
        imp[e0] += g_tw0[n]; ld[e0] += 1.f;
        if (e1 != 255) { imp[e1] += g_tw1[n]; ld[e1] += 1.f; }
    }
    #pragma unroll
    for (int e = 0; e < 8; e++) {
        #pragma unroll
        for (int o = 16; o; o >>= 1) {
            imp[e] += __shfl_xor_sync(0xffffffffu, imp[e], o);
            ld[e]  += __shfl_xor_sync(0xffffffffu, ld[e],  o);
        }
        if (lane == 0) { sI[e][warp] = imp[e]; sL[e][warp] = ld[e]; }
    }
    __syncthreads();
    if (tid == 0) {
        float I[8], L[8], mi = 0.f, ml = 0.f;
        for (int e = 0; e < 8; e++) {
            float a = 0.f, b = 0.f;
            for (int w = 0; w < 32; w++) { a += sI[e][w]; b += sL[e][w]; }
            I[e] = a; L[e] = b; mi += a; ml += b;
        }
        mi *= 0.125f; ml *= 0.125f;
        float vi = 0.f, vl = 0.f;
        for (int e = 0; e < 8; e++) {
            float di = I[e] - mi; vi += di*di;
            float dl = L[e] - ml; vl += dl*dl;
        }
        vi *= 0.125f; vl *= 0.125f;
        float loss = (vi / (mi*mi + 1e-10f) + vl / (ml*ml + 1e-10f)) * 0.01f;
        if (out_size > NTOK*OUTD) out[NTOK*OUTD] = loss;
    }
    for (int i = NTOK*OUTD + 1 + tid; i < out_size; i += 1024) out[i] = 0.f;
}

// ---------------- launch ----------------
extern "C" void kernel_launch(void* const* d_in, const int* in_sizes, int n_in,
                              void* d_out, int out_size) {
    const float* x     = (const float*)d_in[0];
    const float* bw    = (const float*)d_in[1];
    const float* xprev = (const float*)d_in[2];
    const float* Wz    = (const float*)d_in[3];
    const float* lng   = (const float*)d_in[4];
    const float* lnb   = (const float*)d_in[5];
    const float* Wg    = (const float*)d_in[6];
    const float* bg    = (const float*)d_in[7];
    const float* W1    = (const float*)d_in[8];
    const float* b1    = (const float*)d_in[9];
    const float* W2    = (const float*)d_in[10];
    const float* b2    = (const float*)d_in[11];
    const float* A1    = (const float*)d_in[12];
    const float* B1    = (const float*)d_in[13];
    const float* A2    = (const float*)d_in[14];
    const float* B2    = (const float*)d_in[15];
    float* out = (float*)d_out;

    const size_t GATE_SMEM = (size_t)(12288 + 2322 + 258 + 258 + 8 + 32*192) * 4;
    const size_t FFN_SMEM  = (size_t)FFN_U32 * 4;
    cudaFuncSetAttribute(gate_kernel, cudaFuncAttributeMaxDynamicSharedMemorySize, (int)GATE_SMEM);
    cudaFuncSetAttribute(ffn_kernel,  cudaFuncAttributeMaxDynamicSharedMemorySize, (int)FFN_SMEM);

    init_kernel<<<2, 1024>>>();
    split_kernel<<<336, 1024>>>(W1, B1, W2, B2, A1, A2);
    gate_kernel<<<NTOK/32, 1024, GATE_SMEM>>>(x, xprev, Wz, lng, lnb, Wg, bg);
    for (int p = 0; p < 4; p++) {
        int shift = 24 - p*8;
        hist_kernel<<<dim3(32, NE), 256>>>(shift);
        digit_kernel<<<NE, 32>>>(shift);
    }
    mark_kernel<<<dim3(64, NE), 256>>>();
    scan_kernel<<<NE, 32>>>();
    tie_kernel<<<dim3(64, NE), 32>>>();
    route_kernel<<<NTOK/256, 256>>>(out);
    ffn_kernel<<<dim3(NTOK/TTILE, NE), 256, FFN_SMEM>>>(x, bw, b1, b2, out);
    loss_kernel<<<1, 1024>>>(out, out_size);
}

// round 15
// speedup vs baseline: 2.6991x; 1.0983x over previous
#include <cuda_runtime.h>
#include <math.h>
#include <stdint.h>

#define NTOK 65536
#define CIN 192
#define HID 384
#define OUTD 192
#define NE 8
#define KCAP 10240
#define TTILE 32
#define LSCALE 2.0f

// FFN smem (u32 units); X and H planes share one union (x dead before h written)
#define XW32   116
#define HW32   212
#define OFF_XL 3712      /* 32*116 */
#define OFF_HL 6784      /* 32*212 */
#define OFF_BW 13568
#define OFF_GW 13696
#define OFF_TOK 13728
#define FFN_U32 13760

#define W1PE 43904       /* per-expert u32: 112*392 */
#define W2PE 41600       /* 208*200 */
#define A1PE 3840        /* 96*40 */
#define A2PE 7680        /* 192*40 */

__device__ __forceinline__ unsigned short f2bf(float x) {
    unsigned u = __float_as_uint(x);
    return (unsigned short)((u + 0x7fffu + ((u >> 16) & 1u)) >> 16);
}
__device__ __forceinline__ float bf2f(unsigned short b) {
    return __uint_as_float((unsigned)b << 16);
}
__device__ __forceinline__ void bfsplit(float x, unsigned short& h, unsigned short& l) {
    h = f2bf(x);
    l = f2bf(x - bf2f(h));
}
__device__ __forceinline__ void mma16(float* d, const unsigned* a, unsigned b0, unsigned b1) {
    asm("mma.sync.aligned.m16n8k16.row.col.f32.bf16.bf16.f32 "
        "{%0,%1,%2,%3},{%4,%5,%6,%7},{%8,%9},{%0,%1,%2,%3};"
        : "+f"(d[0]), "+f"(d[1]), "+f"(d[2]), "+f"(d[3])
        : "r"(a[0]), "r"(a[1]), "r"(a[2]), "r"(a[3]), "r"(b0), "r"(b1));
}

// ---------------- device scratch ----------------
__device__ float    g_logits[NE * NTOK];
__device__ unsigned g_mask[NTOK];
__device__ int      g_cnt[NE];
__device__ int      g_list[NE * NTOK];
__device__ float    g_wl[NE * NTOK];
__device__ unsigned g_te[NTOK];
__device__ float    g_tw0[NTOK];
__device__ float    g_tw1[NTOK];
__device__ __align__(16) unsigned g_w1h[NE*W1PE];
__device__ __align__(16) unsigned g_w1l[NE*W1PE];
__device__ __align__(16) unsigned g_w2h[NE*W2PE];
__device__ __align__(16) unsigned g_w2l[NE*W2PE];
__device__ __align__(16) unsigned g_a1h[NE*A1PE];
__device__ __align__(16) unsigned g_a1l[NE*A1PE];
__device__ __align__(16) unsigned g_a2h[NE*A2PE];
__device__ __align__(16) unsigned g_a2l[NE*A2PE];
// parallel radix select state
__device__ unsigned g_hist[NE][256];
__device__ unsigned g_thr[NE];
__device__ unsigned g_need[NE];
__device__ int      g_ccount[NE][64];
__device__ int      g_cbase[NE][64];

__global__ void init_kernel() {
    int t = blockIdx.x * 1024 + threadIdx.x;
    if (t < NE) { g_cnt[t] = 0; g_thr[t] = 0u; g_need[t] = KCAP; }
    if (t < NE*256) ((unsigned*)g_hist)[t] = 0u;
}

// ---------------- one-shot weight split ----------------
__global__ void __launch_bounds__(1024) split_kernel(
    const float* __restrict__ W1, const float* __restrict__ B1,
    const float* __restrict__ W2, const float* __restrict__ B2,
    const float* __restrict__ A1, const float* __restrict__ A2)
{
    int i = blockIdx.x * 1024 + threadIdx.x;
    if (i < NE*112*384) {
        int e = i / 43008, rem = i % 43008;
        int kp = rem / 384, n = rem % 384;
        int k0 = 2*kp, k1 = k0 + 1;
        float v0 = (k0 < 192) ? W1[((size_t)e*192 + k0)*384 + n]
                              : B1[((size_t)e*32 + (k0-192))*384 + n];
        float v1 = (k1 < 192) ? W1[((size_t)e*192 + k1)*384 + n]
                              : B1[((size_t)e*32 + (k1-192))*384 + n];
        unsigned short h0,l0,h1,l1;
        bfsplit(v0,h0,l0); bfsplit(v1,h1,l1);
        g_w1h[(size_t)e*W1PE + kp*392 + n] = (unsigned)h0 | ((unsigned)h1 << 16);
        g_w1l[(size_t)e*W1PE + kp*392 + n] = (unsigned)l0 | ((unsigned)l1 << 16);
    }
    if (i < NE*208*192) {
        int e = i / 39936, rem = i % 39936;
        int kp = rem / 192, n = rem % 192;
        int k0 = 2*kp, k1 = k0 + 1;
        float v0 = (k0 < 384) ? W2[((size_t)e*384 + k0)*192 + n]
                              : B2[((size_t)e*32 + (k0-384))*192 + n];
        float v1 = (k1 < 384) ? W2[((size_t)e*384 + k1)*192 + n]
                              : B2[((size_t)e*32 + (k1-384))*192 + n];
        unsigned short h0,l0,h1,l1;
        bfsplit(v0,h0,l0); bfsplit(v1,h1,l1);
        g_w2h[(size_t)e*W2PE + kp*200 + n] = (unsigned)h0 | ((unsigned)h1 << 16);
        g_w2l[(size_t)e*W2PE + kp*200 + n] = (unsigned)l0 | ((unsigned)l1 << 16);
    }
    if (i < NE*96*32) {
        int e = i / 3072, rem = i % 3072;
        int kp = rem / 32, col = rem & 31;
        int b = col >> 3, r = col & 7;
        const float* A = A1 + ((size_t)(e*4 + b)*192)*8 + r;
        float v0 = A[(size_t)(2*kp)*8], v1 = A[(size_t)(2*kp+1)*8];
        unsigned short h0,l0,h1,l1;
        bfsplit(v0,h0,l0); bfsplit(v1,h1,l1);
        g_a1h[(size_t)e*A1PE + kp*40 + col] = (unsigned)h0 | ((unsigned)h1 << 16);
        g_a1l[(size_t)e*A1PE + kp*40 + col] = (unsigned)l0 | ((unsigned)l1 << 16);
    }
    if (i < NE*192*32) {
        int e = i / 6144, rem = i % 6144;
        int kp = rem / 32, col = rem & 31;
        int b = col >> 3, r = col & 7;
        const float* A = A2 + ((size_t)(e*4 + b)*384)*8 + r;
        float v0 = A[(size_t)(2*kp)*8], v1 = A[(size_t)(2*kp+1)*8];
        unsigned short h0,l0,h1,l1;
        bfsplit(v0,h0,l0); bfsplit(v1,h1,l1);
        g_a2h[(size_t)e*A2PE + kp*40 + col] = (unsigned)h0 | ((unsigned)h1 << 16);
        g_a2l[(size_t)e*A2PE + kp*40 + col] = (unsigned)l0 | ((unsigned)l1 << 16);
    }
}

// ---------------- gate: features + LN + logits ----------------
__global__ void __launch_bounds__(1024) gate_kernel(
    const float* __restrict__ x, const float* __restrict__ xprev,
    const float* __restrict__ Wz, const float* __restrict__ lng,
    const float* __restrict__ lnb, const float* __restrict__ Wg,
    const float* __restrict__ bg)
{
    extern __shared__ float sm[];
    float* sWz = sm;              // 12288, pair-interleaved
    float* sWg = sWz + 12288;     // 258*12 stride-12 padded
    float* sg  = sWg + 3096;
    float* sb  = sg + 258;
    float* sbg = sb + 258;
    float* sX  = sbg + 8;         // 32*192

    int tid = threadIdx.x, lane = tid & 31, warp = tid >> 5;
    int n = blockIdx.x * 32 + warp;

    for (int i = tid; i < 12288; i += 1024) {
        int col = i & 63;
        int col2 = ((col & 31) << 1) | (col >> 5);
        sWz[(i & ~63) + col2] = Wz[i];
    }
    for (int i = tid; i < 2064;  i += 1024) sWg[(i >> 3)*12 + (i & 7)] = Wg[i];
    for (int i = tid; i < 258;   i += 1024) { sg[i] = lng[i]; sb[i] = lnb[i]; }
    if (tid < 8) sbg[tid] = bg[tid];

    float xr[6];
    #pragma unroll
    for (int i = 0; i < 6; i++) {
        xr[i] = x[(size_t)n*CIN + lane + 32*i];
        sX[warp*CIN + lane + 32*i] = xr[i];
    }
    float s = 0.f, ss = 0.f;
    #pragma unroll
    for (int i = 0; i < 6; i++) {
        float a = fabsf(xr[i] - xprev[(size_t)n*CIN + lane + 32*i]);
        s += a; ss += a*a;
    }
    #pragma unroll
    for (int o = 16; o; o >>= 1) {
        s  += __shfl_xor_sync(0xffffffffu, s, o);
        ss += __shfl_xor_sync(0xffffffffu, ss, o);
    }
    float dmean = s * (1.0f/192.0f);
    float dvar  = fmaxf((ss - s*dmean) * (1.0f/191.0f), 0.f);
    float mu = log1pf(dmean), sd = log1pf(sqrtf(dvar));

    __syncthreads();

    float z0 = 0.f, z1 = 0.f;
    for (int c = 0; c < CIN; c++) {
        float xv = sX[warp*CIN + c];
        float2 w = *(const float2*)(sWz + c*64 + 2*lane);
        z0 = fmaf(xv, w.x, z0);
        z1 = fmaf(xv, w.y, z1);
    }
    float sa = z0 + z1, s2 = z0*z0 + z1*z1;
    #pragma unroll
    for (int i = 0; i < 6; i++) { sa += xr[i]; s2 += xr[i]*xr[i]; }
    if (lane == 0) { sa += mu + sd; s2 += mu*mu + sd*sd; }
    #pragma unroll
    for (int o = 16; o; o >>= 1) {
        sa += __shfl_xor_sync(0xffffffffu, sa, o);
        s2 += __shfl_xor_sync(0xffffffffu, s2, o);
    }
    float m_   = sa * (1.0f/258.0f);
    float rstd = rsqrtf(s2 * (1.0f/258.0f) - m_*m_ + 1e-5f);

    float acc[8] = {0,0,0,0,0,0,0,0};
    #pragma unroll
    for (int i = 0; i < 6; i++) {
        int idx = lane + 32*i;
        float nv = (xr[i] - m_)*rstd*sg[idx] + sb[idx];
        float4 wa = *(const float4*)(sWg + idx*12);
        float4 wb = *(const float4*)(sWg + idx*12 + 4);
        acc[0]=fmaf(nv,wa.x,acc[0]); acc[1]=fmaf(nv,wa.y,acc[1]);
        acc[2]=fmaf(nv,wa.z,acc[2]); acc[3]=fmaf(nv,wa.w,acc[3]);
        acc[4]=fmaf(nv,wb.x,acc[4]); acc[5]=fmaf(nv,wb.y,acc[5]);
        acc[6]=fmaf(nv,wb.z,acc[6]); acc[7]=fmaf(nv,wb.w,acc[7]);
    }
    {
        int idx = 192 + lane;
        float nv = (z0 - m_)*rstd*sg[idx] + sb[idx];
        float4 wa = *(const float4*)(sWg + idx*12);
        float4 wb = *(const float4*)(sWg + idx*12 + 4);
        acc[0]=fmaf(nv,wa.x,acc[0]); acc[1]=fmaf(nv,wa.y,acc[1]);
        acc[2]=fmaf(nv,wa.z,acc[2]); acc[3]=fmaf(nv,wa.w,acc[3]);
        acc[4]=fmaf(nv,wb.x,acc[4]); acc[5]=fmaf(nv,wb.y,acc[5]);
        acc[6]=fmaf(nv,wb.z,acc[6]); acc[7]=fmaf(nv,wb.w,acc[7]);
        idx = 224 + lane;
        nv = (z1 - m_)*rstd*sg[idx] + sb[idx];
        wa = *(const float4*)(sWg + idx*12);
        wb = *(const float4*)(sWg + idx*12 + 4);
        acc[0]=fmaf(nv,wa.x,acc[0]); acc[1]=fmaf(nv,wa.y,acc[1]);
        acc[2]=fmaf(nv,wa.z,acc[2]); acc[3]=fmaf(nv,wa.w,acc[3]);
        acc[4]=fmaf(nv,wb.x,acc[4]); acc[5]=fmaf(nv,wb.y,acc[5]);
        acc[6]=fmaf(nv,wb.z,acc[6]); acc[7]=fmaf(nv,wb.w,acc[7]);
    }
    if (lane == 0) {
        float nv = (mu - m_)*rstd*sg[256] + sb[256];
        float4 wa = *(const float4*)(sWg + 256*12);
        float4 wb = *(const float4*)(sWg + 256*12 + 4);
        acc[0]=fmaf(nv,wa.x,acc[0]); acc[1]=fmaf(nv,wa.y,acc[1]);
        acc[2]=fmaf(nv,wa.z,acc[2]); acc[3]=fmaf(nv,wa.w,acc[3]);
        acc[4]=fmaf(nv,wb.x,acc[4]); acc[5]=fmaf(nv,wb.y,acc[5]);
        acc[6]=fmaf(nv,wb.z,acc[6]); acc[7]=fmaf(nv,wb.w,acc[7]);
        nv = (sd - m_)*rstd*sg[257] + sb[257];
        wa = *(const float4*)(sWg + 257*12);
        wb = *(const float4*)(sWg + 257*12 + 4);
        acc[0]=fmaf(nv,wa.x,acc[0]); acc[1]=fmaf(nv,wa.y,acc[1]);
        acc[2]=fmaf(nv,wa.z,acc[2]); acc[3]=fmaf(nv,wa.w,acc[3]);
        acc[4]=fmaf(nv,wb.x,acc[4]); acc[5]=fmaf(nv,wb.y,acc[5]);
        acc[6]=fmaf(nv,wb.z,acc[6]); acc[7]=fmaf(nv,wb.w,acc[7]);
    }
    #pragma unroll
    for (int e = 0; e < 8; e++) {
        #pragma unroll
        for (int o = 16; o; o >>= 1) acc[e] += __shfl_xor_sync(0xffffffffu, acc[e], o);
    }
    if (lane == 0) {
        #pragma unroll
        for (int e = 0; e < 8; e++) g_logits[e*NTOK + n] = acc[e] + sbg[e];
        g_mask[n] = 0u;
    }
}

// ---------------- parallel radix select ----------------
__device__ __forceinline__ unsigned f2key(float f) {
    unsigned u = __float_as_uint(f);
    return (u & 0x80000000u) ? ~u : (u | 0x80000000u);
}

__global__ void __launch_bounds__(256) hist_kernel(int shift) {
    __shared__ unsigned hist[256];
    int e = blockIdx.y, tid = threadIdx.x, lane = tid & 31;
    hist[tid] = 0;
    __syncthreads();
    unsigned pmask = (shift == 24) ? 0u : (0xFFFFFFFFu << (shift + 8));
    unsigned prefix = g_thr[e] & pmask;
    const float* base = g_logits + (size_t)e * NTOK;
    int n0 = blockIdx.x * 2048;
    for (int i = tid; i < 2048; i += 256) {
        unsigned k = f2key(base[n0 + i]);
        bool act = ((k & pmask) == prefix);
        unsigned dg = act ? ((k >> shift) & 255u) : 0xffffffffu;
        unsigned peers = __match_any_sync(0xffffffffu, dg);
        if (act && (__ffs(peers) - 1) == lane)
            atomicAdd(&hist[dg], (unsigned)__popc(peers));
    }
    __syncthreads();
    if (hist[tid]) atomicAdd(&g_hist[e][tid], hist[tid]);
}

// grid NE x 32: warp-parallel digit pick (descending), then zero hist
__global__ void __launch_bounds__(32) digit_kernel(int shift) {
    int e = blockIdx.x, lane = threadIdx.x;
    unsigned need = g_need[e];
    unsigned v[8];
    unsigned lsum = 0;
    #pragma unroll
    for (int j = 0; j < 8; j++) {
        v[j] = g_hist[e][255 - (lane*8 + j)];
        lsum += v[j];
    }
    unsigned inc = lsum;
    #pragma unroll
    for (int o = 1; o < 32; o <<= 1) {
        unsigned t = __shfl_up_sync(0xffffffffu, inc, o);
        if (lane >= o) inc += t;
    }
    unsigned pre = inc - lsum;   // cum from top before my group
    bool crossing = (pre < need) && (pre + lsum >= need);
    if (crossing) {
        unsigned cum = pre;
        #pragma unroll
        for (int j = 0; j < 8; j++) {
            int d = 255 - (lane*8 + j);
            if (d == 0 || cum + v[j] >= need) {
                g_thr[e] |= ((unsigned)d) << shift;
                g_need[e] = need - cum;
                break;
            }
            cum += v[j];
        }
    }
    __syncwarp();
    #pragma unroll
    for (int j = 0; j < 8; j++) g_hist[e][lane*8 + j] = 0u;
}

__global__ void __launch_bounds__(256) mark_kernel() {
    int e = blockIdx.y, c = blockIdx.x, tid = threadIdx.x, lane = tid & 31;
    unsigned thr = g_thr[e];
    const float* base = g_logits + (size_t)e * NTOK;
    int cnt = 0;
    for (int i = tid; i < 1024; i += 256) {
        unsigned k = f2key(base[c*1024 + i]);
        if (k > thr) atomicOr(&g_mask[c*1024 + i], 1u << e);
        cnt += (k == thr);
    }
    #pragma unroll
    for (int o = 16; o; o >>= 1) cnt += __shfl_xor_sync(0xffffffffu, cnt, o);
    __shared__ int ws[8];
    if (lane == 0) ws[tid >> 5] = cnt;
    __syncthreads();
    if (tid == 0) {
        int t = 0;
        for (int w = 0; w < 8; w++) t += ws[w];
        g_ccount[e][c] = t;
    }
}

__global__ void __launch_bounds__(32) scan_kernel() {
    int e = blockIdx.x;
    if (threadIdx.x == 0) {
        int run = 0;
        for (int c = 0; c < 64; c++) { g_cbase[e][c] = run; run += g_ccount[e][c]; }
    }
}

__global__ void __launch_bounds__(32) tie_kernel() {
    int e = blockIdx.y, c = blockIdx.x, lane = threadIdx.x;
    int r = (int)g_need[e];
    int rank = g_cbase[e][c];
    if (rank >= r) return;
    unsigned thr = g_thr[e];
    const float* base = g_logits + (size_t)e * NTOK;
    for (int s = 0; s < 32; s++) {
        int n = c*1024 + s*32 + lane;
        bool p = (f2key(base[n]) == thr);
        unsigned bal = __ballot_sync(0xffffffffu, p);
        int myrank = rank + __popc(bal & ((1u << lane) - 1u));
        if (p && myrank < r) atomicOr(&g_mask[n], 1u << e);
        rank += __popc(bal);
        if (rank >= r) break;
    }
}

// ---------------- routing (block-aggregated dispatch) ----------------
__global__ void __launch_bounds__(256) route_kernel(float* __restrict__ out) {
    __shared__ int sCnt[8], sBase[8];
    int tid = threadIdx.x;
    int n = blockIdx.x * 256 + tid;
    if (tid < 8) sCnt[tid] = 0;
    __syncthreads();

    float l[8];
    #pragma unroll
    for (int e = 0; e < 8; e++) l[e] = g_logits[e*NTOK + n];
    unsigned m = g_mask[n];
    if (m == 0u) {
        int best = 0; float bv = l[0];
        #pragma unroll
        for (int e = 1; e < 8; e++) if (l[e] > bv) { bv = l[e]; best = e; }
        m = 1u << best;
    }
    int e0 = -1, e1 = -1; float v0 = -INFINITY, v1 = -INFINITY;
    #pragma unroll
    for (int e = 0; e < 8; e++) {
        if ((m >> e) & 1u) {
            float f = l[e];
            if (f > v0)      { v1 = v0; e1 = e0; v0 = f; e0 = e; }
            else if (f > v1) { v1 = f; e1 = e; }
        }
    }
    float w0 = 1.f, w1 = 0.f;
    if (e1 >= 0) {
        float ex = expf(v1 - v0);
        w0 = 1.0f / (1.0f + ex);
        w1 = ex * w0;
    }
    bool has1 = (e1 >= 0 && w1 > 0.f);
    int p0 = atomicAdd(&sCnt[e0], 1);
    int p1 = has1 ? atomicAdd(&sCnt[e1], 1) : -1;
    __syncthreads();
    if (tid < 8) sBase[tid] = atomicAdd(&g_cnt[tid], sCnt[tid]);
    __syncthreads();
    {
        int pos = sBase[e0] + p0;
        g_list[e0*NTOK + pos] = n;
        g_wl[e0*NTOK + pos]   = w0;
    }
    unsigned te = (unsigned)e0 | (255u << 8);
    float tw1 = 0.f;
    if (has1) {
        int pos = sBase[e1] + p1;
        g_list[e1*NTOK + pos] = n;
        g_wl[e1*NTOK + pos]   = w1;
        te = (unsigned)e0 | ((unsigned)e1 << 8);
        tw1 = w1;
    }
    g_te[n] = te; g_tw0[n] = w0; g_tw1[n] = tw1;

    float4 z4 = make_float4(0.f, 0.f, 0.f, 0.f);
    float4* o4 = (float4*)out;
    for (int i = n; i < NTOK*OUTD/4; i += NTOK) o4[i] = z4;
}

// ---------------- fused expert FFN v15: weights from global, 2 CTAs/SM ------
__global__ void __launch_bounds__(256, 2) ffn_kernel(
    const float* __restrict__ x,  const float* __restrict__ bw,
    const float* __restrict__ b1, const float* __restrict__ b2,
    float* __restrict__ out)
{
    extern __shared__ float sm[];
    unsigned* um = (unsigned*)sm;
    float* sBw = sm + OFF_BW;
    float* sGw = sm + OFF_GW;
    int*   sTok = (int*)(sm + OFF_TOK);

    int e = blockIdx.y;
    int cnt = g_cnt[e];
    int t0 = blockIdx.x * TTILE;
    if (t0 >= cnt) return;
    int nt = min(TTILE, cnt - t0);
    int tid = threadIdx.x;

    if (tid < TTILE) {
        int idx = t0 + min(tid, nt - 1);
        int tok = g_list[e*NTOK + idx];
        sTok[tid] = tok;
        sGw[tid]  = (tid < nt) ? g_wl[e*NTOK + idx] : 0.f;
        *(float4*)(sBw + tid*4) = *(const float4*)(bw + (size_t)tok*4);
    }
    __syncthreads();

    {   // gather x -> packed bf16 hi/lo planes [tok][k]
        int t = tid & 31, part = tid >> 5;
        int tok = sTok[t];
        const float4* src = (const float4*)(x + (size_t)tok*CIN) + part*6;
        unsigned* dh = um + t*XW32 + part*12;
        unsigned* dl = um + OFF_XL + t*XW32 + part*12;
        #pragma unroll
        for (int i = 0; i < 6; i++) {
            float4 v = src[i];
            unsigned short h0,l0,h1,l1,h2,l2,h3,l3;
            bfsplit(v.x,h0,l0); bfsplit(v.y,h1,l1);
            bfsplit(v.z,h2,l2); bfsplit(v.w,h3,l3);
            dh[2*i]   = (unsigned)h0 | ((unsigned)h1 << 16);
            dh[2*i+1] = (unsigned)h2 | ((unsigned)h3 << 16);
            dl[2*i]   = (unsigned)l0 | ((unsigned)l1 << 16);
            dl[2*i+1] = (unsigned)l2 | ((unsigned)l3 << 16);
        }
    }
    __syncthreads();

    int warp = tid >> 5, lane = tid & 31;
    int g = lane >> 2, kq = lane & 3;

    // LoRA1 as MMA: [32,192]x[192,32]; warp = (mt = warp>>2, nh = warp&3)
    {
        int mt = warp >> 2, nh = warp & 3;
        float d[4] = {0,0,0,0};
        const unsigned* a1h = g_a1h + (size_t)e*A1PE;
        const unsigned* a1l = g_a1l + (size_t)e*A1PE;
        #pragma unroll
        for (int kt = 0; kt < 12; kt++) {
            int base = (mt*16 + g)*XW32 + kt*8 + kq;
            unsigned ah[4], al[4];
            ah[0]=um[base];              al[0]=um[OFF_XL+base];
            ah[1]=um[base+8*XW32];       al[1]=um[OFF_XL+base+8*XW32];
            ah[2]=um[base+4];            al[2]=um[OFF_XL+base+4];
            ah[3]=um[base+8*XW32+4];     al[3]=um[OFF_XL+base+8*XW32+4];
            int col = nh*8 + g;
            unsigned bh0 = a1h[(kt*8+kq)*40 + col], bh1 = a1h[(kt*8+kq+4)*40 + col];
            unsigned bl0 = a1l[(kt*8+kq)*40 + col], bl1 = a1l[(kt*8+kq+4)*40 + col];
            mma16(d, ah, bh0, bh1);
            mma16(d, ah, bl0, bl1);
            mma16(d, al, bh0, bh1);
        }
        int b = nh;
        int kp = 96 + nh*4 + kq;
        #pragma unroll
        for (int half = 0; half < 2; half++) {
            int t = mt*16 + g + half*8;
            float scl = LSCALE * sBw[t*4 + b];
            unsigned short h0,l0,h1,l1;
            bfsplit(scl*d[2*half],   h0, l0);
            bfsplit(scl*d[2*half+1], h1, l1);
            um[t*XW32 + kp]          = (unsigned)h0 | ((unsigned)h1 << 16);
            um[OFF_XL + t*XW32 + kp] = (unsigned)l0 | ((unsigned)l1 << 16);
        }
    }
    __syncthreads();

    // ---- layer 1: [32,224]x[224,384]; warp = 2 M-tiles x 48 cols; W from global
    float d1[2][6][4];
    #pragma unroll
    for (int nj = 0; nj < 6; nj++) {
        int col = warp*48 + nj*8 + 2*kq;
        float b0v = b1[e*HID + col], b1v = b1[e*HID + col + 1];
        #pragma unroll
        for (int mt = 0; mt < 2; mt++) {
            d1[mt][nj][0] = b0v; d1[mt][nj][1] = b1v;
            d1[mt][nj][2] = b0v; d1[mt][nj][3] = b1v;
        }
    }
    const unsigned* w1h = g_w1h + (size_t)e*W1PE;
    const unsigned* w1l = g_w1l + (size_t)e*W1PE;
    for (int kt = 0; kt < 14; kt++) {
        unsigned ah[2][4], al[2][4];
        #pragma unroll
        for (int mt = 0; mt < 2; mt++) {
            int base = (mt*16 + g)*XW32 + kt*8 + kq;
            ah[mt][0] = um[base];              al[mt][0] = um[OFF_XL + base];
            ah[mt][1] = um[base + 8*XW32];     al[mt][1] = um[OFF_XL + base + 8*XW32];
            ah[mt][2] = um[base + 4];          al[mt][2] = um[OFF_XL + base + 4];
            ah[mt][3] = um[base + 8*XW32 + 4]; al[mt][3] = um[OFF_XL + base + 8*XW32 + 4];
        }
        const unsigned* Wh = w1h + kt*3136;
        const unsigned* Wl = w1l + kt*3136;
        #pragma unroll
        for (int nj = 0; nj < 6; nj++) {
            int n = warp*48 + nj*8 + g;
            unsigned bh0 = Wh[kq*392 + n], bh1 = Wh[(kq+4)*392 + n];
            unsigned bl0 = Wl[kq*392 + n], bl1 = Wl[(kq+4)*392 + n];
            #pragma unroll
            for (int mt = 0; mt < 2; mt++) {
                mma16(d1[mt][nj], ah[mt], bh0, bh1);
                mma16(d1[mt][nj], ah[mt], bl0, bl1);
                mma16(d1[mt][nj], al[mt], bh0, bh1);
            }
        }
    }
    __syncthreads();   // X reads done; H overwrites the union region

    // exact GELU -> packed bf16 split H [tok][h]
    #pragma unroll
    for (int mt = 0; mt < 2; mt++)
        #pragma unroll
        for (int nj = 0; nj < 6; nj++) {
            int uc = warp*24 + nj*4 + kq;
            #pragma unroll
            for (int half = 0; half < 2; half++) {
                int t = mt*16 + g + half*8;
                float v0 = d1[mt][nj][2*half], v1 = d1[mt][nj][2*half + 1];
                float g0 = v0 * 0.5f * (1.0f + erff(v0 * 0.70710678118654752f));
                float g1 = v1 * 0.5f * (1.0f + erff(v1 * 0.70710678118654752f));
                unsigned short h0,l0,h1,l1;
                bfsplit(g0,h0,l0); bfsplit(g1,h1,l1);
                um[t*HW32 + uc]          = (unsigned)h0 | ((unsigned)h1 << 16);
                um[OFF_HL + t*HW32 + uc] = (unsigned)l0 | ((unsigned)l1 << 16);
            }
        }
    __syncthreads();

    // LoRA2 as MMA: [32,384]x[384,32]
    {
        int mt = warp >> 2, nh = warp & 3;
        float d[4] = {0,0,0,0};
        const unsigned* a2h = g_a2h + (size_t)e*A2PE;
        const unsigned* a2l = g_a2l + (size_t)e*A2PE;
        #pragma unroll 4
        for (int kt = 0; kt < 24; kt++) {
            int base = (mt*16 + g)*HW32 + kt*8 + kq;
            unsigned ah[4], al[4];
            ah[0]=um[base];              al[0]=um[OFF_HL+base];
            ah[1]=um[base+8*HW32];       al[1]=um[OFF_HL+base+8*HW32];
            ah[2]=um[base+4];            al[2]=um[OFF_HL+base+4];
            ah[3]=um[base+8*HW32+4];     al[3]=um[OFF_HL+base+8*HW32+4];
            int col = nh*8 + g;
            unsigned bh0 = a2h[(kt*8+kq)*40 + col], bh1 = a2h[(kt*8+kq+4)*40 + col];
            unsigned bl0 = a2l[(kt*8+kq)*40 + col], bl1 = a2l[(kt*8+kq+4)*40 + col];
            mma16(d, ah, bh0, bh1);
            mma16(d, ah, bl0, bl1);
            mma16(d, al, bh0, bh1);
        }
        int b = nh;
        int kp = 192 + nh*4 + kq;
        #pragma unroll
        for (int half = 0; half < 2; half++) {
            int t = mt*16 + g + half*8;
            float scl = LSCALE * sBw[t*4 + b];
            unsigned short h0,l0,h1,l1;
            bfsplit(scl*d[2*half],   h0, l0);
            bfsplit(scl*d[2*half+1], h1, l1);
            um[t*HW32 + kp]          = (unsigned)h0 | ((unsigned)h1 << 16);
            um[OFF_HL + t*HW32 + kp] = (unsigned)l0 | ((unsigned)l1 << 16);
        }
    }
    __syncthreads();

    // ---- layer 2: [32,416]x[416,192]; warp = 2 M-tiles x 24 cols; W global
    float d2[2][3][4];
    #pragma unroll
    for (int nj = 0; nj < 3; nj++) {
        int col = warp*24 + nj*8 + 2*kq;
        float b0v = b2[e*OUTD + col], b1v = b2[e*OUTD + col + 1];
        #pragma unroll
        for (int mt = 0; mt < 2; mt++) {
            d2[mt][nj][0] = b0v; d2[mt][nj][1] = b1v;
            d2[mt][nj][2] = b0v; d2[mt][nj][3] = b1v;
        }
    }
    const unsigned* w2h = g_w2h + (size_t)e*W2PE;
    const unsigned* w2l = g_w2l + (size_t)e*W2PE;
    for (int kt = 0; kt < 26; kt++) {
        unsigned ah[2][4], al[2][4];
        #pragma unroll
        for (int mt = 0; mt < 2; mt++) {
            int base = (mt*16 + g)*HW32 + kt*8 + kq;
            ah[mt][0] = um[base];              al[mt][0] = um[OFF_HL + base];
            ah[mt][1] = um[base + 8*HW32];     al[mt][1] = um[OFF_HL + base + 8*HW32];
            ah[mt][2] = um[base + 4];          al[mt][2] = um[OFF_HL + base + 4];
            ah[mt][3] = um[base + 8*HW32 + 4]; al[mt][3] = um[OFF_HL + base + 8*HW32 + 4];
        }
        const unsigned* Wh = w2h + kt*1600;
        const unsigned* Wl = w2l + kt*1600;
        #pragma unroll
        for (int nj = 0; nj < 3; nj++) {
            int n = warp*24 + nj*8 + g;
            unsigned bh0 = Wh[kq*200 + n], bh1 = Wh[(kq+4)*200 + n];
            unsigned bl0 = Wl[kq*200 + n], bl1 = Wl[(kq+4)*200 + n];
            #pragma unroll
            for (int mt = 0; mt < 2; mt++) {
                mma16(d2[mt][nj], ah[mt], bh0, bh1);
                mma16(d2[mt][nj], ah[mt], bl0, bl1);
                mma16(d2[mt][nj], al[mt], bh0, bh1);
            }
        }
    }
    // epilogue
    #pragma unroll
    for (int mt = 0; mt < 2; mt++)
        #pragma unroll
        for (int nj = 0; nj < 3; nj++) {
            int col = warp*24 + nj*8 + 2*kq;
            #pragma unroll
            for (int q = 0; q < 4; q++) {
                int t = mt*16 + g + (q >> 1)*8;
                if (t < nt) {
                    int tok = sTok[t];
                    atomicAdd(&out[(size_t)tok*OUTD + col + (q & 1)],
                              sGw[t]*d2[mt][nj][q]);
                }
            }
        }
}

// ---------------- deterministic loss ----------------
__global__ void __launch_bounds__(1024) loss_kernel(float* out, int out_size) {
    __shared__ float sI[8][32], sL[8][32];
    int tid = threadIdx.x, lane = tid & 31, warp = tid >> 5;
    float imp[8] = {0,0,0,0,0,0,0,0}, ld[8] = {0,0,0,0,0,0,0,0};
    for (int n = tid; n < NTOK; n += 1024) {
        unsigned te = g_te[n];
        int e0 = te & 255u, e1 = (te >> 8) & 255u;
        imp[e0] += g_tw0[n]; ld[e0] += 1.f;
        if (e1 != 255) { imp[e1] += g_tw1[n]; ld[e1] += 1.f; }
    }
    #pragma unroll
    for (int e = 0; e < 8; e++) {
        #pragma unroll
        for (int o = 16; o; o >>= 1) {
            imp[e] += __shfl_xor_sync(0xffffffffu, imp[e], o);
            ld[e]  += __shfl_xor_sync(0xffffffffu, ld[e],  o);
        }
        if (lane == 0) { sI[e][warp] = imp[e]; sL[e][warp] = ld[e]; }
    }
    __syncthreads();
    if (tid == 0) {
        float I[8], L[8], mi = 0.f, ml = 0.f;
        for (int e = 0; e < 8; e++) {
            float a = 0.f, b = 0.f;
            for (int w = 0; w < 32; w++) { a += sI[e][w]; b += sL[e][w]; }
            I[e] = a; L[e] = b; mi += a; ml += b;
        }
        mi *= 0.125f; ml *= 0.125f;
        float vi = 0.f, vl = 0.f;
        for (int e = 0; e < 8; e++) {
            float di = I[e] - mi; vi += di*di;
            float dl = L[e] - ml; vl += dl*dl;
        }
        vi *= 0.125f; vl *= 0.125f;
        float loss = (vi / (mi*mi + 1e-10f) + vl / (ml*ml + 1e-10f)) * 0.01f;
        if (out_size > NTOK*OUTD) out[NTOK*OUTD] = loss;
    }
    for (int i = NTOK*OUTD + 1 + tid; i < out_size; i += 1024) out[i] = 0.f;
}

// ---------------- launch ----------------
extern "C" void kernel_launch(void* const* d_in, const int* in_sizes, int n_in,
                              void* d_out, int out_size) {
    const float* x     = (const float*)d_in[0];
    const float* bw    = (const float*)d_in[1];
    const float* xprev = (const float*)d_in[2];
    const float* Wz    = (const float*)d_in[3];
    const float* lng   = (const float*)d_in[4];
    const float* lnb   = (const float*)d_in[5];
    const float* Wg    = (const float*)d_in[6];
    const float* bg    = (const float*)d_in[7];
    const float* W1    = (const float*)d_in[8];
    const float* b1    = (const float*)d_in[9];
    const float* W2    = (const float*)d_in[10];
    const float* b2    = (const float*)d_in[11];
    const float* A1    = (const float*)d_in[12];
    const float* B1    = (const float*)d_in[13];
    const float* A2    = (const float*)d_in[14];
    const float* B2    = (const float*)d_in[15];
    float* out = (float*)d_out;

    const size_t GATE_SMEM = (size_t)(12288 + 3096 + 258 + 258 + 8 + 32*192) * 4;
    const size_t FFN_SMEM  = (size_t)FFN_U32 * 4;
    cudaFuncSetAttribute(gate_kernel, cudaFuncAttributeMaxDynamicSharedMemorySize, (int)GATE_SMEM);
    cudaFuncSetAttribute(ffn_kernel,  cudaFuncAttributeMaxDynamicSharedMemorySize, (int)FFN_SMEM);

    init_kernel<<<2, 1024>>>();
    split_kernel<<<336, 1024>>>(W1, B1, W2, B2, A1, A2);
    gate_kernel<<<NTOK/32, 1024, GATE_SMEM>>>(x, xprev, Wz, lng, lnb, Wg, bg);
    for (int p = 0; p < 4; p++) {
        int shift = 24 - p*8;
        hist_kernel<<<dim3(32, NE), 256>>>(shift);
        digit_kernel<<<NE, 32>>>(shift);
    }
    mark_kernel<<<dim3(64, NE), 256>>>();
    scan_kernel<<<NE, 32>>>();
    tie_kernel<<<dim3(64, NE), 32>>>();
    route_kernel<<<NTOK/256, 256>>>(out);
    ffn_kernel<<<dim3(NTOK/TTILE, NE), 256, FFN_SMEM>>>(x, bw, b1, b2, out);
    loss_kernel<<<1, 1024>>>(out, out_size);
}